// round 1
// baseline (speedup 1.0000x reference)
#include <cuda_runtime.h>

#define Bq   4
#define Nn   512
#define Hh   12
#define Dh   64
#define HIDD 768
#define Ee   65536
#define NREL 64
#define NSEG (Bq*Nn)      // 2048
#define MAXCH 192         // row-chunks per relation (covers cnt up to 2048 edges/rel)

// ---------------- device scratch (no allocations allowed) ----------------
__device__ float g_Q[NSEG*HIDD];
__device__ float g_K[NSEG*HIDD];
__device__ float g_V[NSEG*HIDD];
__device__ float g_logits[Ee*Hh];
__device__ int   g_rel_cnt[NREL], g_rel_off[NREL+1], g_rel_cur[NREL];
__device__ int   g_seg_cnt[NSEG], g_seg_off[NSEG+1], g_seg_cur[NSEG];
__device__ int   g_rel_list[Ee], g_seg_list[Ee];

// ---------------- tiny kernels: counting sorts ----------------
__global__ void zero_k() {
    int i = blockIdx.x*blockDim.x + threadIdx.x;
    if (i < NREL) g_rel_cnt[i] = 0;
    if (i < NSEG) g_seg_cnt[i] = 0;
}

__global__ void hist_k(const int* __restrict__ ei) {
    int e = blockIdx.x*blockDim.x + threadIdx.x;
    if (e < Ee) {
        int b = ei[e], hn = ei[Ee+e], r = ei[3*Ee+e];
        atomicAdd(&g_rel_cnt[r], 1);
        atomicAdd(&g_seg_cnt[b*Nn + hn], 1);
    }
}

__global__ void scan_k() {
    __shared__ int sb[NSEG];
    int t = threadIdx.x;                       // 1024 threads
    sb[t]        = g_seg_cnt[t];
    sb[t+1024]   = g_seg_cnt[t+1024];
    __syncthreads();
    for (int d = 1; d < NSEG; d <<= 1) {
        int v0 = (t >= d) ? sb[t-d] : 0;
        int v1 = sb[t+1024-d];                 // t+1024-d >= 0 always (d<=1024)
        __syncthreads();
        sb[t] += v0; sb[t+1024] += v1;
        __syncthreads();
    }
    if (t == 0) g_seg_off[0] = 0;
    g_seg_off[t+1]      = sb[t];
    g_seg_off[t+1+1024] = sb[t+1024];
    g_seg_cur[t]        = sb[t]      - g_seg_cnt[t];
    g_seg_cur[t+1024]   = sb[t+1024] - g_seg_cnt[t+1024];
    if (t == 0) {
        int acc = 0;
        for (int r = 0; r < NREL; r++) {
            g_rel_off[r] = acc; g_rel_cur[r] = acc; acc += g_rel_cnt[r];
        }
        g_rel_off[NREL] = acc;
    }
}

__global__ void scatter_k(const int* __restrict__ ei) {
    int e = blockIdx.x*blockDim.x + threadIdx.x;
    if (e < Ee) {
        int b = ei[e], hn = ei[Ee+e], r = ei[3*Ee+e];
        int p1 = atomicAdd(&g_rel_cur[r], 1);         g_rel_list[p1] = e;
        int p2 = atomicAdd(&g_seg_cur[b*Nn + hn], 1); g_seg_list[p2] = e;
    }
}

// ---------------- QKV projection: Y = X @ W^T + b ----------------
// BM=BN=128, BK=16, 256 threads, 8x8 micro-tile. grid (16, 6, 3)
__global__ __launch_bounds__(256) void qkv_k(
    const float* __restrict__ X,
    const float* __restrict__ Wq, const float* __restrict__ bq,
    const float* __restrict__ Wk, const float* __restrict__ bk,
    const float* __restrict__ Wv, const float* __restrict__ bv)
{
    const int z = blockIdx.z;
    const float* W    = (z == 0) ? Wq : (z == 1) ? Wk : Wv;
    const float* bias = (z == 0) ? bq : (z == 1) ? bk : bv;
    float*       Y    = (z == 0) ? g_Q : (z == 1) ? g_K : g_V;

    __shared__ float As[16][128];
    __shared__ float Bs[16][128];

    const int tid = threadIdx.x;
    const int tr = tid & 15, tc = tid >> 4;       // 16 x 16 thread grid
    const int row0 = blockIdx.x*128, col0 = blockIdx.y*128;

    const int lr = tid >> 1;                      // load row/col 0..127
    const int lk = (tid & 1) * 8;                 // 0 or 8

    const float* Ax = X + (size_t)(row0 + lr)*HIDD;
    const float* Bx = W + (size_t)(col0 + lr)*HIDD;

    float acc[8][8];
#pragma unroll
    for (int i = 0; i < 8; i++)
#pragma unroll
        for (int j = 0; j < 8; j++) acc[i][j] = 0.f;

    for (int kb = 0; kb < HIDD; kb += 16) {
        float4 a0 = *(const float4*)(Ax + kb + lk);
        float4 a1 = *(const float4*)(Ax + kb + lk + 4);
        float4 b0 = *(const float4*)(Bx + kb + lk);
        float4 b1 = *(const float4*)(Bx + kb + lk + 4);
        __syncthreads();
        As[lk+0][lr]=a0.x; As[lk+1][lr]=a0.y; As[lk+2][lr]=a0.z; As[lk+3][lr]=a0.w;
        As[lk+4][lr]=a1.x; As[lk+5][lr]=a1.y; As[lk+6][lr]=a1.z; As[lk+7][lr]=a1.w;
        Bs[lk+0][lr]=b0.x; Bs[lk+1][lr]=b0.y; Bs[lk+2][lr]=b0.z; Bs[lk+3][lr]=b0.w;
        Bs[lk+4][lr]=b1.x; Bs[lk+5][lr]=b1.y; Bs[lk+6][lr]=b1.z; Bs[lk+7][lr]=b1.w;
        __syncthreads();
#pragma unroll
        for (int kk = 0; kk < 16; kk++) {
            float a[8], b[8];
            *(float4*)(a)   = *(const float4*)&As[kk][tr*8];
            *(float4*)(a+4) = *(const float4*)&As[kk][tr*8+4];
            *(float4*)(b)   = *(const float4*)&Bs[kk][tc*8];
            *(float4*)(b+4) = *(const float4*)&Bs[kk][tc*8+4];
#pragma unroll
            for (int i = 0; i < 8; i++)
#pragma unroll
                for (int j = 0; j < 8; j++) acc[i][j] += a[i]*b[j];
        }
    }

#pragma unroll
    for (int i = 0; i < 8; i++) {
        int r = row0 + tr*8 + i;
        float* yp = Y + (size_t)r*HIDD + col0 + tc*8;
        float4 o0, o1;
        o0.x = acc[i][0] + bias[col0+tc*8+0];
        o0.y = acc[i][1] + bias[col0+tc*8+1];
        o0.z = acc[i][2] + bias[col0+tc*8+2];
        o0.w = acc[i][3] + bias[col0+tc*8+3];
        o1.x = acc[i][4] + bias[col0+tc*8+4];
        o1.y = acc[i][5] + bias[col0+tc*8+5];
        o1.z = acc[i][6] + bias[col0+tc*8+6];
        o1.w = acc[i][7] + bias[col0+tc*8+7];
        *(float4*)(yp)   = o0;
        *(float4*)(yp+4) = o1;
    }
}

// ---------------- edge logits: logit[e,h] = (Qe[h]·Re)·Ke[h] / 8 ----------------
// Relation-grouped GEMM: rows = (edge-in-relation)*12+h; BM=128 rows, BN=64 (=D),
// K=64 (=D). Re staged fully in shared. grid (MAXCH, NREL), 256 threads, 8x4 tile.
__global__ __launch_bounds__(256) void logits_k(
    const int* __restrict__ ei, const float* __restrict__ rel)
{
    const int r   = blockIdx.y;
    const int off = g_rel_off[r];
    const int cnt = g_rel_off[r+1] - off;
    const int rows = cnt * Hh;
    const int row0 = blockIdx.x * 128;
    if (row0 >= rows) return;

    __shared__ float Rs[64][64];          // 16 KB: full relation matrix
    __shared__ float As[16][128];         // 8 KB: Q rows chunk (transposed)
    __shared__ float Sred[128][17];       // 8.5 KB: cross-thread reduce
    __shared__ int   rowQ[128], rowK[128], rowEH[128];

    const int tid = threadIdx.x;
    for (int i = tid; i < 64*64; i += 256)
        ((float*)Rs)[i] = rel[(size_t)r*4096 + i];

    if (tid < 128) {
        int row = row0 + tid;
        if (row < rows) {
            int el = row / Hh, h = row - el*Hh;
            int e  = g_rel_list[off + el];
            int b  = ei[e], hn = ei[Ee+e], tn = ei[2*Ee+e];
            rowQ[tid]  = (b*Nn + hn)*HIDD + h*Dh;
            rowK[tid]  = (b*Nn + tn)*HIDD + h*Dh;
            rowEH[tid] = e*Hh + h;
        } else {
            rowQ[tid] = 0; rowK[tid] = 0; rowEH[tid] = -1;
        }
    }
    __syncthreads();

    const int tr = tid & 15, tc = tid >> 4;       // rows: tr*8+i, cols: tc*4+j
    const int lr = tid >> 1, lk = (tid & 1) * 8;

    float acc[8][4];
#pragma unroll
    for (int i = 0; i < 8; i++)
#pragma unroll
        for (int j = 0; j < 4; j++) acc[i][j] = 0.f;

    const int qbase = rowQ[lr];
    for (int kb = 0; kb < 64; kb += 16) {
        float4 a0 = *(const float4*)(g_Q + qbase + kb + lk);
        float4 a1 = *(const float4*)(g_Q + qbase + kb + lk + 4);
        __syncthreads();
        As[lk+0][lr]=a0.x; As[lk+1][lr]=a0.y; As[lk+2][lr]=a0.z; As[lk+3][lr]=a0.w;
        As[lk+4][lr]=a1.x; As[lk+5][lr]=a1.y; As[lk+6][lr]=a1.z; As[lk+7][lr]=a1.w;
        __syncthreads();
#pragma unroll
        for (int kk = 0; kk < 16; kk++) {
            float a[8], b[4];
            *(float4*)(a)   = *(const float4*)&As[kk][tr*8];
            *(float4*)(a+4) = *(const float4*)&As[kk][tr*8+4];
            *(float4*)(b)   = *(const float4*)&Rs[kb+kk][tc*4];
#pragma unroll
            for (int i = 0; i < 8; i++)
#pragma unroll
                for (int j = 0; j < 4; j++) acc[i][j] += a[i]*b[j];
        }
    }

    // rowwise dot with Ke, reduce across the 16 column-thread groups
#pragma unroll
    for (int i = 0; i < 8; i++) {
        int rw = tr*8 + i;
        const float* kp = g_K + rowK[rw] + tc*4;
        Sred[rw][tc] = acc[i][0]*kp[0] + acc[i][1]*kp[1]
                     + acc[i][2]*kp[2] + acc[i][3]*kp[3];
    }
    __syncthreads();
    if (tid < 128) {
        float s = 0.f;
#pragma unroll
        for (int c = 0; c < 16; c++) s += Sred[tid][c];
        if (rowEH[tid] >= 0) g_logits[rowEH[tid]] = s * 0.125f;   // 1/sqrt(64)
    }
}

// ---------------- per-segment softmax + aggregation ----------------
// grid = 2048 segments, 384 threads = 12 warps (one per head).
__global__ __launch_bounds__(384) void softagg_k(
    const int* __restrict__ ei, float* __restrict__ out)
{
    const int s   = blockIdx.x;
    const int off = g_seg_off[s];
    const int cnt = g_seg_off[s+1] - off;
    const int w = threadIdx.x >> 5, lane = threadIdx.x & 31;

    if (cnt == 0) {
        for (int i = threadIdx.x; i < HIDD; i += 384) out[(size_t)s*HIDD + i] = 0.f;
        return;
    }

    float m = -3.4e38f;
    for (int i = lane; i < cnt; i += 32)
        m = fmaxf(m, g_logits[g_seg_list[off+i]*Hh + w]);
#pragma unroll
    for (int o = 16; o; o >>= 1) m = fmaxf(m, __shfl_xor_sync(0xffffffffu, m, o));

    float sm = 0.f;
    for (int i = lane; i < cnt; i += 32)
        sm += __expf(g_logits[g_seg_list[off+i]*Hh + w] - m);
#pragma unroll
    for (int o = 16; o; o >>= 1) sm += __shfl_xor_sync(0xffffffffu, sm, o);
    const float rsc = 1.f / sm;

    float a0 = 0.f, a1 = 0.f;
    for (int i = 0; i < cnt; i++) {
        int e = g_seg_list[off+i];
        float p = __expf(g_logits[e*Hh + w] - m);
        const float* vp = g_V + ((size_t)(ei[e]*Nn + ei[2*Ee+e]))*HIDD + w*Dh;
        a0 += p * vp[lane];
        a1 += p * vp[lane+32];
    }
    out[(size_t)s*HIDD + w*Dh + lane]      = a0 * rsc;
    out[(size_t)s*HIDD + w*Dh + lane + 32] = a1 * rsc;
}

// ---------------- launch ----------------
extern "C" void kernel_launch(void* const* d_in, const int* in_sizes, int n_in,
                              void* d_out, int out_size)
{
    const float* X    = (const float*)d_in[0];
    const int*   ei   = (const int*)  d_in[1];
    // d_in[2] = node_type_ids (unused)
    const float* Wq   = (const float*)d_in[3];
    const float* bq   = (const float*)d_in[4];
    const float* Wk   = (const float*)d_in[5];
    const float* bk   = (const float*)d_in[6];
    const float* Wv   = (const float*)d_in[7];
    const float* bv   = (const float*)d_in[8];
    const float* rel  = (const float*)d_in[9];
    float* out = (float*)d_out;

    zero_k   <<<8, 256>>>();
    hist_k   <<<Ee/256, 256>>>(ei);
    scan_k   <<<1, 1024>>>();
    scatter_k<<<Ee/256, 256>>>(ei);
    qkv_k    <<<dim3(16, 6, 3), 256>>>(X, Wq, bq, Wk, bk, Wv, bv);
    logits_k <<<dim3(MAXCH, NREL), 256>>>(ei, rel);
    softagg_k<<<NSEG, 384>>>(ei, out);
}

// round 2
// speedup vs baseline: 1.4080x; 1.4080x over previous
#include <cuda_runtime.h>

#define Bq   4
#define Nn   512
#define Hh   12
#define Dh   64
#define HIDD 768
#define Ee   65536
#define NREL 64
#define NSEG (Bq*Nn)      // 2048
#define MAXCH 96          // 256-row chunks per relation (covers 2048 edges/rel)

typedef unsigned long long u64;

__device__ __forceinline__ u64 pk2(float x, float y) {
    u64 r; asm("mov.b64 %0,{%1,%2};" : "=l"(r) : "f"(x), "f"(y)); return r;
}
__device__ __forceinline__ void upk2(u64 v, float& x, float& y) {
    asm("mov.b64 {%0,%1},%2;" : "=f"(x), "=f"(y) : "l"(v));
}
__device__ __forceinline__ void fm2(u64& d, u64 a, u64 b) {
    asm("fma.rn.f32x2 %0,%1,%2,%0;" : "+l"(d) : "l"(a), "l"(b));
}

// ---------------- device scratch ----------------
__device__ float g_Q[NSEG*HIDD];
__device__ float g_K[NSEG*HIDD];
__device__ float g_V[NSEG*HIDD];
__device__ float g_logits[Ee*Hh];
__device__ int   g_rel_cnt[NREL], g_rel_off[NREL+1], g_rel_cur[NREL];
__device__ int   g_seg_cnt[NSEG], g_seg_off[NSEG+1], g_seg_cur[NSEG];
__device__ int   g_rel_list[Ee], g_seg_list[Ee];

// ---------------- counting sorts ----------------
__global__ void zero_k() {
    int i = blockIdx.x*blockDim.x + threadIdx.x;
    if (i < NREL) g_rel_cnt[i] = 0;
    if (i < NSEG) g_seg_cnt[i] = 0;
}

__global__ void hist_k(const int* __restrict__ ei) {
    __shared__ int relh[NREL];
    int t = threadIdx.x;
    if (t < NREL) relh[t] = 0;
    __syncthreads();
    int e = blockIdx.x*blockDim.x + t;
    int b = ei[e], hn = ei[Ee+e], r = ei[3*Ee+e];
    atomicAdd(&relh[r], 1);
    atomicAdd(&g_seg_cnt[b*Nn + hn], 1);
    __syncthreads();
    if (t < NREL && relh[t]) atomicAdd(&g_rel_cnt[t], relh[t]);
}

__global__ void scan_k() {
    __shared__ int sb[NSEG];
    int t = threadIdx.x;                       // 1024 threads
    sb[t]        = g_seg_cnt[t];
    sb[t+1024]   = g_seg_cnt[t+1024];
    __syncthreads();
    for (int d = 1; d < NSEG; d <<= 1) {
        int v0 = (t >= d) ? sb[t-d] : 0;
        int v1 = sb[t+1024-d];
        __syncthreads();
        sb[t] += v0; sb[t+1024] += v1;
        __syncthreads();
    }
    if (t == 0) g_seg_off[0] = 0;
    g_seg_off[t+1]      = sb[t];
    g_seg_off[t+1+1024] = sb[t+1024];
    g_seg_cur[t]        = sb[t]      - g_seg_cnt[t];
    g_seg_cur[t+1024]   = sb[t+1024] - g_seg_cnt[t+1024];
    if (t == 0) {
        int acc = 0;
        for (int r = 0; r < NREL; r++) {
            g_rel_off[r] = acc; g_rel_cur[r] = acc; acc += g_rel_cnt[r];
        }
        g_rel_off[NREL] = acc;
    }
}

__global__ void scatter_k(const int* __restrict__ ei) {
    __shared__ int relh[NREL], relbase[NREL];
    int t = threadIdx.x;
    if (t < NREL) relh[t] = 0;
    __syncthreads();
    int e = blockIdx.x*blockDim.x + t;
    int b = ei[e], hn = ei[Ee+e], r = ei[3*Ee+e];
    int myofs = atomicAdd(&relh[r], 1);
    __syncthreads();
    if (t < NREL) relbase[t] = relh[t] ? atomicAdd(&g_rel_cur[t], relh[t]) : 0;
    __syncthreads();
    g_rel_list[relbase[r] + myofs] = e;
    int p2 = atomicAdd(&g_seg_cur[b*Nn + hn], 1); g_seg_list[p2] = e;
}

// ---------------- QKV projection: Y = X @ W^T + b (f32x2 packed) ----------------
// BM=BN=128, BK=16, 256 threads, 8x8 micro-tile. grid (16, 6, 3)
__global__ __launch_bounds__(256) void qkv_k(
    const float* __restrict__ X,
    const float* __restrict__ Wq, const float* __restrict__ bq,
    const float* __restrict__ Wk, const float* __restrict__ bk,
    const float* __restrict__ Wv, const float* __restrict__ bv)
{
    const int z = blockIdx.z;
    const float* W    = (z == 0) ? Wq : (z == 1) ? Wk : Wv;
    const float* bias = (z == 0) ? bq : (z == 1) ? bk : bv;
    float*       Y    = (z == 0) ? g_Q : (z == 1) ? g_K : g_V;

    __shared__ float As[16][128];
    __shared__ float Bs[16][128];

    const int tid = threadIdx.x;
    const int tr = tid & 15, tc = tid >> 4;       // 16 x 16 thread grid
    const int row0 = blockIdx.x*128, col0 = blockIdx.y*128;

    const int lr = tid >> 1;                      // load row 0..127
    const int lk = (tid & 1) * 8;                 // 0 or 8

    const float* Ax = X + (size_t)(row0 + lr)*HIDD;
    const float* Bx = W + (size_t)(col0 + lr)*HIDD;

    u64 acc[8][4];
    const u64 z2 = pk2(0.f, 0.f);
#pragma unroll
    for (int i = 0; i < 8; i++)
#pragma unroll
        for (int j = 0; j < 4; j++) acc[i][j] = z2;

    for (int kb = 0; kb < HIDD; kb += 16) {
        float4 a0 = *(const float4*)(Ax + kb + lk);
        float4 a1 = *(const float4*)(Ax + kb + lk + 4);
        float4 b0 = *(const float4*)(Bx + kb + lk);
        float4 b1 = *(const float4*)(Bx + kb + lk + 4);
        __syncthreads();
        As[lk+0][lr]=a0.x; As[lk+1][lr]=a0.y; As[lk+2][lr]=a0.z; As[lk+3][lr]=a0.w;
        As[lk+4][lr]=a1.x; As[lk+5][lr]=a1.y; As[lk+6][lr]=a1.z; As[lk+7][lr]=a1.w;
        Bs[lk+0][lr]=b0.x; Bs[lk+1][lr]=b0.y; Bs[lk+2][lr]=b0.z; Bs[lk+3][lr]=b0.w;
        Bs[lk+4][lr]=b1.x; Bs[lk+5][lr]=b1.y; Bs[lk+6][lr]=b1.z; Bs[lk+7][lr]=b1.w;
        __syncthreads();
#pragma unroll
        for (int kk = 0; kk < 16; kk++) {
            float a[8];
            *(float4*)(a)   = *(const float4*)&As[kk][tr*8];
            *(float4*)(a+4) = *(const float4*)&As[kk][tr*8+4];
            ulonglong2 bp0 = *(const ulonglong2*)&Bs[kk][tc*8];
            ulonglong2 bp1 = *(const ulonglong2*)&Bs[kk][tc*8+4];
            u64 ap[8];
#pragma unroll
            for (int i = 0; i < 8; i++) ap[i] = pk2(a[i], a[i]);
#pragma unroll
            for (int i = 0; i < 8; i++) {
                fm2(acc[i][0], ap[i], bp0.x);
                fm2(acc[i][1], ap[i], bp0.y);
                fm2(acc[i][2], ap[i], bp1.x);
                fm2(acc[i][3], ap[i], bp1.y);
            }
        }
    }

#pragma unroll
    for (int i = 0; i < 8; i++) {
        int r = row0 + tr*8 + i;
        float* yp = Y + (size_t)r*HIDD + col0 + tc*8;
        float o[8];
#pragma unroll
        for (int jp = 0; jp < 4; jp++) upk2(acc[i][jp], o[2*jp], o[2*jp+1]);
#pragma unroll
        for (int j = 0; j < 8; j++) o[j] += bias[col0 + tc*8 + j];
        *(float4*)(yp)   = *(float4*)(o);
        *(float4*)(yp+4) = *(float4*)(o+4);
    }
}

// ---------------- edge logits: logit[e,h] = (Qe[h]·Re)·Ke[h] / 8 (f32x2) ----------------
// Relation-grouped GEMM: rows = (edge-in-relation)*12+h; BM=256 rows, BN=64 (=D),
// K=64 (=D). Re staged fully in shared. grid (MAXCH, NREL), 256 threads, 8x8 tile.
__global__ __launch_bounds__(256) void logits_k(
    const int* __restrict__ ei, const float* __restrict__ rel)
{
    const int r   = blockIdx.y;
    const int off = g_rel_off[r];
    const int cnt = g_rel_off[r+1] - off;
    const int rows = cnt * Hh;
    const int row0 = blockIdx.x * 256;
    if (row0 >= rows) return;

    __shared__ float Rs[64][64];          // 16 KB: full relation matrix
    __shared__ float As[16][256];         // 16 KB: Q rows chunk (transposed)
    __shared__ float Sred[256][9];        //  9 KB: cross-thread reduce
    __shared__ int   rowQ[256], rowK[256], rowEH[256];

    const int tid = threadIdx.x;
#pragma unroll
    for (int i = tid; i < 64*64/4; i += 256)
        ((float4*)Rs)[i] = ((const float4*)(rel + (size_t)r*4096))[i];

    {
        int row = row0 + tid;
        if (row < rows) {
            int el = row / Hh, h = row - el*Hh;
            int e  = g_rel_list[off + el];
            int b  = ei[e], hn = ei[Ee+e], tn = ei[2*Ee+e];
            rowQ[tid]  = (b*Nn + hn)*HIDD + h*Dh;
            rowK[tid]  = (b*Nn + tn)*HIDD + h*Dh;
            rowEH[tid] = e*Hh + h;
        } else {
            rowQ[tid] = 0; rowK[tid] = 0; rowEH[tid] = -1;
        }
    }

    const int tr = tid >> 3, tc = tid & 7;        // rows: tr*8+i, cols: tc*8+j

    u64 acc[8][4];
    const u64 z2 = pk2(0.f, 0.f);
#pragma unroll
    for (int i = 0; i < 8; i++)
#pragma unroll
        for (int j = 0; j < 4; j++) acc[i][j] = z2;

    const int qbase = rowQ[tid];   // own slot, no sync needed for this read
    for (int kb = 0; kb < 64; kb += 16) {
        float4 q0 = *(const float4*)(g_Q + qbase + kb);
        float4 q1 = *(const float4*)(g_Q + qbase + kb + 4);
        float4 q2 = *(const float4*)(g_Q + qbase + kb + 8);
        float4 q3 = *(const float4*)(g_Q + qbase + kb + 12);
        __syncthreads();
        As[0][tid]=q0.x;  As[1][tid]=q0.y;  As[2][tid]=q0.z;  As[3][tid]=q0.w;
        As[4][tid]=q1.x;  As[5][tid]=q1.y;  As[6][tid]=q1.z;  As[7][tid]=q1.w;
        As[8][tid]=q2.x;  As[9][tid]=q2.y;  As[10][tid]=q2.z; As[11][tid]=q2.w;
        As[12][tid]=q3.x; As[13][tid]=q3.y; As[14][tid]=q3.z; As[15][tid]=q3.w;
        __syncthreads();
#pragma unroll
        for (int kk = 0; kk < 16; kk++) {
            float a[8];
            *(float4*)(a)   = *(const float4*)&As[kk][tr*8];
            *(float4*)(a+4) = *(const float4*)&As[kk][tr*8+4];
            ulonglong2 bp0 = *(const ulonglong2*)&Rs[kb+kk][tc*8];
            ulonglong2 bp1 = *(const ulonglong2*)&Rs[kb+kk][tc*8+4];
            u64 ap[8];
#pragma unroll
            for (int i = 0; i < 8; i++) ap[i] = pk2(a[i], a[i]);
#pragma unroll
            for (int i = 0; i < 8; i++) {
                fm2(acc[i][0], ap[i], bp0.x);
                fm2(acc[i][1], ap[i], bp0.y);
                fm2(acc[i][2], ap[i], bp1.x);
                fm2(acc[i][3], ap[i], bp1.y);
            }
        }
    }

    // rowwise dot with Ke over this thread's 8 columns, reduce across 8 tc groups
#pragma unroll
    for (int i = 0; i < 8; i++) {
        int rw = tr*8 + i;
        const float* kp = g_K + rowK[rw] + tc*8;
        float4 k0 = *(const float4*)(kp);
        float4 k1 = *(const float4*)(kp + 4);
        float o[8];
#pragma unroll
        for (int jp = 0; jp < 4; jp++) upk2(acc[i][jp], o[2*jp], o[2*jp+1]);
        Sred[rw][tc] = o[0]*k0.x + o[1]*k0.y + o[2]*k0.z + o[3]*k0.w
                     + o[4]*k1.x + o[5]*k1.y + o[6]*k1.z + o[7]*k1.w;
    }
    __syncthreads();
    {
        float s = 0.f;
#pragma unroll
        for (int c = 0; c < 8; c++) s += Sred[tid][c];
        if (rowEH[tid] >= 0) g_logits[rowEH[tid]] = s * 0.125f;   // 1/sqrt(64)
    }
}

// ---------------- per-segment softmax + aggregation ----------------
__global__ __launch_bounds__(384) void softagg_k(
    const int* __restrict__ ei, float* __restrict__ out)
{
    const int s   = blockIdx.x;
    const int off = g_seg_off[s];
    const int cnt = g_seg_off[s+1] - off;
    const int w = threadIdx.x >> 5, lane = threadIdx.x & 31;

    if (cnt == 0) {
        for (int i = threadIdx.x; i < HIDD; i += 384) out[(size_t)s*HIDD + i] = 0.f;
        return;
    }

    float m = -3.4e38f;
    for (int i = lane; i < cnt; i += 32)
        m = fmaxf(m, g_logits[g_seg_list[off+i]*Hh + w]);
#pragma unroll
    for (int o = 16; o; o >>= 1) m = fmaxf(m, __shfl_xor_sync(0xffffffffu, m, o));

    float sm = 0.f;
    for (int i = lane; i < cnt; i += 32)
        sm += __expf(g_logits[g_seg_list[off+i]*Hh + w] - m);
#pragma unroll
    for (int o = 16; o; o >>= 1) sm += __shfl_xor_sync(0xffffffffu, sm, o);
    const float rsc = 1.f / sm;

    float a0 = 0.f, a1 = 0.f;
    for (int i = 0; i < cnt; i++) {
        int e = g_seg_list[off+i];
        float p = __expf(g_logits[e*Hh + w] - m);
        const float* vp = g_V + ((size_t)(ei[e]*Nn + ei[2*Ee+e]))*HIDD + w*Dh;
        a0 += p * vp[lane];
        a1 += p * vp[lane+32];
    }
    out[(size_t)s*HIDD + w*Dh + lane]      = a0 * rsc;
    out[(size_t)s*HIDD + w*Dh + lane + 32] = a1 * rsc;
}

// ---------------- launch ----------------
extern "C" void kernel_launch(void* const* d_in, const int* in_sizes, int n_in,
                              void* d_out, int out_size)
{
    const float* X    = (const float*)d_in[0];
    const int*   ei   = (const int*)  d_in[1];
    const float* Wq   = (const float*)d_in[3];
    const float* bq   = (const float*)d_in[4];
    const float* Wk   = (const float*)d_in[5];
    const float* bk   = (const float*)d_in[6];
    const float* Wv   = (const float*)d_in[7];
    const float* bv   = (const float*)d_in[8];
    const float* rel  = (const float*)d_in[9];
    float* out = (float*)d_out;

    zero_k   <<<8, 256>>>();
    hist_k   <<<Ee/256, 256>>>(ei);
    scan_k   <<<1, 1024>>>();
    scatter_k<<<Ee/256, 256>>>(ei);
    qkv_k    <<<dim3(16, 6, 3), 256>>>(X, Wq, bq, Wk, bk, Wv, bv);
    logits_k <<<dim3(MAXCH, NREL), 256>>>(ei, rel);
    softagg_k<<<NSEG, 384>>>(ei, out);
}

// round 6
// speedup vs baseline: 1.7254x; 1.2254x over previous
#include <cuda_runtime.h>
#include <cuda_bf16.h>
#include <cstdint>

#define Bq   4
#define Nn   512
#define Hh   12
#define Dh   64
#define HIDD 768
#define Ee   65536
#define NREL 64
#define NSEG (Bq*Nn)      // 2048
#define MAXCH 96          // 256-row chunks per relation
#define KP   2304         // 3*HIDD (bf16x3 split K)
#define BKq  32
#define NIT  (KP/BKq)     // 72
#define LDS_ 40           // padded smem row stride (bf16 elems)

typedef unsigned long long u64;

__device__ __forceinline__ u64 pk2(float x, float y) {
    u64 r; asm("mov.b64 %0,{%1,%2};" : "=l"(r) : "f"(x), "f"(y)); return r;
}
__device__ __forceinline__ void upk2(u64 v, float& x, float& y) {
    asm("mov.b64 {%0,%1},%2;" : "=f"(x), "=f"(y) : "l"(v));
}
__device__ __forceinline__ void fm2(u64& d, u64 a, u64 b) {
    asm("fma.rn.f32x2 %0,%1,%2,%0;" : "+l"(d) : "l"(a), "l"(b));
}

__device__ __forceinline__ uint32_t smem_u32(const void* p) {
    uint32_t a;
    asm("{ .reg .u64 t; cvta.to.shared.u64 t, %1; cvt.u32.u64 %0, t; }"
        : "=r"(a) : "l"(p));
    return a;
}
__device__ __forceinline__ void ldm_x4(uint32_t& r0, uint32_t& r1, uint32_t& r2,
                                       uint32_t& r3, uint32_t addr) {
    asm volatile("ldmatrix.sync.aligned.m8n8.x4.shared.b16 {%0,%1,%2,%3},[%4];"
                 : "=r"(r0), "=r"(r1), "=r"(r2), "=r"(r3) : "r"(addr));
}
__device__ __forceinline__ void mma16816(float* c, const uint32_t* a,
                                         uint32_t b0, uint32_t b1) {
    asm volatile("mma.sync.aligned.m16n8k16.row.col.f32.bf16.bf16.f32 "
                 "{%0,%1,%2,%3},{%4,%5,%6,%7},{%8,%9},{%0,%1,%2,%3};"
                 : "+f"(c[0]), "+f"(c[1]), "+f"(c[2]), "+f"(c[3])
                 : "r"(a[0]), "r"(a[1]), "r"(a[2]), "r"(a[3]), "r"(b0), "r"(b1));
}
__device__ __forceinline__ void cpa16(uint32_t s, const void* g) {
    asm volatile("cp.async.cg.shared.global [%0],[%1],16;" :: "r"(s), "l"(g));
}

// ---------------- device scratch ----------------
__device__ float g_Q[NSEG*HIDD];
__device__ float g_K[NSEG*HIDD];
__device__ float g_V[NSEG*HIDD];
__device__ float g_logits[Ee*Hh];
__device__ int   g_rel_cnt[NREL], g_rel_off[NREL+1], g_rel_cur[NREL];
__device__ int   g_seg_cnt[NSEG], g_seg_off[NSEG+1], g_seg_cur[NSEG];
__device__ int   g_rel_list[Ee], g_seg_list[Ee];
__device__ __nv_bfloat16 g_Xp[NSEG*KP];       // [hi, hi, lo]
__device__ __nv_bfloat16 g_Wp[3*HIDD*KP];     // [hi, lo, hi]

// ---------------- counting sorts ----------------
__global__ void zero_k() {
    int i = blockIdx.x*blockDim.x + threadIdx.x;
    if (i < NREL) g_rel_cnt[i] = 0;
    if (i < NSEG) g_seg_cnt[i] = 0;
}

__global__ void hist_k(const int* __restrict__ ei) {
    __shared__ int relh[NREL];
    int t = threadIdx.x;
    if (t < NREL) relh[t] = 0;
    __syncthreads();
    int e = blockIdx.x*blockDim.x + t;
    int b = ei[e], hn = ei[Ee+e], r = ei[3*Ee+e];
    atomicAdd(&relh[r], 1);
    atomicAdd(&g_seg_cnt[b*Nn + hn], 1);
    __syncthreads();
    if (t < NREL && relh[t]) atomicAdd(&g_rel_cnt[t], relh[t]);
}

__global__ void scan_k() {
    __shared__ int sb[NSEG];
    int t = threadIdx.x;                       // 1024 threads
    sb[t]        = g_seg_cnt[t];
    sb[t+1024]   = g_seg_cnt[t+1024];
    __syncthreads();
    for (int d = 1; d < NSEG; d <<= 1) {
        int v0 = (t >= d) ? sb[t-d] : 0;
        int v1 = sb[t+1024-d];
        __syncthreads();
        sb[t] += v0; sb[t+1024] += v1;
        __syncthreads();
    }
    if (t == 0) g_seg_off[0] = 0;
    g_seg_off[t+1]      = sb[t];
    g_seg_off[t+1+1024] = sb[t+1024];
    g_seg_cur[t]        = sb[t]      - g_seg_cnt[t];
    g_seg_cur[t+1024]   = sb[t+1024] - g_seg_cnt[t+1024];
    if (t == 0) {
        int acc = 0;
        for (int r = 0; r < NREL; r++) {
            g_rel_off[r] = acc; g_rel_cur[r] = acc; acc += g_rel_cnt[r];
        }
        g_rel_off[NREL] = acc;
    }
}

__global__ void scatter_k(const int* __restrict__ ei) {
    __shared__ int relh[NREL], relbase[NREL];
    int t = threadIdx.x;
    if (t < NREL) relh[t] = 0;
    __syncthreads();
    int e = blockIdx.x*blockDim.x + t;
    int b = ei[e], hn = ei[Ee+e], r = ei[3*Ee+e];
    int myofs = atomicAdd(&relh[r], 1);
    __syncthreads();
    if (t < NREL) relbase[t] = relh[t] ? atomicAdd(&g_rel_cur[t], relh[t]) : 0;
    __syncthreads();
    g_rel_list[relbase[r] + myofs] = e;
    int p2 = atomicAdd(&g_seg_cur[b*Nn + hn], 1); g_seg_list[p2] = e;
}

// ---------------- bf16x3 conversion ----------------
__global__ void convX_k(const float* __restrict__ X) {
    int i = blockIdx.x*blockDim.x + threadIdx.x;     // over 2048*768
    int row = i / HIDD, k = i - row*HIDD;
    float x = X[i];
    __nv_bfloat16 hi = __float2bfloat16(x);
    __nv_bfloat16 lo = __float2bfloat16(x - __bfloat162float(hi));
    size_t base = (size_t)row*KP + k;
    g_Xp[base]          = hi;
    g_Xp[base + HIDD]   = hi;
    g_Xp[base + 2*HIDD] = lo;
}

__global__ void convW_k(const float* __restrict__ Wq,
                        const float* __restrict__ Wk,
                        const float* __restrict__ Wv) {
    int z = blockIdx.y;
    const float* W = (z == 0) ? Wq : (z == 1) ? Wk : Wv;
    int i = blockIdx.x*blockDim.x + threadIdx.x;     // over 768*768
    int n = i / HIDD, k = i - n*HIDD;
    float x = W[i];
    __nv_bfloat16 hi = __float2bfloat16(x);
    __nv_bfloat16 lo = __float2bfloat16(x - __bfloat162float(hi));
    size_t base = (size_t)z*HIDD*KP + (size_t)n*KP + k;
    g_Wp[base]          = hi;
    g_Wp[base + HIDD]   = lo;
    g_Wp[base + 2*HIDD] = hi;
}

// ---------------- QKV via mma.sync bf16x3: Y = X' @ W'^T + b ----------------
// 128x128 block tile, BK=32, 8 warps each 32x64, cp.async double buffer.
// grid (16, 6, 3), 256 threads.
__global__ __launch_bounds__(256) void qkv_mma_k(
    const float* __restrict__ bq, const float* __restrict__ bk,
    const float* __restrict__ bv)
{
    __shared__ __align__(16) __nv_bfloat16 sA[2][128*LDS_];
    __shared__ __align__(16) __nv_bfloat16 sB[2][128*LDS_];

    const int tid = threadIdx.x;
    const int wid = tid >> 5, lane = tid & 31;
    const int warp_m = wid & 3, warp_n = wid >> 2;   // 4 x 2 warp grid
    const int z = blockIdx.z;
    const int row0 = blockIdx.x * 128;
    const int col0 = blockIdx.y * 128;
    const float* bias = (z == 0) ? bq : (z == 1) ? bk : bv;
    float* Y = (z == 0) ? g_Q : (z == 1) ? g_K : g_V;

    const __nv_bfloat16* Ag = g_Xp + (size_t)row0*KP;
    const __nv_bfloat16* Bg = g_Wp + (size_t)(z*HIDD + col0)*KP;

    const uint32_t sAu[2] = { smem_u32(sA[0]), smem_u32(sA[1]) };
    const uint32_t sBu[2] = { smem_u32(sB[0]), smem_u32(sB[1]) };

    // load thread mapping: 2 chunks of 16B per array per thread
    const int ldrow0 = tid >> 2,        ldc0 = (tid & 3) * 16;       // bytes
    const int ldrow1 = (tid + 256) >> 2;
    const int gofs0  = (tid & 3) * 8;                                 // elems

    float acc[2][8][4];
#pragma unroll
    for (int mt = 0; mt < 2; mt++)
#pragma unroll
        for (int nt = 0; nt < 8; nt++)
#pragma unroll
            for (int q = 0; q < 4; q++) acc[mt][nt][q] = 0.f;

    // stage buf 0
    {
        cpa16(sAu[0] + ldrow0*(LDS_*2) + ldc0, Ag + (size_t)ldrow0*KP + gofs0);
        cpa16(sAu[0] + ldrow1*(LDS_*2) + ldc0, Ag + (size_t)ldrow1*KP + gofs0);
        cpa16(sBu[0] + ldrow0*(LDS_*2) + ldc0, Bg + (size_t)ldrow0*KP + gofs0);
        cpa16(sBu[0] + ldrow1*(LDS_*2) + ldc0, Bg + (size_t)ldrow1*KP + gofs0);
        asm volatile("cp.async.commit_group;" ::: "memory");
    }

    for (int it = 0; it < NIT; it++) {
        const int cur = it & 1;
        if (it + 1 < NIT) {
            const int nb = cur ^ 1, kb = (it + 1) * BKq;
            cpa16(sAu[nb] + ldrow0*(LDS_*2) + ldc0, Ag + (size_t)ldrow0*KP + kb + gofs0);
            cpa16(sAu[nb] + ldrow1*(LDS_*2) + ldc0, Ag + (size_t)ldrow1*KP + kb + gofs0);
            cpa16(sBu[nb] + ldrow0*(LDS_*2) + ldc0, Bg + (size_t)ldrow0*KP + kb + gofs0);
            cpa16(sBu[nb] + ldrow1*(LDS_*2) + ldc0, Bg + (size_t)ldrow1*KP + kb + gofs0);
            asm volatile("cp.async.commit_group;" ::: "memory");
            asm volatile("cp.async.wait_group 1;" ::: "memory");
        } else {
            asm volatile("cp.async.wait_group 0;" ::: "memory");
        }
        __syncthreads();

#pragma unroll
        for (int ks = 0; ks < 2; ks++) {
            const int kbyte = (ks*16 + ((lane >> 4) * 8)) * 2;
            uint32_t a[2][4];
#pragma unroll
            for (int mt = 0; mt < 2; mt++) {
                int r = warp_m*32 + mt*16 + (lane & 15);
                ldm_x4(a[mt][0], a[mt][1], a[mt][2], a[mt][3],
                       sAu[cur] + r*(LDS_*2) + kbyte);
            }
#pragma unroll
            for (int ng = 0; ng < 4; ng++) {
                int n = warp_n*64 + ng*16 + (lane & 15);
                uint32_t b0, b1, b2, b3;
                ldm_x4(b0, b1, b2, b3, sBu[cur] + n*(LDS_*2) + kbyte);
#pragma unroll
                for (int mt = 0; mt < 2; mt++) {
                    mma16816(acc[mt][ng*2+0], a[mt], b0, b2);
                    mma16816(acc[mt][ng*2+1], a[mt], b1, b3);
                }
            }
        }
        __syncthreads();
    }

    // epilogue: bias add + f32 store
#pragma unroll
    for (int mt = 0; mt < 2; mt++) {
        const int r = row0 + warp_m*32 + mt*16 + (lane >> 2);
#pragma unroll
        for (int nt = 0; nt < 8; nt++) {
            const int cc = col0 + warp_n*64 + nt*8 + (lane & 3)*2;
            float2 v0 = { acc[mt][nt][0] + bias[cc], acc[mt][nt][1] + bias[cc+1] };
            float2 v1 = { acc[mt][nt][2] + bias[cc], acc[mt][nt][3] + bias[cc+1] };
            *(float2*)(Y + (size_t)r*HIDD + cc)       = v0;
            *(float2*)(Y + (size_t)(r+8)*HIDD + cc)   = v1;
        }
    }
}

// ---------------- edge logits: logit[e,h] = (Qe[h]·Re)·Ke[h] / 8 (f32x2) ----------------
__global__ __launch_bounds__(256) void logits_k(
    const int* __restrict__ ei, const float* __restrict__ rel)
{
    const int r   = blockIdx.y;
    const int off = g_rel_off[r];
    const int cnt = g_rel_off[r+1] - off;
    const int rows = cnt * Hh;
    const int row0 = blockIdx.x * 256;
    if (row0 >= rows) return;

    __shared__ float Rs[64][64];
    __shared__ float As[16][256];
    __shared__ float Sred[256][9];
    __shared__ int   rowQ[256], rowK[256], rowEH[256];

    const int tid = threadIdx.x;
#pragma unroll
    for (int i = tid; i < 64*64/4; i += 256)
        ((float4*)Rs)[i] = ((const float4*)(rel + (size_t)r*4096))[i];

    {
        int row = row0 + tid;
        if (row < rows) {
            int el = row / Hh, h = row - el*Hh;
            int e  = g_rel_list[off + el];
            int b  = ei[e], hn = ei[Ee+e], tn = ei[2*Ee+e];
            rowQ[tid]  = (b*Nn + hn)*HIDD + h*Dh;
            rowK[tid]  = (b*Nn + tn)*HIDD + h*Dh;
            rowEH[tid] = e*Hh + h;
        } else {
            rowQ[tid] = 0; rowK[tid] = 0; rowEH[tid] = -1;
        }
    }

    const int tr = tid >> 3, tc = tid & 7;

    u64 acc[8][4];
    const u64 z2 = pk2(0.f, 0.f);
#pragma unroll
    for (int i = 0; i < 8; i++)
#pragma unroll
        for (int j = 0; j < 4; j++) acc[i][j] = z2;

    const int qbase = rowQ[tid];
    for (int kb = 0; kb < 64; kb += 16) {
        float4 q0 = *(const float4*)(g_Q + qbase + kb);
        float4 q1 = *(const float4*)(g_Q + qbase + kb + 4);
        float4 q2 = *(const float4*)(g_Q + qbase + kb + 8);
        float4 q3 = *(const float4*)(g_Q + qbase + kb + 12);
        __syncthreads();
        As[0][tid]=q0.x;  As[1][tid]=q0.y;  As[2][tid]=q0.z;  As[3][tid]=q0.w;
        As[4][tid]=q1.x;  As[5][tid]=q1.y;  As[6][tid]=q1.z;  As[7][tid]=q1.w;
        As[8][tid]=q2.x;  As[9][tid]=q2.y;  As[10][tid]=q2.z; As[11][tid]=q2.w;
        As[12][tid]=q3.x; As[13][tid]=q3.y; As[14][tid]=q3.z; As[15][tid]=q3.w;
        __syncthreads();
#pragma unroll
        for (int kk = 0; kk < 16; kk++) {
            float a[8];
            *(float4*)(a)   = *(const float4*)&As[kk][tr*8];
            *(float4*)(a+4) = *(const float4*)&As[kk][tr*8+4];
            ulonglong2 bp0 = *(const ulonglong2*)&Rs[kb+kk][tc*8];
            ulonglong2 bp1 = *(const ulonglong2*)&Rs[kb+kk][tc*8+4];
            u64 ap[8];
#pragma unroll
            for (int i = 0; i < 8; i++) ap[i] = pk2(a[i], a[i]);
#pragma unroll
            for (int i = 0; i < 8; i++) {
                fm2(acc[i][0], ap[i], bp0.x);
                fm2(acc[i][1], ap[i], bp0.y);
                fm2(acc[i][2], ap[i], bp1.x);
                fm2(acc[i][3], ap[i], bp1.y);
            }
        }
    }

#pragma unroll
    for (int i = 0; i < 8; i++) {
        int rw = tr*8 + i;
        const float* kp = g_K + rowK[rw] + tc*8;
        float4 k0 = *(const float4*)(kp);
        float4 k1 = *(const float4*)(kp + 4);
        float o[8];
#pragma unroll
        for (int jp = 0; jp < 4; jp++) upk2(acc[i][jp], o[2*jp], o[2*jp+1]);
        Sred[rw][tc] = o[0]*k0.x + o[1]*k0.y + o[2]*k0.z + o[3]*k0.w
                     + o[4]*k1.x + o[5]*k1.y + o[6]*k1.z + o[7]*k1.w;
    }
    __syncthreads();
    {
        float s = 0.f;
#pragma unroll
        for (int c = 0; c < 8; c++) s += Sred[tid][c];
        if (rowEH[tid] >= 0) g_logits[rowEH[tid]] = s * 0.125f;
    }
}

// ---------------- per-segment softmax + aggregation ----------------
__global__ __launch_bounds__(384) void softagg_k(
    const int* __restrict__ ei, float* __restrict__ out)
{
    const int s   = blockIdx.x;
    const int off = g_seg_off[s];
    const int cnt = g_seg_off[s+1] - off;
    const int w = threadIdx.x >> 5, lane = threadIdx.x & 31;

    if (cnt == 0) {
        for (int i = threadIdx.x; i < HIDD; i += 384) out[(size_t)s*HIDD + i] = 0.f;
        return;
    }

    float m = -3.4e38f;
    for (int i = lane; i < cnt; i += 32)
        m = fmaxf(m, g_logits[g_seg_list[off+i]*Hh + w]);
#pragma unroll
    for (int o = 16; o; o >>= 1) m = fmaxf(m, __shfl_xor_sync(0xffffffffu, m, o));

    float sm = 0.f;
    for (int i = lane; i < cnt; i += 32)
        sm += __expf(g_logits[g_seg_list[off+i]*Hh + w] - m);
#pragma unroll
    for (int o = 16; o; o >>= 1) sm += __shfl_xor_sync(0xffffffffu, sm, o);
    const float rsc = 1.f / sm;

    float a0 = 0.f, a1 = 0.f;
    for (int i = 0; i < cnt; i++) {
        int e = g_seg_list[off+i];
        float p = __expf(g_logits[e*Hh + w] - m);
        const float* vp = g_V + ((size_t)(ei[e]*Nn + ei[2*Ee+e]))*HIDD + w*Dh;
        a0 += p * vp[lane];
        a1 += p * vp[lane+32];
    }
    out[(size_t)s*HIDD + w*Dh + lane]      = a0 * rsc;
    out[(size_t)s*HIDD + w*Dh + lane + 32] = a1 * rsc;
}

// ---------------- launch ----------------
extern "C" void kernel_launch(void* const* d_in, const int* in_sizes, int n_in,
                              void* d_out, int out_size)
{
    const float* X    = (const float*)d_in[0];
    const int*   ei   = (const int*)  d_in[1];
    const float* Wq   = (const float*)d_in[3];
    const float* bq   = (const float*)d_in[4];
    const float* Wk   = (const float*)d_in[5];
    const float* bk   = (const float*)d_in[6];
    const float* Wv   = (const float*)d_in[7];
    const float* bv   = (const float*)d_in[8];
    const float* rel  = (const float*)d_in[9];
    float* out = (float*)d_out;

    zero_k   <<<8, 256>>>();
    hist_k   <<<Ee/256, 256>>>(ei);
    scan_k   <<<1, 1024>>>();
    scatter_k<<<Ee/256, 256>>>(ei);
    convX_k  <<<(NSEG*HIDD)/256, 256>>>(X);
    convW_k  <<<dim3((HIDD*HIDD)/256, 3), 256>>>(Wq, Wk, Wv);
    qkv_mma_k<<<dim3(16, 6, 3), 256>>>(bq, bk, bv);
    logits_k <<<dim3(MAXCH, NREL), 256>>>(ei, rel);
    softagg_k<<<NSEG, 384>>>(ei, out);
}

// round 7
// speedup vs baseline: 1.9074x; 1.1054x over previous
#include <cuda_runtime.h>
#include <cuda_bf16.h>
#include <cstdint>

#define Bq   4
#define Nn   512
#define Hh   12
#define Dh   64
#define HIDD 768
#define Ee   65536
#define NREL 64
#define NSEG (Bq*Nn)      // 2048
#define KP   2304         // 3*HIDD (bf16x3 split K for QKV)
#define BKq  32
#define NIT  (KP/BKq)     // 72
#define LDS_ 40           // qkv smem row stride (bf16)
#define LKP  192          // logits split K' = 3*64
#define LSTR 200          // logits smem row stride (bf16), 400B
#define MAXCHL 192        // 128-row chunks per relation (covers 2048 edges/rel)

typedef unsigned long long u64;

__device__ __forceinline__ uint32_t smem_u32(const void* p) {
    uint32_t a;
    asm("{ .reg .u64 t; cvta.to.shared.u64 t, %1; cvt.u32.u64 %0, t; }"
        : "=r"(a) : "l"(p));
    return a;
}
__device__ __forceinline__ void ldm_x4(uint32_t& r0, uint32_t& r1, uint32_t& r2,
                                       uint32_t& r3, uint32_t addr) {
    asm volatile("ldmatrix.sync.aligned.m8n8.x4.shared.b16 {%0,%1,%2,%3},[%4];"
                 : "=r"(r0), "=r"(r1), "=r"(r2), "=r"(r3) : "r"(addr));
}
__device__ __forceinline__ void mma16816(float* c, const uint32_t* a,
                                         uint32_t b0, uint32_t b1) {
    asm volatile("mma.sync.aligned.m16n8k16.row.col.f32.bf16.bf16.f32 "
                 "{%0,%1,%2,%3},{%4,%5,%6,%7},{%8,%9},{%0,%1,%2,%3};"
                 : "+f"(c[0]), "+f"(c[1]), "+f"(c[2]), "+f"(c[3])
                 : "r"(a[0]), "r"(a[1]), "r"(a[2]), "r"(a[3]), "r"(b0), "r"(b1));
}
__device__ __forceinline__ void cpa16(uint32_t s, const void* g) {
    asm volatile("cp.async.cg.shared.global [%0],[%1],16;" :: "r"(s), "l"(g));
}

// ---------------- device scratch ----------------
__device__ float g_Q[NSEG*HIDD];
__device__ float g_K[NSEG*HIDD];
__device__ float g_V[NSEG*HIDD];
__device__ __nv_bfloat16 g_Qhi[NSEG*HIDD];
__device__ __nv_bfloat16 g_Qlo[NSEG*HIDD];
__device__ float g_logits[Ee*Hh];
__device__ int   g_rel_cnt[NREL], g_rel_off[NREL+1], g_rel_cur[NREL];
__device__ int   g_seg_cnt[NSEG], g_seg_off[NSEG+1], g_seg_cur[NSEG];
__device__ int   g_rel_list[Ee], g_seg_list[Ee];
__device__ __nv_bfloat16 g_Xp[NSEG*KP];       // [hi, hi, lo]
__device__ __nv_bfloat16 g_Wp[3*HIDD*KP];     // [hi, lo, hi]

// ---------------- counting sorts ----------------
__global__ void zero_k() {
    int i = blockIdx.x*blockDim.x + threadIdx.x;
    if (i < NREL) g_rel_cnt[i] = 0;
    if (i < NSEG) g_seg_cnt[i] = 0;
}

__global__ void hist_k(const int* __restrict__ ei) {
    __shared__ int relh[NREL];
    int t = threadIdx.x;
    if (t < NREL) relh[t] = 0;
    __syncthreads();
    int e = blockIdx.x*blockDim.x + t;
    int b = ei[e], hn = ei[Ee+e], r = ei[3*Ee+e];
    atomicAdd(&relh[r], 1);
    atomicAdd(&g_seg_cnt[b*Nn + hn], 1);
    __syncthreads();
    if (t < NREL && relh[t]) atomicAdd(&g_rel_cnt[t], relh[t]);
}

__global__ void scan_k() {
    __shared__ int sb[NSEG];
    int t = threadIdx.x;                       // 1024 threads
    sb[t]        = g_seg_cnt[t];
    sb[t+1024]   = g_seg_cnt[t+1024];
    __syncthreads();
    for (int d = 1; d < NSEG; d <<= 1) {
        int v0 = (t >= d) ? sb[t-d] : 0;
        int v1 = sb[t+1024-d];
        __syncthreads();
        sb[t] += v0; sb[t+1024] += v1;
        __syncthreads();
    }
    if (t == 0) g_seg_off[0] = 0;
    g_seg_off[t+1]      = sb[t];
    g_seg_off[t+1+1024] = sb[t+1024];
    g_seg_cur[t]        = sb[t]      - g_seg_cnt[t];
    g_seg_cur[t+1024]   = sb[t+1024] - g_seg_cnt[t+1024];
    if (t == 0) {
        int acc = 0;
        for (int r = 0; r < NREL; r++) {
            g_rel_off[r] = acc; g_rel_cur[r] = acc; acc += g_rel_cnt[r];
        }
        g_rel_off[NREL] = acc;
    }
}

__global__ void scatter_k(const int* __restrict__ ei) {
    __shared__ int relh[NREL], relbase[NREL];
    int t = threadIdx.x;
    if (t < NREL) relh[t] = 0;
    __syncthreads();
    int e = blockIdx.x*blockDim.x + t;
    int b = ei[e], hn = ei[Ee+e], r = ei[3*Ee+e];
    int myofs = atomicAdd(&relh[r], 1);
    __syncthreads();
    if (t < NREL) relbase[t] = relh[t] ? atomicAdd(&g_rel_cur[t], relh[t]) : 0;
    __syncthreads();
    g_rel_list[relbase[r] + myofs] = e;
    int p2 = atomicAdd(&g_seg_cur[b*Nn + hn], 1); g_seg_list[p2] = e;
}

// ---------------- bf16x3 conversion ----------------
__global__ void convX_k(const float* __restrict__ X) {
    int i = blockIdx.x*blockDim.x + threadIdx.x;     // over 2048*768
    int row = i / HIDD, k = i - row*HIDD;
    float x = X[i];
    __nv_bfloat16 hi = __float2bfloat16(x);
    __nv_bfloat16 lo = __float2bfloat16(x - __bfloat162float(hi));
    size_t base = (size_t)row*KP + k;
    g_Xp[base]          = hi;
    g_Xp[base + HIDD]   = hi;
    g_Xp[base + 2*HIDD] = lo;
}

__global__ void convW_k(const float* __restrict__ Wq,
                        const float* __restrict__ Wk,
                        const float* __restrict__ Wv) {
    int z = blockIdx.y;
    const float* W = (z == 0) ? Wq : (z == 1) ? Wk : Wv;
    int i = blockIdx.x*blockDim.x + threadIdx.x;     // over 768*768
    int n = i / HIDD, k = i - n*HIDD;
    float x = W[i];
    __nv_bfloat16 hi = __float2bfloat16(x);
    __nv_bfloat16 lo = __float2bfloat16(x - __bfloat162float(hi));
    size_t base = (size_t)z*HIDD*KP + (size_t)n*KP + k;
    g_Wp[base]          = hi;
    g_Wp[base + HIDD]   = lo;
    g_Wp[base + 2*HIDD] = hi;
}

// ---------------- QKV via mma.sync bf16x3: Y = X' @ W'^T + b ----------------
// 128x128 block tile, BK=32, 8 warps each 32x64, cp.async double buffer.
// For z==0 (Q) the epilogue also emits bf16 hi/lo split of Q for the logits GEMM.
__global__ __launch_bounds__(256) void qkv_mma_k(
    const float* __restrict__ bq, const float* __restrict__ bk,
    const float* __restrict__ bv)
{
    __shared__ __align__(16) __nv_bfloat16 sA[2][128*LDS_];
    __shared__ __align__(16) __nv_bfloat16 sB[2][128*LDS_];

    const int tid = threadIdx.x;
    const int wid = tid >> 5, lane = tid & 31;
    const int warp_m = wid & 3, warp_n = wid >> 2;   // 4 x 2 warp grid
    const int z = blockIdx.z;
    const int row0 = blockIdx.x * 128;
    const int col0 = blockIdx.y * 128;
    const float* bias = (z == 0) ? bq : (z == 1) ? bk : bv;
    float* Y = (z == 0) ? g_Q : (z == 1) ? g_K : g_V;

    const __nv_bfloat16* Ag = g_Xp + (size_t)row0*KP;
    const __nv_bfloat16* Bg = g_Wp + (size_t)(z*HIDD + col0)*KP;

    const uint32_t sAu[2] = { smem_u32(sA[0]), smem_u32(sA[1]) };
    const uint32_t sBu[2] = { smem_u32(sB[0]), smem_u32(sB[1]) };

    const int ldrow0 = tid >> 2,        ldc0 = (tid & 3) * 16;       // bytes
    const int ldrow1 = (tid + 256) >> 2;
    const int gofs0  = (tid & 3) * 8;                                 // elems

    float acc[2][8][4];
#pragma unroll
    for (int mt = 0; mt < 2; mt++)
#pragma unroll
        for (int nt = 0; nt < 8; nt++)
#pragma unroll
            for (int q = 0; q < 4; q++) acc[mt][nt][q] = 0.f;

    {
        cpa16(sAu[0] + ldrow0*(LDS_*2) + ldc0, Ag + (size_t)ldrow0*KP + gofs0);
        cpa16(sAu[0] + ldrow1*(LDS_*2) + ldc0, Ag + (size_t)ldrow1*KP + gofs0);
        cpa16(sBu[0] + ldrow0*(LDS_*2) + ldc0, Bg + (size_t)ldrow0*KP + gofs0);
        cpa16(sBu[0] + ldrow1*(LDS_*2) + ldc0, Bg + (size_t)ldrow1*KP + gofs0);
        asm volatile("cp.async.commit_group;" ::: "memory");
    }

    for (int it = 0; it < NIT; it++) {
        const int cur = it & 1;
        if (it + 1 < NIT) {
            const int nb = cur ^ 1, kb = (it + 1) * BKq;
            cpa16(sAu[nb] + ldrow0*(LDS_*2) + ldc0, Ag + (size_t)ldrow0*KP + kb + gofs0);
            cpa16(sAu[nb] + ldrow1*(LDS_*2) + ldc0, Ag + (size_t)ldrow1*KP + kb + gofs0);
            cpa16(sBu[nb] + ldrow0*(LDS_*2) + ldc0, Bg + (size_t)ldrow0*KP + kb + gofs0);
            cpa16(sBu[nb] + ldrow1*(LDS_*2) + ldc0, Bg + (size_t)ldrow1*KP + kb + gofs0);
            asm volatile("cp.async.commit_group;" ::: "memory");
            asm volatile("cp.async.wait_group 1;" ::: "memory");
        } else {
            asm volatile("cp.async.wait_group 0;" ::: "memory");
        }
        __syncthreads();

#pragma unroll
        for (int ks = 0; ks < 2; ks++) {
            const int kbyte = (ks*16 + ((lane >> 4) * 8)) * 2;
            uint32_t a[2][4];
#pragma unroll
            for (int mt = 0; mt < 2; mt++) {
                int r = warp_m*32 + mt*16 + (lane & 15);
                ldm_x4(a[mt][0], a[mt][1], a[mt][2], a[mt][3],
                       sAu[cur] + r*(LDS_*2) + kbyte);
            }
#pragma unroll
            for (int ng = 0; ng < 4; ng++) {
                int n = warp_n*64 + ng*16 + (lane & 15);
                uint32_t b0, b1, b2, b3;
                ldm_x4(b0, b1, b2, b3, sBu[cur] + n*(LDS_*2) + kbyte);
#pragma unroll
                for (int mt = 0; mt < 2; mt++) {
                    mma16816(acc[mt][ng*2+0], a[mt], b0, b2);
                    mma16816(acc[mt][ng*2+1], a[mt], b1, b3);
                }
            }
        }
        __syncthreads();
    }

    // epilogue: bias add + f32 store (+ bf16 hi/lo of Q when z==0)
#pragma unroll
    for (int mt = 0; mt < 2; mt++) {
        const int r = row0 + warp_m*32 + mt*16 + (lane >> 2);
#pragma unroll
        for (int nt = 0; nt < 8; nt++) {
            const int cc = col0 + warp_n*64 + nt*8 + (lane & 3)*2;
            float v00 = acc[mt][nt][0] + bias[cc];
            float v01 = acc[mt][nt][1] + bias[cc+1];
            float v10 = acc[mt][nt][2] + bias[cc];
            float v11 = acc[mt][nt][3] + bias[cc+1];
            *(float2*)(Y + (size_t)r*HIDD + cc)     = make_float2(v00, v01);
            *(float2*)(Y + (size_t)(r+8)*HIDD + cc) = make_float2(v10, v11);
            if (z == 0) {
                __nv_bfloat16 h00 = __float2bfloat16(v00), h01 = __float2bfloat16(v01);
                __nv_bfloat16 h10 = __float2bfloat16(v10), h11 = __float2bfloat16(v11);
                __nv_bfloat162 hh0; hh0.x = h00; hh0.y = h01;
                __nv_bfloat162 hh1; hh1.x = h10; hh1.y = h11;
                __nv_bfloat162 ll0;
                ll0.x = __float2bfloat16(v00 - __bfloat162float(h00));
                ll0.y = __float2bfloat16(v01 - __bfloat162float(h01));
                __nv_bfloat162 ll1;
                ll1.x = __float2bfloat16(v10 - __bfloat162float(h10));
                ll1.y = __float2bfloat16(v11 - __bfloat162float(h11));
                *(__nv_bfloat162*)(g_Qhi + (size_t)r*HIDD + cc)     = hh0;
                *(__nv_bfloat162*)(g_Qhi + (size_t)(r+8)*HIDD + cc) = hh1;
                *(__nv_bfloat162*)(g_Qlo + (size_t)r*HIDD + cc)     = ll0;
                *(__nv_bfloat162*)(g_Qlo + (size_t)(r+8)*HIDD + cc) = ll1;
            }
        }
    }
}

// ---------------- edge logits via mma.sync bf16x3 ----------------
// P = [q_hi,q_hi,q_lo] @ [r_hi;r_lo;r_hi]  (K'=192), then logit = (P·Ke)/8 in fp32.
// Block: 128 edge-head rows x 64 cols, 8 warps (4m x 2n), grid (MAXCHL, NREL).
// Dynamic smem: sB 64x200 bf16 | sA 128x200 bf16 | rowK/rowEH/rowQ int[128] | Sred f32[256]
__global__ __launch_bounds__(256) void logits_mma_k(
    const int* __restrict__ ei, const float* __restrict__ rel)
{
    extern __shared__ char dsm[];
    __nv_bfloat16* sB = (__nv_bfloat16*)dsm;                    // 25600 B
    __nv_bfloat16* sA = (__nv_bfloat16*)(dsm + 25600);          // 51200 B
    int*   rowK  = (int*)(dsm + 76800);
    int*   rowEH = (int*)(dsm + 77312);
    int*   rowQ  = (int*)(dsm + 77824);
    float* Sred  = (float*)(dsm + 78336);                       // [128][2]

    const int r   = blockIdx.y;
    const int off = g_rel_off[r];
    const int cnt = g_rel_off[r+1] - off;
    const int rows = cnt * Hh;
    const int row0 = blockIdx.x * 128;
    if (row0 >= rows) return;

    const int tid = threadIdx.x;
    const int wid = tid >> 5, lane = tid & 31;
    const int warp_m = wid & 3, warp_n = wid >> 2;

    // row indices
    if (tid < 128) {
        int row = row0 + tid;
        if (row < rows) {
            int el = row / Hh, h = row - el*Hh;
            int e  = g_rel_list[off + el];
            int b  = ei[e], hn = ei[Ee+e], tn = ei[2*Ee+e];
            rowQ[tid]  = (b*Nn + hn)*HIDD + h*Dh;
            rowK[tid]  = (b*Nn + tn)*HIDD + h*Dh;
            rowEH[tid] = e*Hh + h;
        } else {
            rowQ[tid] = 0; rowK[tid] = 0; rowEH[tid] = -1;
        }
    }

    // stage B' = split of Re^T: sB[n][d]=hi, sB[n][64+d]=lo, sB[n][128+d]=hi
    const float* Rg = rel + (size_t)r*4096;
#pragma unroll 4
    for (int i = tid; i < 4096; i += 256) {
        int d = i >> 6, n = i & 63;
        float f = Rg[i];
        __nv_bfloat16 hi = __float2bfloat16(f);
        __nv_bfloat16 lo = __float2bfloat16(f - __bfloat162float(hi));
        sB[n*LSTR + d]       = hi;
        sB[n*LSTR + 64 + d]  = lo;
        sB[n*LSTR + 128 + d] = hi;
    }
    __syncthreads();

    // stage A': sA[row][0:64]=hi, [64:128]=hi, [128:192]=lo
    {
        const int row = tid >> 1, half = tid & 1;
        const __nv_bfloat16* qh = g_Qhi + rowQ[row] + half*32;
        const __nv_bfloat16* ql = g_Qlo + rowQ[row] + half*32;
        __nv_bfloat16* dst = sA + row*LSTR + half*32;
#pragma unroll
        for (int j = 0; j < 4; j++) {
            uint4 h = *(const uint4*)(qh + j*8);
            uint4 l = *(const uint4*)(ql + j*8);
            *(uint4*)(dst + j*8)        = h;
            *(uint4*)(dst + 64 + j*8)   = h;
            *(uint4*)(dst + 128 + j*8)  = l;
        }
    }
    __syncthreads();

    const uint32_t sAu = smem_u32(sA), sBu = smem_u32(sB);

    float acc[2][4][4];
#pragma unroll
    for (int mt = 0; mt < 2; mt++)
#pragma unroll
        for (int nt = 0; nt < 4; nt++)
#pragma unroll
            for (int q = 0; q < 4; q++) acc[mt][nt][q] = 0.f;

#pragma unroll
    for (int ks = 0; ks < 12; ks++) {
        const int kbyte = (ks*16 + ((lane >> 4) * 8)) * 2;
        uint32_t a[2][4];
#pragma unroll
        for (int mt = 0; mt < 2; mt++) {
            int rr = warp_m*32 + mt*16 + (lane & 15);
            ldm_x4(a[mt][0], a[mt][1], a[mt][2], a[mt][3],
                   sAu + rr*(LSTR*2) + kbyte);
        }
#pragma unroll
        for (int ng = 0; ng < 2; ng++) {
            int n = warp_n*32 + ng*16 + (lane & 15);
            uint32_t b0, b1, b2, b3;
            ldm_x4(b0, b1, b2, b3, sBu + n*(LSTR*2) + kbyte);
#pragma unroll
            for (int mt = 0; mt < 2; mt++) {
                mma16816(acc[mt][ng*2+0], a[mt], b0, b2);
                mma16816(acc[mt][ng*2+1], a[mt], b1, b3);
            }
        }
    }

    // logit = P . Ke  (fp32 gather of K, quad reduce, cross-warp_n reduce)
#pragma unroll
    for (int mt = 0; mt < 2; mt++) {
        int rl0 = warp_m*32 + mt*16 + (lane >> 2);
        int rl1 = rl0 + 8;
        const float* k0p = g_K + rowK[rl0];
        const float* k1p = g_K + rowK[rl1];
        float s0 = 0.f, s1 = 0.f;
#pragma unroll
        for (int nt = 0; nt < 4; nt++) {
            int cc = warp_n*32 + (nt>>1)*16 + (nt&1)*8 + (lane & 3)*2;
            float2 kv0 = *(const float2*)(k0p + cc);
            float2 kv1 = *(const float2*)(k1p + cc);
            s0 += acc[mt][nt][0]*kv0.x + acc[mt][nt][1]*kv0.y;
            s1 += acc[mt][nt][2]*kv1.x + acc[mt][nt][3]*kv1.y;
        }
        s0 += __shfl_xor_sync(0xffffffffu, s0, 1);
        s0 += __shfl_xor_sync(0xffffffffu, s0, 2);
        s1 += __shfl_xor_sync(0xffffffffu, s1, 1);
        s1 += __shfl_xor_sync(0xffffffffu, s1, 2);
        if ((lane & 3) == 0) {
            Sred[rl0*2 + warp_n] = s0;
            Sred[rl1*2 + warp_n] = s1;
        }
    }
    __syncthreads();
    if (tid < 128) {
        float s = (Sred[tid*2] + Sred[tid*2+1]) * 0.125f;   // 1/sqrt(64)
        if (rowEH[tid] >= 0) g_logits[rowEH[tid]] = s;
    }
}

// ---------------- per-segment softmax + aggregation ----------------
__global__ __launch_bounds__(384) void softagg_k(
    const int* __restrict__ ei, float* __restrict__ out)
{
    const int s   = blockIdx.x;
    const int off = g_seg_off[s];
    const int cnt = g_seg_off[s+1] - off;
    const int w = threadIdx.x >> 5, lane = threadIdx.x & 31;

    if (cnt == 0) {
        for (int i = threadIdx.x; i < HIDD; i += 384) out[(size_t)s*HIDD + i] = 0.f;
        return;
    }

    float m = -3.4e38f;
    for (int i = lane; i < cnt; i += 32)
        m = fmaxf(m, g_logits[g_seg_list[off+i]*Hh + w]);
#pragma unroll
    for (int o = 16; o; o >>= 1) m = fmaxf(m, __shfl_xor_sync(0xffffffffu, m, o));

    float sm = 0.f;
    for (int i = lane; i < cnt; i += 32)
        sm += __expf(g_logits[g_seg_list[off+i]*Hh + w] - m);
#pragma unroll
    for (int o = 16; o; o >>= 1) sm += __shfl_xor_sync(0xffffffffu, sm, o);
    const float rsc = 1.f / sm;

    float a0 = 0.f, a1 = 0.f;
    for (int i = 0; i < cnt; i++) {
        int e = g_seg_list[off+i];
        float p = __expf(g_logits[e*Hh + w] - m);
        const float* vp = g_V + ((size_t)(ei[e]*Nn + ei[2*Ee+e]))*HIDD + w*Dh;
        a0 += p * vp[lane];
        a1 += p * vp[lane+32];
    }
    out[(size_t)s*HIDD + w*Dh + lane]      = a0 * rsc;
    out[(size_t)s*HIDD + w*Dh + lane + 32] = a1 * rsc;
}

// ---------------- launch ----------------
extern "C" void kernel_launch(void* const* d_in, const int* in_sizes, int n_in,
                              void* d_out, int out_size)
{
    const float* X    = (const float*)d_in[0];
    const int*   ei   = (const int*)  d_in[1];
    const float* Wq   = (const float*)d_in[3];
    const float* bq   = (const float*)d_in[4];
    const float* Wk   = (const float*)d_in[5];
    const float* bk   = (const float*)d_in[6];
    const float* Wv   = (const float*)d_in[7];
    const float* bv   = (const float*)d_in[8];
    const float* rel  = (const float*)d_in[9];
    float* out = (float*)d_out;

    cudaFuncSetAttribute(logits_mma_k,
                         cudaFuncAttributeMaxDynamicSharedMemorySize, 79360);

    zero_k   <<<8, 256>>>();
    hist_k   <<<Ee/256, 256>>>(ei);
    scan_k   <<<1, 1024>>>();
    scatter_k<<<Ee/256, 256>>>(ei);
    convX_k  <<<(NSEG*HIDD)/256, 256>>>(X);
    convW_k  <<<dim3((HIDD*HIDD)/256, 3), 256>>>(Wq, Wk, Wv);
    qkv_mma_k<<<dim3(16, 6, 3), 256>>>(bq, bk, bv);
    logits_mma_k<<<dim3(MAXCHL, NREL), 256, 79360>>>(ei, rel);
    softagg_k<<<NSEG, 384>>>(ei, out);
}

// round 9
// speedup vs baseline: 2.2304x; 1.1693x over previous
#include <cuda_runtime.h>
#include <cuda_bf16.h>
#include <cstdint>

#define Bq   4
#define Nn   512
#define Hh   12
#define Dh   64
#define HIDD 768
#define Ee   65536
#define NREL 64
#define NSEG (Bq*Nn)      // 2048
#define BK   32
#define NITQ (HIDD/BK)    // 24
#define LDS_ 40           // qkv smem row stride (bf16 elems)
#define LST  72           // logits smem row stride (bf16 elems)
#define MAXCHL 192        // 128-row chunks per relation

__device__ __forceinline__ uint32_t smem_u32(const void* p) {
    uint32_t a;
    asm("{ .reg .u64 t; cvta.to.shared.u64 t, %1; cvt.u32.u64 %0, t; }"
        : "=r"(a) : "l"(p));
    return a;
}
__device__ __forceinline__ void ldm_x4(uint32_t& r0, uint32_t& r1, uint32_t& r2,
                                       uint32_t& r3, uint32_t addr) {
    asm volatile("ldmatrix.sync.aligned.m8n8.x4.shared.b16 {%0,%1,%2,%3},[%4];"
                 : "=r"(r0), "=r"(r1), "=r"(r2), "=r"(r3) : "r"(addr));
}
__device__ __forceinline__ void mma16816(float* c, const uint32_t* a,
                                         uint32_t b0, uint32_t b1) {
    asm volatile("mma.sync.aligned.m16n8k16.row.col.f32.bf16.bf16.f32 "
                 "{%0,%1,%2,%3},{%4,%5,%6,%7},{%8,%9},{%0,%1,%2,%3};"
                 : "+f"(c[0]), "+f"(c[1]), "+f"(c[2]), "+f"(c[3])
                 : "r"(a[0]), "r"(a[1]), "r"(a[2]), "r"(a[3]), "r"(b0), "r"(b1));
}
__device__ __forceinline__ void cpa16(uint32_t s, const void* g) {
    asm volatile("cp.async.cg.shared.global [%0],[%1],16;" :: "r"(s), "l"(g));
}

// ---------------- device scratch ----------------
__device__ float g_Q[NSEG*HIDD];
__device__ float g_K[NSEG*HIDD];
__device__ float g_V[NSEG*HIDD];
__device__ __nv_bfloat16 g_Qhi[NSEG*HIDD];
__device__ __nv_bfloat16 g_Qlo[NSEG*HIDD];
__device__ float g_logits[Ee*Hh];
__device__ int   g_rel_cnt[NREL], g_rel_off[NREL+1], g_rel_cur[NREL];
__device__ int   g_seg_cnt[NSEG], g_seg_off[NSEG+1], g_seg_cur[NSEG];
__device__ int   g_rel_list[Ee], g_seg_list[Ee];
__device__ __nv_bfloat16 g_Xhi[NSEG*HIDD];
__device__ __nv_bfloat16 g_Xlo[NSEG*HIDD];
__device__ __nv_bfloat16 g_Whi[3*HIDD*HIDD];
__device__ __nv_bfloat16 g_Wlo[3*HIDD*HIDD];

// ---------------- counting sorts ----------------
__global__ void zero_k() {
    int i = blockIdx.x*blockDim.x + threadIdx.x;
    if (i < NREL) g_rel_cnt[i] = 0;
    if (i < NSEG) g_seg_cnt[i] = 0;
}

__global__ void hist_k(const int* __restrict__ ei) {
    __shared__ int relh[NREL];
    int t = threadIdx.x;
    if (t < NREL) relh[t] = 0;
    __syncthreads();
    int e = blockIdx.x*blockDim.x + t;
    int b = ei[e], hn = ei[Ee+e], r = ei[3*Ee+e];
    atomicAdd(&relh[r], 1);
    atomicAdd(&g_seg_cnt[b*Nn + hn], 1);
    __syncthreads();
    if (t < NREL && relh[t]) atomicAdd(&g_rel_cnt[t], relh[t]);
}

// two-level shfl scan, 1024 threads, 2 elems/thread
__global__ void scan_k() {
    __shared__ int wsum[32];
    int t = threadIdx.x, lane = t & 31, w = t >> 5;
    int v0 = g_seg_cnt[2*t], v1 = g_seg_cnt[2*t+1];
    int s = v0 + v1, sc = s;
#pragma unroll
    for (int o = 1; o < 32; o <<= 1) {
        int u = __shfl_up_sync(0xffffffffu, sc, o);
        if (lane >= o) sc += u;
    }
    if (lane == 31) wsum[w] = sc;
    __syncthreads();
    if (w == 0) {
        int ws = wsum[lane];
#pragma unroll
        for (int o = 1; o < 32; o <<= 1) {
            int u = __shfl_up_sync(0xffffffffu, ws, o);
            if (lane >= o) ws += u;
        }
        wsum[lane] = ws;
    }
    __syncthreads();
    int base = (w ? wsum[w-1] : 0) + (sc - s);   // exclusive prefix of elem 2t
    g_seg_cur[2*t]   = base;
    g_seg_cur[2*t+1] = base + v0;
    if (t == 0) g_seg_off[0] = 0;
    g_seg_off[2*t+1] = base + v0;
    g_seg_off[2*t+2] = base + v0 + v1;
    if (t == 0) {
        int acc = 0;
        for (int r = 0; r < NREL; r++) {
            g_rel_off[r] = acc; g_rel_cur[r] = acc; acc += g_rel_cnt[r];
        }
        g_rel_off[NREL] = acc;
    }
}

__global__ void scatter_k(const int* __restrict__ ei) {
    __shared__ int relh[NREL], relbase[NREL];
    int t = threadIdx.x;
    if (t < NREL) relh[t] = 0;
    __syncthreads();
    int e = blockIdx.x*blockDim.x + t;
    int b = ei[e], hn = ei[Ee+e], r = ei[3*Ee+e];
    int myofs = atomicAdd(&relh[r], 1);
    __syncthreads();
    if (t < NREL) relbase[t] = relh[t] ? atomicAdd(&g_rel_cur[t], relh[t]) : 0;
    __syncthreads();
    g_rel_list[relbase[r] + myofs] = e;
    int p2 = atomicAdd(&g_seg_cur[b*Nn + hn], 1); g_seg_list[p2] = e;
}

// ---------------- bf16 hi/lo conversion (no duplication) ----------------
__global__ void convX_k(const float* __restrict__ X) {
    int i = blockIdx.x*blockDim.x + threadIdx.x;     // over 2048*768
    float x = X[i];
    __nv_bfloat16 hi = __float2bfloat16(x);
    g_Xhi[i] = hi;
    g_Xlo[i] = __float2bfloat16(x - __bfloat162float(hi));
}

__global__ void convW_k(const float* __restrict__ Wq,
                        const float* __restrict__ Wk,
                        const float* __restrict__ Wv) {
    int z = blockIdx.y;
    const float* W = (z == 0) ? Wq : (z == 1) ? Wk : Wv;
    int i = blockIdx.x*blockDim.x + threadIdx.x;     // over 768*768
    float x = W[i];
    __nv_bfloat16 hi = __float2bfloat16(x);
    size_t o = (size_t)z*HIDD*HIDD + i;
    g_Whi[o] = hi;
    g_Wlo[o] = __float2bfloat16(x - __bfloat162float(hi));
}

// ---------------- QKV via mma.sync, split-at-staging ----------------
// C = Ah@Bh + Al@Bh + Ah@Bl.  128x128 tile, BK=32, 24 iters, 8 warps (4m x 2n).
// Dynamic smem: 8 tiles of 128*LDS_ bf16 (Ah0,Ah1,Al0,Al1,Bh0,Bh1,Bl0,Bl1) = 81920 B.
__global__ __launch_bounds__(256) void qkv_mma_k(
    const float* __restrict__ bq, const float* __restrict__ bk,
    const float* __restrict__ bv)
{
    extern __shared__ __align__(16) char qsm[];
    const int TILEB = 128*LDS_*2;                     // bytes per tile

    const int tid = threadIdx.x;
    const int wid = tid >> 5, lane = tid & 31;
    const int warp_m = wid & 3, warp_n = wid >> 2;
    const int z = blockIdx.z;
    const int row0 = blockIdx.x * 128;
    const int col0 = blockIdx.y * 128;
    const float* bias = (z == 0) ? bq : (z == 1) ? bk : bv;
    float* Y = (z == 0) ? g_Q : (z == 1) ? g_K : g_V;

    const uint32_t s0 = smem_u32(qsm);
    const uint32_t tAh[2] = { s0,           s0 + TILEB };
    const uint32_t tAl[2] = { s0 + 2*TILEB, s0 + 3*TILEB };
    const uint32_t tBh[2] = { s0 + 4*TILEB, s0 + 5*TILEB };
    const uint32_t tBl[2] = { s0 + 6*TILEB, s0 + 7*TILEB };

    const __nv_bfloat16* Ah = g_Xhi + (size_t)row0*HIDD;
    const __nv_bfloat16* Al = g_Xlo + (size_t)row0*HIDD;
    const __nv_bfloat16* Bh = g_Whi + (size_t)(z*HIDD + col0)*HIDD;
    const __nv_bfloat16* Bl = g_Wlo + (size_t)(z*HIDD + col0)*HIDD;

    const int ldrow0 = tid >> 2, ldc0 = (tid & 3) * 16;   // bytes
    const int ldrow1 = (tid + 256) >> 2;
    const int gofs0  = (tid & 3) * 8;                      // elems

    float acc[2][8][4];
#pragma unroll
    for (int mt = 0; mt < 2; mt++)
#pragma unroll
        for (int nt = 0; nt < 8; nt++)
#pragma unroll
            for (int q = 0; q < 4; q++) acc[mt][nt][q] = 0.f;

#define QSTAGE(nb, kb)                                                            \
    do {                                                                          \
        cpa16(tAh[nb] + ldrow0*(LDS_*2) + ldc0, Ah + (size_t)ldrow0*HIDD + (kb) + gofs0); \
        cpa16(tAh[nb] + ldrow1*(LDS_*2) + ldc0, Ah + (size_t)ldrow1*HIDD + (kb) + gofs0); \
        cpa16(tAl[nb] + ldrow0*(LDS_*2) + ldc0, Al + (size_t)ldrow0*HIDD + (kb) + gofs0); \
        cpa16(tAl[nb] + ldrow1*(LDS_*2) + ldc0, Al + (size_t)ldrow1*HIDD + (kb) + gofs0); \
        cpa16(tBh[nb] + ldrow0*(LDS_*2) + ldc0, Bh + (size_t)ldrow0*HIDD + (kb) + gofs0); \
        cpa16(tBh[nb] + ldrow1*(LDS_*2) + ldc0, Bh + (size_t)ldrow1*HIDD + (kb) + gofs0); \
        cpa16(tBl[nb] + ldrow0*(LDS_*2) + ldc0, Bl + (size_t)ldrow0*HIDD + (kb) + gofs0); \
        cpa16(tBl[nb] + ldrow1*(LDS_*2) + ldc0, Bl + (size_t)ldrow1*HIDD + (kb) + gofs0); \
        asm volatile("cp.async.commit_group;" ::: "memory");                      \
    } while (0)

    QSTAGE(0, 0);

    for (int it = 0; it < NITQ; it++) {
        const int cur = it & 1;
        if (it + 1 < NITQ) {
            QSTAGE(cur ^ 1, (it + 1) * BK);
            asm volatile("cp.async.wait_group 1;" ::: "memory");
        } else {
            asm volatile("cp.async.wait_group 0;" ::: "memory");
        }
        __syncthreads();

#pragma unroll
        for (int ks = 0; ks < 2; ks++) {
            const int kbyte = (ks*16 + ((lane >> 4) * 8)) * 2;
            uint32_t ah[2][4], al[2][4];
#pragma unroll
            for (int mt = 0; mt < 2; mt++) {
                int rr = warp_m*32 + mt*16 + (lane & 15);
                ldm_x4(ah[mt][0], ah[mt][1], ah[mt][2], ah[mt][3],
                       tAh[cur] + rr*(LDS_*2) + kbyte);
                ldm_x4(al[mt][0], al[mt][1], al[mt][2], al[mt][3],
                       tAl[cur] + rr*(LDS_*2) + kbyte);
            }
#pragma unroll
            for (int ng = 0; ng < 4; ng++) {
                int n = warp_n*64 + ng*16 + (lane & 15);
                uint32_t bh0, bh1, bh2, bh3, bl0, bl1, bl2, bl3;
                ldm_x4(bh0, bh1, bh2, bh3, tBh[cur] + n*(LDS_*2) + kbyte);
                ldm_x4(bl0, bl1, bl2, bl3, tBl[cur] + n*(LDS_*2) + kbyte);
#pragma unroll
                for (int mt = 0; mt < 2; mt++) {
                    mma16816(acc[mt][ng*2+0], ah[mt], bh0, bh2);
                    mma16816(acc[mt][ng*2+1], ah[mt], bh1, bh3);
                    mma16816(acc[mt][ng*2+0], al[mt], bh0, bh2);
                    mma16816(acc[mt][ng*2+1], al[mt], bh1, bh3);
                    mma16816(acc[mt][ng*2+0], ah[mt], bl0, bl2);
                    mma16816(acc[mt][ng*2+1], ah[mt], bl1, bl3);
                }
            }
        }
        __syncthreads();
    }
#undef QSTAGE

    // epilogue: bias add + f32 store (+ bf16 hi/lo of Q when z==0)
#pragma unroll
    for (int mt = 0; mt < 2; mt++) {
        const int r = row0 + warp_m*32 + mt*16 + (lane >> 2);
#pragma unroll
        for (int nt = 0; nt < 8; nt++) {
            const int cc = col0 + warp_n*64 + nt*8 + (lane & 3)*2;
            float v00 = acc[mt][nt][0] + bias[cc];
            float v01 = acc[mt][nt][1] + bias[cc+1];
            float v10 = acc[mt][nt][2] + bias[cc];
            float v11 = acc[mt][nt][3] + bias[cc+1];
            *(float2*)(Y + (size_t)r*HIDD + cc)     = make_float2(v00, v01);
            *(float2*)(Y + (size_t)(r+8)*HIDD + cc) = make_float2(v10, v11);
            if (z == 0) {
                __nv_bfloat16 h00 = __float2bfloat16(v00), h01 = __float2bfloat16(v01);
                __nv_bfloat16 h10 = __float2bfloat16(v10), h11 = __float2bfloat16(v11);
                __nv_bfloat162 hh0; hh0.x = h00; hh0.y = h01;
                __nv_bfloat162 hh1; hh1.x = h10; hh1.y = h11;
                __nv_bfloat162 ll0;
                ll0.x = __float2bfloat16(v00 - __bfloat162float(h00));
                ll0.y = __float2bfloat16(v01 - __bfloat162float(h01));
                __nv_bfloat162 ll1;
                ll1.x = __float2bfloat16(v10 - __bfloat162float(h10));
                ll1.y = __float2bfloat16(v11 - __bfloat162float(h11));
                *(__nv_bfloat162*)(g_Qhi + (size_t)r*HIDD + cc)     = hh0;
                *(__nv_bfloat162*)(g_Qhi + (size_t)(r+8)*HIDD + cc) = hh1;
                *(__nv_bfloat162*)(g_Qlo + (size_t)r*HIDD + cc)     = ll0;
                *(__nv_bfloat162*)(g_Qlo + (size_t)(r+8)*HIDD + cc) = ll1;
            }
        }
    }
}

// ---------------- edge logits via mma.sync, split-at-staging ----------------
// P = Qh@Rh + Ql@Rh + Qh@Rl (K=64), then logit = (P·Ke)/8 in fp32.
// Block: 128 edge-head rows x 64 cols, 8 warps (4m x 2n), grid (MAXCHL, NREL).
// Dynamic smem layout (bytes):
//   sBh @0 (9216) | sBl @9216 (9216) | sAh @18432 (18432) | sAl @36864 (18432)
//   rowK @55296 | rowEH @55808 | rowQ @56320 | Sred @56832 (1024)  => 57856
__global__ __launch_bounds__(256) void logits_mma_k(
    const int* __restrict__ ei, const float* __restrict__ rel)
{
    extern __shared__ __align__(16) char dsm[];
    __nv_bfloat16* sBh = (__nv_bfloat16*)dsm;
    __nv_bfloat16* sBl = (__nv_bfloat16*)(dsm + 9216);
    __nv_bfloat16* sAh = (__nv_bfloat16*)(dsm + 18432);
    __nv_bfloat16* sAl = (__nv_bfloat16*)(dsm + 36864);
    int*   rowK  = (int*)(dsm + 55296);
    int*   rowEH = (int*)(dsm + 55808);
    int*   rowQ  = (int*)(dsm + 56320);
    float* Sred  = (float*)(dsm + 56832);               // [128][2]

    const int r   = blockIdx.y;
    const int off = g_rel_off[r];
    const int cnt = g_rel_off[r+1] - off;
    const int rows = cnt * Hh;
    const int row0 = blockIdx.x * 128;
    if (row0 >= rows) return;

    const int tid = threadIdx.x;
    const int wid = tid >> 5, lane = tid & 31;
    const int warp_m = wid & 3, warp_n = wid >> 2;

    if (tid < 128) {
        int row = row0 + tid;
        if (row < rows) {
            int el = row / Hh, h = row - el*Hh;
            int e  = g_rel_list[off + el];
            int b  = ei[e], hn = ei[Ee+e], tn = ei[2*Ee+e];
            rowQ[tid]  = (b*Nn + hn)*HIDD + h*Dh;
            rowK[tid]  = (b*Nn + tn)*HIDD + h*Dh;
            rowEH[tid] = e*Hh + h;
        } else {
            rowQ[tid] = 0; rowK[tid] = 0; rowEH[tid] = -1;
        }
    }

    // stage B = split of Re^T: sB*[n][d] from R[d][n]
    const float* Rg = rel + (size_t)r*4096;
#pragma unroll 4
    for (int i = tid; i < 4096; i += 256) {
        int d = i >> 6, n = i & 63;
        float f = Rg[i];
        __nv_bfloat16 hi = __float2bfloat16(f);
        sBh[n*LST + d] = hi;
        sBl[n*LST + d] = __float2bfloat16(f - __bfloat162float(hi));
    }
    __syncthreads();

    // stage A from g_Qhi/g_Qlo (uses rowQ)
    {
        const int row = tid >> 1, half = tid & 1;
        const __nv_bfloat16* qh = g_Qhi + rowQ[row] + half*32;
        const __nv_bfloat16* ql = g_Qlo + rowQ[row] + half*32;
        __nv_bfloat16* dh = sAh + row*LST + half*32;
        __nv_bfloat16* dl = sAl + row*LST + half*32;
#pragma unroll
        for (int j = 0; j < 4; j++) {
            *(uint4*)(dh + j*8) = *(const uint4*)(qh + j*8);
            *(uint4*)(dl + j*8) = *(const uint4*)(ql + j*8);
        }
    }
    __syncthreads();

    const uint32_t sAhu = smem_u32(sAh), sAlu = smem_u32(sAl);
    const uint32_t sBhu = smem_u32(sBh), sBlu = smem_u32(sBl);

    float acc[2][4][4];
#pragma unroll
    for (int mt = 0; mt < 2; mt++)
#pragma unroll
        for (int nt = 0; nt < 4; nt++)
#pragma unroll
            for (int q = 0; q < 4; q++) acc[mt][nt][q] = 0.f;

#pragma unroll
    for (int ks = 0; ks < 4; ks++) {
        const int kbyte = (ks*16 + ((lane >> 4) * 8)) * 2;
        uint32_t ah[2][4], al[2][4];
#pragma unroll
        for (int mt = 0; mt < 2; mt++) {
            int rr = warp_m*32 + mt*16 + (lane & 15);
            ldm_x4(ah[mt][0], ah[mt][1], ah[mt][2], ah[mt][3],
                   sAhu + rr*(LST*2) + kbyte);
            ldm_x4(al[mt][0], al[mt][1], al[mt][2], al[mt][3],
                   sAlu + rr*(LST*2) + kbyte);
        }
#pragma unroll
        for (int ng = 0; ng < 2; ng++) {
            int n = warp_n*32 + ng*16 + (lane & 15);
            uint32_t bh0, bh1, bh2, bh3, bl0, bl1, bl2, bl3;
            ldm_x4(bh0, bh1, bh2, bh3, sBhu + n*(LST*2) + kbyte);
            ldm_x4(bl0, bl1, bl2, bl3, sBlu + n*(LST*2) + kbyte);
#pragma unroll
            for (int mt = 0; mt < 2; mt++) {
                mma16816(acc[mt][ng*2+0], ah[mt], bh0, bh2);
                mma16816(acc[mt][ng*2+1], ah[mt], bh1, bh3);
                mma16816(acc[mt][ng*2+0], al[mt], bh0, bh2);
                mma16816(acc[mt][ng*2+1], al[mt], bh1, bh3);
                mma16816(acc[mt][ng*2+0], ah[mt], bl0, bl2);
                mma16816(acc[mt][ng*2+1], ah[mt], bl1, bl3);
            }
        }
    }

    // logit = P . Ke  (fp32 gather of K, quad reduce, cross-warp_n reduce)
#pragma unroll
    for (int mt = 0; mt < 2; mt++) {
        int rl0 = warp_m*32 + mt*16 + (lane >> 2);
        int rl1 = rl0 + 8;
        const float* k0p = g_K + rowK[rl0];
        const float* k1p = g_K + rowK[rl1];
        float s0 = 0.f, s1 = 0.f;
#pragma unroll
        for (int nt = 0; nt < 4; nt++) {
            int cc = warp_n*32 + (nt>>1)*16 + (nt&1)*8 + (lane & 3)*2;
            float2 kv0 = *(const float2*)(k0p + cc);
            float2 kv1 = *(const float2*)(k1p + cc);
            s0 += acc[mt][nt][0]*kv0.x + acc[mt][nt][1]*kv0.y;
            s1 += acc[mt][nt][2]*kv1.x + acc[mt][nt][3]*kv1.y;
        }
        s0 += __shfl_xor_sync(0xffffffffu, s0, 1);
        s0 += __shfl_xor_sync(0xffffffffu, s0, 2);
        s1 += __shfl_xor_sync(0xffffffffu, s1, 1);
        s1 += __shfl_xor_sync(0xffffffffu, s1, 2);
        if ((lane & 3) == 0) {
            Sred[rl0*2 + warp_n] = s0;
            Sred[rl1*2 + warp_n] = s1;
        }
    }
    __syncthreads();
    if (tid < 128) {
        float s = (Sred[tid*2] + Sred[tid*2+1]) * 0.125f;   // 1/sqrt(64)
        if (rowEH[tid] >= 0) g_logits[rowEH[tid]] = s;
    }
}

// ---------------- per-segment softmax + aggregation ----------------
__global__ __launch_bounds__(384) void softagg_k(
    const int* __restrict__ ei, float* __restrict__ out)
{
    const int s   = blockIdx.x;
    const int off = g_seg_off[s];
    const int cnt = g_seg_off[s+1] - off;
    const int w = threadIdx.x >> 5, lane = threadIdx.x & 31;

    if (cnt == 0) {
        for (int i = threadIdx.x; i < HIDD; i += 384) out[(size_t)s*HIDD + i] = 0.f;
        return;
    }

    float m = -3.4e38f;
    for (int i = lane; i < cnt; i += 32)
        m = fmaxf(m, g_logits[g_seg_list[off+i]*Hh + w]);
#pragma unroll
    for (int o = 16; o; o >>= 1) m = fmaxf(m, __shfl_xor_sync(0xffffffffu, m, o));

    float sm = 0.f;
    for (int i = lane; i < cnt; i += 32)
        sm += __expf(g_logits[g_seg_list[off+i]*Hh + w] - m);
#pragma unroll
    for (int o = 16; o; o >>= 1) sm += __shfl_xor_sync(0xffffffffu, sm, o);
    const float rsc = 1.f / sm;

    float a0 = 0.f, a1 = 0.f;
#pragma unroll 4
    for (int i = 0; i < cnt; i++) {
        int e = g_seg_list[off+i];
        float p = __expf(g_logits[e*Hh + w] - m);
        const float* vp = g_V + ((size_t)(ei[e]*Nn + ei[2*Ee+e]))*HIDD + w*Dh;
        a0 += p * vp[lane];
        a1 += p * vp[lane+32];
    }
    out[(size_t)s*HIDD + w*Dh + lane]      = a0 * rsc;
    out[(size_t)s*HIDD + w*Dh + lane + 32] = a1 * rsc;
}

// ---------------- launch ----------------
extern "C" void kernel_launch(void* const* d_in, const int* in_sizes, int n_in,
                              void* d_out, int out_size)
{
    const float* X    = (const float*)d_in[0];
    const int*   ei   = (const int*)  d_in[1];
    const float* Wq   = (const float*)d_in[3];
    const float* bq   = (const float*)d_in[4];
    const float* Wk   = (const float*)d_in[5];
    const float* bk   = (const float*)d_in[6];
    const float* Wv   = (const float*)d_in[7];
    const float* bv   = (const float*)d_in[8];
    const float* rel  = (const float*)d_in[9];
    float* out = (float*)d_out;

    cudaFuncSetAttribute(qkv_mma_k,
                         cudaFuncAttributeMaxDynamicSharedMemorySize, 81920);
    cudaFuncSetAttribute(logits_mma_k,
                         cudaFuncAttributeMaxDynamicSharedMemorySize, 57856);

    zero_k   <<<8, 256>>>();
    hist_k   <<<Ee/256, 256>>>(ei);
    scan_k   <<<1, 1024>>>();
    scatter_k<<<Ee/256, 256>>>(ei);
    convX_k  <<<(NSEG*HIDD)/256, 256>>>(X);
    convW_k  <<<dim3((HIDD*HIDD)/256, 3), 256>>>(Wq, Wk, Wv);
    qkv_mma_k<<<dim3(16, 6, 3), 256, 81920>>>(bq, bk, bv);
    logits_mma_k<<<dim3(MAXCHL, NREL), 256, 57856>>>(ei, rel);
    softagg_k<<<NSEG, 384>>>(ei, out);
}

// round 11
// speedup vs baseline: 2.3013x; 1.0318x over previous
#include <cuda_runtime.h>
#include <cuda_bf16.h>
#include <cstdint>

#define Bq   4
#define Nn   512
#define Hh   12
#define Dh   64
#define HIDD 768
#define Ee   65536
#define NREL 64
#define NSEG (Bq*Nn)      // 2048
#define BK   32
#define NITQ (HIDD/BK)    // 24
#define LDS_ 40           // qkv smem row stride (bf16 elems)
#define LST  72           // logits smem row stride (bf16 elems)
#define MAXCHL 96         // 256-row chunks per relation (covers 2048 edges/rel)

__device__ __forceinline__ uint32_t smem_u32(const void* p) {
    uint32_t a;
    asm("{ .reg .u64 t; cvta.to.shared.u64 t, %1; cvt.u32.u64 %0, t; }"
        : "=r"(a) : "l"(p));
    return a;
}
__device__ __forceinline__ void ldm_x4(uint32_t& r0, uint32_t& r1, uint32_t& r2,
                                       uint32_t& r3, uint32_t addr) {
    asm volatile("ldmatrix.sync.aligned.m8n8.x4.shared.b16 {%0,%1,%2,%3},[%4];"
                 : "=r"(r0), "=r"(r1), "=r"(r2), "=r"(r3) : "r"(addr));
}
__device__ __forceinline__ void mma16816(float* c, const uint32_t* a,
                                         uint32_t b0, uint32_t b1) {
    asm volatile("mma.sync.aligned.m16n8k16.row.col.f32.bf16.bf16.f32 "
                 "{%0,%1,%2,%3},{%4,%5,%6,%7},{%8,%9},{%0,%1,%2,%3};"
                 : "+f"(c[0]), "+f"(c[1]), "+f"(c[2]), "+f"(c[3])
                 : "r"(a[0]), "r"(a[1]), "r"(a[2]), "r"(a[3]), "r"(b0), "r"(b1));
}
__device__ __forceinline__ void cpa16(uint32_t s, const void* g) {
    asm volatile("cp.async.cg.shared.global [%0],[%1],16;" :: "r"(s), "l"(g));
}

// ---------------- device scratch ----------------
__device__ float g_Q[NSEG*HIDD];
__device__ float g_K[NSEG*HIDD];
__device__ float g_V[NSEG*HIDD];
__device__ __nv_bfloat16 g_Qhi[NSEG*HIDD];
__device__ __nv_bfloat16 g_Qlo[NSEG*HIDD];
__device__ float g_logits[Ee*Hh];
__device__ int   g_rel_cnt[NREL], g_rel_off[NREL+1], g_rel_cur[NREL];
__device__ int   g_seg_cnt[NSEG], g_seg_off[NSEG+1], g_seg_cur[NSEG];
__device__ int   g_rel_list[Ee], g_seg_list[Ee];
__device__ __nv_bfloat16 g_Xhi[NSEG*HIDD];
__device__ __nv_bfloat16 g_Xlo[NSEG*HIDD];
__device__ __nv_bfloat16 g_Whi[3*HIDD*HIDD];
__device__ __nv_bfloat16 g_Wlo[3*HIDD*HIDD];

// ---------------- counting sorts ----------------
__global__ void zero_k() {
    int i = blockIdx.x*blockDim.x + threadIdx.x;
    if (i < NREL) g_rel_cnt[i] = 0;
    if (i < NSEG) g_seg_cnt[i] = 0;
}

__global__ void hist_k(const int* __restrict__ ei) {
    __shared__ int relh[NREL];
    int t = threadIdx.x;
    if (t < NREL) relh[t] = 0;
    __syncthreads();
    int e = blockIdx.x*blockDim.x + t;
    int b = ei[e], hn = ei[Ee+e], r = ei[3*Ee+e];
    atomicAdd(&relh[r], 1);
    atomicAdd(&g_seg_cnt[b*Nn + hn], 1);
    __syncthreads();
    if (t < NREL && relh[t]) atomicAdd(&g_rel_cnt[t], relh[t]);
}

// two-level shfl scan, 1024 threads, 2 elems/thread
__global__ void scan_k() {
    __shared__ int wsum[32];
    int t = threadIdx.x, lane = t & 31, w = t >> 5;
    int v0 = g_seg_cnt[2*t], v1 = g_seg_cnt[2*t+1];
    int s = v0 + v1, sc = s;
#pragma unroll
    for (int o = 1; o < 32; o <<= 1) {
        int u = __shfl_up_sync(0xffffffffu, sc, o);
        if (lane >= o) sc += u;
    }
    if (lane == 31) wsum[w] = sc;
    __syncthreads();
    if (w == 0) {
        int ws = wsum[lane];
#pragma unroll
        for (int o = 1; o < 32; o <<= 1) {
            int u = __shfl_up_sync(0xffffffffu, ws, o);
            if (lane >= o) ws += u;
        }
        wsum[lane] = ws;
    }
    __syncthreads();
    int base = (w ? wsum[w-1] : 0) + (sc - s);   // exclusive prefix of elem 2t
    g_seg_cur[2*t]   = base;
    g_seg_cur[2*t+1] = base + v0;
    if (t == 0) g_seg_off[0] = 0;
    g_seg_off[2*t+1] = base + v0;
    g_seg_off[2*t+2] = base + v0 + v1;
    if (t == 0) {
        int acc = 0;
        for (int r = 0; r < NREL; r++) {
            g_rel_off[r] = acc; g_rel_cur[r] = acc; acc += g_rel_cnt[r];
        }
        g_rel_off[NREL] = acc;
    }
}

__global__ void scatter_k(const int* __restrict__ ei) {
    __shared__ int relh[NREL], relbase[NREL];
    int t = threadIdx.x;
    if (t < NREL) relh[t] = 0;
    __syncthreads();
    int e = blockIdx.x*blockDim.x + t;
    int b = ei[e], hn = ei[Ee+e], r = ei[3*Ee+e];
    int myofs = atomicAdd(&relh[r], 1);
    __syncthreads();
    if (t < NREL) relbase[t] = relh[t] ? atomicAdd(&g_rel_cur[t], relh[t]) : 0;
    __syncthreads();
    g_rel_list[relbase[r] + myofs] = e;
    int p2 = atomicAdd(&g_seg_cur[b*Nn + hn], 1); g_seg_list[p2] = e;
}

// ---------------- bf16 hi/lo conversion ----------------
__global__ void convX_k(const float* __restrict__ X) {
    int i = blockIdx.x*blockDim.x + threadIdx.x;     // over 2048*768
    float x = X[i];
    __nv_bfloat16 hi = __float2bfloat16(x);
    g_Xhi[i] = hi;
    g_Xlo[i] = __float2bfloat16(x - __bfloat162float(hi));
}

__global__ void convW_k(const float* __restrict__ Wq,
                        const float* __restrict__ Wk,
                        const float* __restrict__ Wv) {
    int z = blockIdx.y;
    const float* W = (z == 0) ? Wq : (z == 1) ? Wk : Wv;
    int i = blockIdx.x*blockDim.x + threadIdx.x;     // over 768*768
    float x = W[i];
    __nv_bfloat16 hi = __float2bfloat16(x);
    size_t o = (size_t)z*HIDD*HIDD + i;
    g_Whi[o] = hi;
    g_Wlo[o] = __float2bfloat16(x - __bfloat162float(hi));
}

// ---------------- QKV via mma.sync, split-at-staging ----------------
// C = Ah@Bh + Al@Bh + Ah@Bl.  128x128 tile, BK=32, 24 iters, 8 warps (4m x 2n).
__global__ __launch_bounds__(256) void qkv_mma_k(
    const float* __restrict__ bq, const float* __restrict__ bk,
    const float* __restrict__ bv)
{
    extern __shared__ __align__(16) char qsm[];
    const int TILEB = 128*LDS_*2;                     // bytes per tile

    const int tid = threadIdx.x;
    const int wid = tid >> 5, lane = tid & 31;
    const int warp_m = wid & 3, warp_n = wid >> 2;
    const int z = blockIdx.z;
    const int row0 = blockIdx.x * 128;
    const int col0 = blockIdx.y * 128;
    const float* bias = (z == 0) ? bq : (z == 1) ? bk : bv;
    float* Y = (z == 0) ? g_Q : (z == 1) ? g_K : g_V;

    const uint32_t s0 = smem_u32(qsm);
    const uint32_t tAh[2] = { s0,           s0 + TILEB };
    const uint32_t tAl[2] = { s0 + 2*TILEB, s0 + 3*TILEB };
    const uint32_t tBh[2] = { s0 + 4*TILEB, s0 + 5*TILEB };
    const uint32_t tBl[2] = { s0 + 6*TILEB, s0 + 7*TILEB };

    const __nv_bfloat16* Ah = g_Xhi + (size_t)row0*HIDD;
    const __nv_bfloat16* Al = g_Xlo + (size_t)row0*HIDD;
    const __nv_bfloat16* Bh = g_Whi + (size_t)(z*HIDD + col0)*HIDD;
    const __nv_bfloat16* Bl = g_Wlo + (size_t)(z*HIDD + col0)*HIDD;

    const int ldrow0 = tid >> 2, ldc0 = (tid & 3) * 16;   // bytes
    const int ldrow1 = (tid + 256) >> 2;
    const int gofs0  = (tid & 3) * 8;                      // elems

    float acc[2][8][4];
#pragma unroll
    for (int mt = 0; mt < 2; mt++)
#pragma unroll
        for (int nt = 0; nt < 8; nt++)
#pragma unroll
            for (int q = 0; q < 4; q++) acc[mt][nt][q] = 0.f;

#define QSTAGE(nb, kb)                                                            \
    do {                                                                          \
        cpa16(tAh[nb] + ldrow0*(LDS_*2) + ldc0, Ah + (size_t)ldrow0*HIDD + (kb) + gofs0); \
        cpa16(tAh[nb] + ldrow1*(LDS_*2) + ldc0, Ah + (size_t)ldrow1*HIDD + (kb) + gofs0); \
        cpa16(tAl[nb] + ldrow0*(LDS_*2) + ldc0, Al + (size_t)ldrow0*HIDD + (kb) + gofs0); \
        cpa16(tAl[nb] + ldrow1*(LDS_*2) + ldc0, Al + (size_t)ldrow1*HIDD + (kb) + gofs0); \
        cpa16(tBh[nb] + ldrow0*(LDS_*2) + ldc0, Bh + (size_t)ldrow0*HIDD + (kb) + gofs0); \
        cpa16(tBh[nb] + ldrow1*(LDS_*2) + ldc0, Bh + (size_t)ldrow1*HIDD + (kb) + gofs0); \
        cpa16(tBl[nb] + ldrow0*(LDS_*2) + ldc0, Bl + (size_t)ldrow0*HIDD + (kb) + gofs0); \
        cpa16(tBl[nb] + ldrow1*(LDS_*2) + ldc0, Bl + (size_t)ldrow1*HIDD + (kb) + gofs0); \
        asm volatile("cp.async.commit_group;" ::: "memory");                      \
    } while (0)

    QSTAGE(0, 0);

    for (int it = 0; it < NITQ; it++) {
        const int cur = it & 1;
        if (it + 1 < NITQ) {
            QSTAGE(cur ^ 1, (it + 1) * BK);
            asm volatile("cp.async.wait_group 1;" ::: "memory");
        } else {
            asm volatile("cp.async.wait_group 0;" ::: "memory");
        }
        __syncthreads();

#pragma unroll
        for (int ks = 0; ks < 2; ks++) {
            const int kbyte = (ks*16 + ((lane >> 4) * 8)) * 2;
            uint32_t ah[2][4], al[2][4];
#pragma unroll
            for (int mt = 0; mt < 2; mt++) {
                int rr = warp_m*32 + mt*16 + (lane & 15);
                ldm_x4(ah[mt][0], ah[mt][1], ah[mt][2], ah[mt][3],
                       tAh[cur] + rr*(LDS_*2) + kbyte);
                ldm_x4(al[mt][0], al[mt][1], al[mt][2], al[mt][3],
                       tAl[cur] + rr*(LDS_*2) + kbyte);
            }
#pragma unroll
            for (int ng = 0; ng < 4; ng++) {
                int n = warp_n*64 + ng*16 + (lane & 15);
                uint32_t bh0, bh1, bh2, bh3, bl0, bl1, bl2, bl3;
                ldm_x4(bh0, bh1, bh2, bh3, tBh[cur] + n*(LDS_*2) + kbyte);
                ldm_x4(bl0, bl1, bl2, bl3, tBl[cur] + n*(LDS_*2) + kbyte);
#pragma unroll
                for (int mt = 0; mt < 2; mt++) {
                    mma16816(acc[mt][ng*2+0], ah[mt], bh0, bh2);
                    mma16816(acc[mt][ng*2+1], ah[mt], bh1, bh3);
                    mma16816(acc[mt][ng*2+0], al[mt], bh0, bh2);
                    mma16816(acc[mt][ng*2+1], al[mt], bh1, bh3);
                    mma16816(acc[mt][ng*2+0], ah[mt], bl0, bl2);
                    mma16816(acc[mt][ng*2+1], ah[mt], bl1, bl3);
                }
            }
        }
        __syncthreads();
    }
#undef QSTAGE

    // epilogue: bias add + f32 store (+ bf16 hi/lo of Q when z==0)
#pragma unroll
    for (int mt = 0; mt < 2; mt++) {
        const int r = row0 + warp_m*32 + mt*16 + (lane >> 2);
#pragma unroll
        for (int nt = 0; nt < 8; nt++) {
            const int cc = col0 + warp_n*64 + nt*8 + (lane & 3)*2;
            float v00 = acc[mt][nt][0] + bias[cc];
            float v01 = acc[mt][nt][1] + bias[cc+1];
            float v10 = acc[mt][nt][2] + bias[cc];
            float v11 = acc[mt][nt][3] + bias[cc+1];
            *(float2*)(Y + (size_t)r*HIDD + cc)     = make_float2(v00, v01);
            *(float2*)(Y + (size_t)(r+8)*HIDD + cc) = make_float2(v10, v11);
            if (z == 0) {
                __nv_bfloat16 h00 = __float2bfloat16(v00), h01 = __float2bfloat16(v01);
                __nv_bfloat16 h10 = __float2bfloat16(v10), h11 = __float2bfloat16(v11);
                __nv_bfloat162 hh0; hh0.x = h00; hh0.y = h01;
                __nv_bfloat162 hh1; hh1.x = h10; hh1.y = h11;
                __nv_bfloat162 ll0;
                ll0.x = __float2bfloat16(v00 - __bfloat162float(h00));
                ll0.y = __float2bfloat16(v01 - __bfloat162float(h01));
                __nv_bfloat162 ll1;
                ll1.x = __float2bfloat16(v10 - __bfloat162float(h10));
                ll1.y = __float2bfloat16(v11 - __bfloat162float(h11));
                *(__nv_bfloat162*)(g_Qhi + (size_t)r*HIDD + cc)     = hh0;
                *(__nv_bfloat162*)(g_Qhi + (size_t)(r+8)*HIDD + cc) = hh1;
                *(__nv_bfloat162*)(g_Qlo + (size_t)r*HIDD + cc)     = ll0;
                *(__nv_bfloat162*)(g_Qlo + (size_t)(r+8)*HIDD + cc) = ll1;
            }
        }
    }
}

// ---------------- edge logits via mma.sync, 256-row blocks ----------------
// P = Qh@Rh + Ql@Rh + Qh@Rl (K=64), then logit = (P·Ke)/8 in fp32.
// Block: 256 edge-head rows x 64 cols, 8 warps each 32 rows x 64 cols.
// Dynamic smem (bytes): sBh@0 (9216) | sBl@9216 (9216) | sAh@18432 (36864)
//   | sAl@55296 (36864) | rowK@92160 | rowEH@93184 | rowQ@94208  => 95232
__global__ __launch_bounds__(256) void logits_mma_k(
    const int* __restrict__ ei, const float* __restrict__ rel)
{
    extern __shared__ __align__(16) char dsm[];
    __nv_bfloat16* sBh = (__nv_bfloat16*)dsm;
    __nv_bfloat16* sBl = (__nv_bfloat16*)(dsm + 9216);
    __nv_bfloat16* sAh = (__nv_bfloat16*)(dsm + 18432);
    __nv_bfloat16* sAl = (__nv_bfloat16*)(dsm + 55296);
    int* rowK  = (int*)(dsm + 92160);
    int* rowEH = (int*)(dsm + 93184);
    int* rowQ  = (int*)(dsm + 94208);

    const int r   = blockIdx.y;
    const int off = g_rel_off[r];
    const int cnt = g_rel_off[r+1] - off;
    const int rows = cnt * Hh;
    const int row0 = blockIdx.x * 256;
    if (row0 >= rows) return;

    const int tid = threadIdx.x;
    const int wid = tid >> 5, lane = tid & 31;

    {
        int row = row0 + tid;
        if (row < rows) {
            int el = row / Hh, h = row - el*Hh;
            int e  = g_rel_list[off + el];
            int b  = ei[e], hn = ei[Ee+e], tn = ei[2*Ee+e];
            rowQ[tid]  = (b*Nn + hn)*HIDD + h*Dh;
            rowK[tid]  = (b*Nn + tn)*HIDD + h*Dh;
            rowEH[tid] = e*Hh + h;
        } else {
            rowQ[tid] = 0; rowK[tid] = 0; rowEH[tid] = -1;
        }
    }

    // stage B = split of Re^T: sB*[n][d] from R[d][n]
    const float* Rg = rel + (size_t)r*4096;
#pragma unroll 4
    for (int i = tid; i < 4096; i += 256) {
        int d = i >> 6, n = i & 63;
        float f = Rg[i];
        __nv_bfloat16 hi = __float2bfloat16(f);
        sBh[n*LST + d] = hi;
        sBl[n*LST + d] = __float2bfloat16(f - __bfloat162float(hi));
    }

    // stage A from g_Qhi/g_Qlo (own rowQ slot — no sync needed for that read)
    {
        const int row = tid;
        const __nv_bfloat16* qh = g_Qhi + rowQ[row];
        const __nv_bfloat16* ql = g_Qlo + rowQ[row];
        __nv_bfloat16* dh = sAh + row*LST;
        __nv_bfloat16* dl = sAl + row*LST;
#pragma unroll
        for (int j = 0; j < 8; j++) {
            *(uint4*)(dh + j*8) = *(const uint4*)(qh + j*8);
            *(uint4*)(dl + j*8) = *(const uint4*)(ql + j*8);
        }
    }
    __syncthreads();

    const uint32_t sAhu = smem_u32(sAh), sAlu = smem_u32(sAl);
    const uint32_t sBhu = smem_u32(sBh), sBlu = smem_u32(sBl);

    float acc[2][8][4];
#pragma unroll
    for (int mt = 0; mt < 2; mt++)
#pragma unroll
        for (int nt = 0; nt < 8; nt++)
#pragma unroll
            for (int q = 0; q < 4; q++) acc[mt][nt][q] = 0.f;

#pragma unroll
    for (int ks = 0; ks < 4; ks++) {
        const int kbyte = (ks*16 + ((lane >> 4) * 8)) * 2;
        uint32_t ah[2][4], al[2][4];
#pragma unroll
        for (int mt = 0; mt < 2; mt++) {
            int rr = wid*32 + mt*16 + (lane & 15);
            ldm_x4(ah[mt][0], ah[mt][1], ah[mt][2], ah[mt][3],
                   sAhu + rr*(LST*2) + kbyte);
            ldm_x4(al[mt][0], al[mt][1], al[mt][2], al[mt][3],
                   sAlu + rr*(LST*2) + kbyte);
        }
#pragma unroll
        for (int ng = 0; ng < 4; ng++) {
            int n = ng*16 + (lane & 15);
            uint32_t bh0, bh1, bh2, bh3, bl0, bl1, bl2, bl3;
            ldm_x4(bh0, bh1, bh2, bh3, sBhu + n*(LST*2) + kbyte);
            ldm_x4(bl0, bl1, bl2, bl3, sBlu + n*(LST*2) + kbyte);
#pragma unroll
            for (int mt = 0; mt < 2; mt++) {
                mma16816(acc[mt][ng*2+0], ah[mt], bh0, bh2);
                mma16816(acc[mt][ng*2+1], ah[mt], bh1, bh3);
                mma16816(acc[mt][ng*2+0], al[mt], bh0, bh2);
                mma16816(acc[mt][ng*2+1], al[mt], bh1, bh3);
                mma16816(acc[mt][ng*2+0], ah[mt], bl0, bl2);
                mma16816(acc[mt][ng*2+1], ah[mt], bl1, bl3);
            }
        }
    }

    // logit = P . Ke  — each warp owns full rows: quad shfl completes the dot
#pragma unroll
    for (int mt = 0; mt < 2; mt++) {
        int rl0 = wid*32 + mt*16 + (lane >> 2);
        int rl1 = rl0 + 8;
        const float* k0p = g_K + rowK[rl0];
        const float* k1p = g_K + rowK[rl1];
        float s0 = 0.f, s1 = 0.f;
#pragma unroll
        for (int nt = 0; nt < 8; nt++) {
            int cc = (nt>>1)*16 + (nt&1)*8 + (lane & 3)*2;
            float2 kv0 = *(const float2*)(k0p + cc);
            float2 kv1 = *(const float2*)(k1p + cc);
            s0 += acc[mt][nt][0]*kv0.x + acc[mt][nt][1]*kv0.y;
            s1 += acc[mt][nt][2]*kv1.x + acc[mt][nt][3]*kv1.y;
        }
        s0 += __shfl_xor_sync(0xffffffffu, s0, 1);
        s0 += __shfl_xor_sync(0xffffffffu, s0, 2);
        s1 += __shfl_xor_sync(0xffffffffu, s1, 1);
        s1 += __shfl_xor_sync(0xffffffffu, s1, 2);
        if ((lane & 3) == 0) {
            if (rowEH[rl0] >= 0) g_logits[rowEH[rl0]] = s0 * 0.125f;
            if (rowEH[rl1] >= 0) g_logits[rowEH[rl1]] = s1 * 0.125f;
        }
    }
}

// ---------------- per-segment softmax + aggregation ----------------
__global__ __launch_bounds__(384) void softagg_k(
    const int* __restrict__ ei, float* __restrict__ out)
{
    __shared__ int sVoff[512];
    __shared__ int sEh[512];

    const int s   = blockIdx.x;
    const int off = g_seg_off[s];
    const int cnt = g_seg_off[s+1] - off;
    const int w = threadIdx.x >> 5, lane = threadIdx.x & 31;

    if (cnt == 0) {
        for (int i = threadIdx.x; i < HIDD; i += 384) out[(size_t)s*HIDD + i] = 0.f;
        return;
    }

    if (cnt <= 512) {
        for (int j = threadIdx.x; j < cnt; j += 384) {
            int e = g_seg_list[off+j];
            sVoff[j] = (ei[e]*Nn + ei[2*Ee+e])*HIDD;
            sEh[j]   = e*Hh;
        }
        __syncthreads();

        float m = -3.4e38f;
        for (int i = lane; i < cnt; i += 32)
            m = fmaxf(m, g_logits[sEh[i] + w]);
#pragma unroll
        for (int o = 16; o; o >>= 1) m = fmaxf(m, __shfl_xor_sync(0xffffffffu, m, o));

        float sm = 0.f;
        for (int i = lane; i < cnt; i += 32)
            sm += __expf(g_logits[sEh[i] + w] - m);
#pragma unroll
        for (int o = 16; o; o >>= 1) sm += __shfl_xor_sync(0xffffffffu, sm, o);
        const float rsc = 1.f / sm;

        float a0 = 0.f, a1 = 0.f;
#pragma unroll 4
        for (int i = 0; i < cnt; i++) {
            float p = __expf(g_logits[sEh[i] + w] - m);
            const float* vp = g_V + sVoff[i] + w*Dh;
            a0 += p * vp[lane];
            a1 += p * vp[lane+32];
        }
        out[(size_t)s*HIDD + w*Dh + lane]      = a0 * rsc;
        out[(size_t)s*HIDD + w*Dh + lane + 32] = a1 * rsc;
    } else {
        float m = -3.4e38f;
        for (int i = lane; i < cnt; i += 32)
            m = fmaxf(m, g_logits[g_seg_list[off+i]*Hh + w]);
#pragma unroll
        for (int o = 16; o; o >>= 1) m = fmaxf(m, __shfl_xor_sync(0xffffffffu, m, o));

        float sm = 0.f;
        for (int i = lane; i < cnt; i += 32)
            sm += __expf(g_logits[g_seg_list[off+i]*Hh + w] - m);
#pragma unroll
        for (int o = 16; o; o >>= 1) sm += __shfl_xor_sync(0xffffffffu, sm, o);
        const float rsc = 1.f / sm;

        float a0 = 0.f, a1 = 0.f;
        for (int i = 0; i < cnt; i++) {
            int e = g_seg_list[off+i];
            float p = __expf(g_logits[e*Hh + w] - m);
            const float* vp = g_V + ((size_t)(ei[e]*Nn + ei[2*Ee+e]))*HIDD + w*Dh;
            a0 += p * vp[lane];
            a1 += p * vp[lane+32];
        }
        out[(size_t)s*HIDD + w*Dh + lane]      = a0 * rsc;
        out[(size_t)s*HIDD + w*Dh + lane + 32] = a1 * rsc;
    }
}

// ---------------- launch ----------------
extern "C" void kernel_launch(void* const* d_in, const int* in_sizes, int n_in,
                              void* d_out, int out_size)
{
    const float* X    = (const float*)d_in[0];
    const int*   ei   = (const int*)  d_in[1];
    const float* Wq   = (const float*)d_in[3];
    const float* bq   = (const float*)d_in[4];
    const float* Wk   = (const float*)d_in[5];
    const float* bk   = (const float*)d_in[6];
    const float* Wv   = (const float*)d_in[7];
    const float* bv   = (const float*)d_in[8];
    const float* rel  = (const float*)d_in[9];
    float* out = (float*)d_out;

    cudaFuncSetAttribute(qkv_mma_k,
                         cudaFuncAttributeMaxDynamicSharedMemorySize, 81920);
    cudaFuncSetAttribute(logits_mma_k,
                         cudaFuncAttributeMaxDynamicSharedMemorySize, 95232);

    // fork: sort chain on side stream, overlapped with conv + qkv GEMM
    cudaStream_t s2;
    cudaStreamCreateWithFlags(&s2, cudaStreamNonBlocking);
    cudaEvent_t evF, evJ;
    cudaEventCreateWithFlags(&evF, cudaEventDisableTiming);
    cudaEventCreateWithFlags(&evJ, cudaEventDisableTiming);

    cudaEventRecord(evF, 0);
    cudaStreamWaitEvent(s2, evF, 0);
    zero_k   <<<8, 256, 0, s2>>>();
    hist_k   <<<Ee/256, 256, 0, s2>>>(ei);
    scan_k   <<<1, 1024, 0, s2>>>();
    scatter_k<<<Ee/256, 256, 0, s2>>>(ei);
    cudaEventRecord(evJ, s2);

    convX_k  <<<(NSEG*HIDD)/256, 256>>>(X);
    convW_k  <<<dim3((HIDD*HIDD)/256, 3), 256>>>(Wq, Wk, Wv);
    qkv_mma_k<<<dim3(16, 6, 3), 256, 81920>>>(bq, bk, bv);

    cudaStreamWaitEvent(0, evJ, 0);   // join before logits (needs rel sort)
    logits_mma_k<<<dim3(MAXCHL, NREL), 256, 95232>>>(ei, rel);
    softagg_k<<<NSEG, 384>>>(ei, out);
}

// round 12
// speedup vs baseline: 2.3062x; 1.0021x over previous
#include <cuda_runtime.h>
#include <cuda_bf16.h>
#include <cstdint>

#define Bq   4
#define Nn   512
#define Hh   12
#define Dh   64
#define HIDD 768
#define Ee   65536
#define NREL 64
#define NSEG (Bq*Nn)      // 2048
#define BK   32
#define NITQ (HIDD/BK)    // 24
#define LDS_ 40           // qkv smem row stride (bf16 elems)
#define LST  72           // logits smem row stride (bf16 elems)
#define NCHK 3136         // max total 256-row chunks over all relations

__device__ __forceinline__ uint32_t smem_u32(const void* p) {
    uint32_t a;
    asm("{ .reg .u64 t; cvta.to.shared.u64 t, %1; cvt.u32.u64 %0, t; }"
        : "=r"(a) : "l"(p));
    return a;
}
__device__ __forceinline__ void ldm_x4(uint32_t& r0, uint32_t& r1, uint32_t& r2,
                                       uint32_t& r3, uint32_t addr) {
    asm volatile("ldmatrix.sync.aligned.m8n8.x4.shared.b16 {%0,%1,%2,%3},[%4];"
                 : "=r"(r0), "=r"(r1), "=r"(r2), "=r"(r3) : "r"(addr));
}
__device__ __forceinline__ void mma16816(float* c, const uint32_t* a,
                                         uint32_t b0, uint32_t b1) {
    asm volatile("mma.sync.aligned.m16n8k16.row.col.f32.bf16.bf16.f32 "
                 "{%0,%1,%2,%3},{%4,%5,%6,%7},{%8,%9},{%0,%1,%2,%3};"
                 : "+f"(c[0]), "+f"(c[1]), "+f"(c[2]), "+f"(c[3])
                 : "r"(a[0]), "r"(a[1]), "r"(a[2]), "r"(a[3]), "r"(b0), "r"(b1));
}
__device__ __forceinline__ void cpa16(uint32_t s, const void* g) {
    asm volatile("cp.async.cg.shared.global [%0],[%1],16;" :: "r"(s), "l"(g));
}

// ---------------- device scratch ----------------
__device__ float g_Q[NSEG*HIDD];
__device__ float g_K[NSEG*HIDD];
__device__ float g_V[NSEG*HIDD];
__device__ __nv_bfloat16 g_Qhi[NSEG*HIDD];
__device__ __nv_bfloat16 g_Qlo[NSEG*HIDD];
__device__ float g_logits[Ee*Hh];
__device__ int   g_rel_cnt[NREL], g_rel_off[NREL+1], g_rel_cur[NREL];
__device__ int   g_chunk_off[NREL+1];
__device__ int   g_seg_cnt[NSEG], g_seg_off[NSEG+1], g_seg_cur[NSEG];
__device__ int   g_rel_list[Ee], g_seg_list[Ee];
__device__ __nv_bfloat16 g_Xhi[NSEG*HIDD];
__device__ __nv_bfloat16 g_Xlo[NSEG*HIDD];
__device__ __nv_bfloat16 g_Whi[3*HIDD*HIDD];
__device__ __nv_bfloat16 g_Wlo[3*HIDD*HIDD];

// ---------------- counting sorts ----------------
__global__ void zero_k() {
    int i = blockIdx.x*blockDim.x + threadIdx.x;
    if (i < NREL) g_rel_cnt[i] = 0;
    if (i < NSEG) g_seg_cnt[i] = 0;
}

__global__ void hist_k(const int* __restrict__ ei) {
    __shared__ int relh[NREL];
    int t = threadIdx.x;
    if (t < NREL) relh[t] = 0;
    __syncthreads();
    int e = blockIdx.x*blockDim.x + t;
    int b = ei[e], hn = ei[Ee+e], r = ei[3*Ee+e];
    atomicAdd(&relh[r], 1);
    atomicAdd(&g_seg_cnt[b*Nn + hn], 1);
    __syncthreads();
    if (t < NREL && relh[t]) atomicAdd(&g_rel_cnt[t], relh[t]);
}

// two-level shfl scan, 1024 threads, 2 elems/thread
__global__ void scan_k() {
    __shared__ int wsum[32];
    int t = threadIdx.x, lane = t & 31, w = t >> 5;
    int v0 = g_seg_cnt[2*t], v1 = g_seg_cnt[2*t+1];
    int s = v0 + v1, sc = s;
#pragma unroll
    for (int o = 1; o < 32; o <<= 1) {
        int u = __shfl_up_sync(0xffffffffu, sc, o);
        if (lane >= o) sc += u;
    }
    if (lane == 31) wsum[w] = sc;
    __syncthreads();
    if (w == 0) {
        int ws = wsum[lane];
#pragma unroll
        for (int o = 1; o < 32; o <<= 1) {
            int u = __shfl_up_sync(0xffffffffu, ws, o);
            if (lane >= o) ws += u;
        }
        wsum[lane] = ws;
    }
    __syncthreads();
    int base = (w ? wsum[w-1] : 0) + (sc - s);   // exclusive prefix of elem 2t
    g_seg_cur[2*t]   = base;
    g_seg_cur[2*t+1] = base + v0;
    if (t == 0) g_seg_off[0] = 0;
    g_seg_off[2*t+1] = base + v0;
    g_seg_off[2*t+2] = base + v0 + v1;
    if (t == 0) {
        int acc = 0, acc2 = 0;
        for (int r = 0; r < NREL; r++) {
            g_rel_off[r] = acc; g_rel_cur[r] = acc;
            g_chunk_off[r] = acc2;
            acc  += g_rel_cnt[r];
            acc2 += (g_rel_cnt[r]*Hh + 255) >> 8;
        }
        g_rel_off[NREL]   = acc;
        g_chunk_off[NREL] = acc2;
    }
}

__global__ void scatter_k(const int* __restrict__ ei) {
    __shared__ int relh[NREL], relbase[NREL];
    int t = threadIdx.x;
    if (t < NREL) relh[t] = 0;
    __syncthreads();
    int e = blockIdx.x*blockDim.x + t;
    int b = ei[e], hn = ei[Ee+e], r = ei[3*Ee+e];
    int myofs = atomicAdd(&relh[r], 1);
    __syncthreads();
    if (t < NREL) relbase[t] = relh[t] ? atomicAdd(&g_rel_cur[t], relh[t]) : 0;
    __syncthreads();
    g_rel_list[relbase[r] + myofs] = e;
    int p2 = atomicAdd(&g_seg_cur[b*Nn + hn], 1); g_seg_list[p2] = e;
}

// ---------------- bf16 hi/lo conversion ----------------
__global__ void convX_k(const float* __restrict__ X) {
    int i = blockIdx.x*blockDim.x + threadIdx.x;     // over 2048*768
    float x = X[i];
    __nv_bfloat16 hi = __float2bfloat16(x);
    g_Xhi[i] = hi;
    g_Xlo[i] = __float2bfloat16(x - __bfloat162float(hi));
}

__global__ void convW_k(const float* __restrict__ Wq,
                        const float* __restrict__ Wk,
                        const float* __restrict__ Wv) {
    int z = blockIdx.y;
    const float* W = (z == 0) ? Wq : (z == 1) ? Wk : Wv;
    int i = blockIdx.x*blockDim.x + threadIdx.x;     // over 768*768
    float x = W[i];
    __nv_bfloat16 hi = __float2bfloat16(x);
    size_t o = (size_t)z*HIDD*HIDD + i;
    g_Whi[o] = hi;
    g_Wlo[o] = __float2bfloat16(x - __bfloat162float(hi));
}

// ---------------- QKV via mma.sync, split-at-staging ----------------
// C = Ah@Bh + Al@Bh + Ah@Bl.  128x128 tile, BK=32, 24 iters, 8 warps (4m x 2n).
// z = zbase + blockIdx.z (so V can be launched separately on another stream).
__global__ __launch_bounds__(256) void qkv_mma_k(
    const float* __restrict__ bq, const float* __restrict__ bk,
    const float* __restrict__ bv, int zbase)
{
    extern __shared__ __align__(16) char qsm[];
    const int TILEB = 128*LDS_*2;                     // bytes per tile

    const int tid = threadIdx.x;
    const int wid = tid >> 5, lane = tid & 31;
    const int warp_m = wid & 3, warp_n = wid >> 2;
    const int z = zbase + blockIdx.z;
    const int row0 = blockIdx.x * 128;
    const int col0 = blockIdx.y * 128;
    const float* bias = (z == 0) ? bq : (z == 1) ? bk : bv;
    float* Y = (z == 0) ? g_Q : (z == 1) ? g_K : g_V;

    const uint32_t s0 = smem_u32(qsm);
    const uint32_t tAh[2] = { s0,           s0 + TILEB };
    const uint32_t tAl[2] = { s0 + 2*TILEB, s0 + 3*TILEB };
    const uint32_t tBh[2] = { s0 + 4*TILEB, s0 + 5*TILEB };
    const uint32_t tBl[2] = { s0 + 6*TILEB, s0 + 7*TILEB };

    const __nv_bfloat16* Ah = g_Xhi + (size_t)row0*HIDD;
    const __nv_bfloat16* Al = g_Xlo + (size_t)row0*HIDD;
    const __nv_bfloat16* Bh = g_Whi + (size_t)(z*HIDD + col0)*HIDD;
    const __nv_bfloat16* Bl = g_Wlo + (size_t)(z*HIDD + col0)*HIDD;

    const int ldrow0 = tid >> 2, ldc0 = (tid & 3) * 16;   // bytes
    const int ldrow1 = (tid + 256) >> 2;
    const int gofs0  = (tid & 3) * 8;                      // elems

    float acc[2][8][4];
#pragma unroll
    for (int mt = 0; mt < 2; mt++)
#pragma unroll
        for (int nt = 0; nt < 8; nt++)
#pragma unroll
            for (int q = 0; q < 4; q++) acc[mt][nt][q] = 0.f;

#define QSTAGE(nb, kb)                                                            \
    do {                                                                          \
        cpa16(tAh[nb] + ldrow0*(LDS_*2) + ldc0, Ah + (size_t)ldrow0*HIDD + (kb) + gofs0); \
        cpa16(tAh[nb] + ldrow1*(LDS_*2) + ldc0, Ah + (size_t)ldrow1*HIDD + (kb) + gofs0); \
        cpa16(tAl[nb] + ldrow0*(LDS_*2) + ldc0, Al + (size_t)ldrow0*HIDD + (kb) + gofs0); \
        cpa16(tAl[nb] + ldrow1*(LDS_*2) + ldc0, Al + (size_t)ldrow1*HIDD + (kb) + gofs0); \
        cpa16(tBh[nb] + ldrow0*(LDS_*2) + ldc0, Bh + (size_t)ldrow0*HIDD + (kb) + gofs0); \
        cpa16(tBh[nb] + ldrow1*(LDS_*2) + ldc0, Bh + (size_t)ldrow1*HIDD + (kb) + gofs0); \
        cpa16(tBl[nb] + ldrow0*(LDS_*2) + ldc0, Bl + (size_t)ldrow0*HIDD + (kb) + gofs0); \
        cpa16(tBl[nb] + ldrow1*(LDS_*2) + ldc0, Bl + (size_t)ldrow1*HIDD + (kb) + gofs0); \
        asm volatile("cp.async.commit_group;" ::: "memory");                      \
    } while (0)

    QSTAGE(0, 0);

    for (int it = 0; it < NITQ; it++) {
        const int cur = it & 1;
        if (it + 1 < NITQ) {
            QSTAGE(cur ^ 1, (it + 1) * BK);
            asm volatile("cp.async.wait_group 1;" ::: "memory");
        } else {
            asm volatile("cp.async.wait_group 0;" ::: "memory");
        }
        __syncthreads();

#pragma unroll
        for (int ks = 0; ks < 2; ks++) {
            const int kbyte = (ks*16 + ((lane >> 4) * 8)) * 2;
            uint32_t ah[2][4], al[2][4];
#pragma unroll
            for (int mt = 0; mt < 2; mt++) {
                int rr = warp_m*32 + mt*16 + (lane & 15);
                ldm_x4(ah[mt][0], ah[mt][1], ah[mt][2], ah[mt][3],
                       tAh[cur] + rr*(LDS_*2) + kbyte);
                ldm_x4(al[mt][0], al[mt][1], al[mt][2], al[mt][3],
                       tAl[cur] + rr*(LDS_*2) + kbyte);
            }
#pragma unroll
            for (int ng = 0; ng < 4; ng++) {
                int n = warp_n*64 + ng*16 + (lane & 15);
                uint32_t bh0, bh1, bh2, bh3, bl0, bl1, bl2, bl3;
                ldm_x4(bh0, bh1, bh2, bh3, tBh[cur] + n*(LDS_*2) + kbyte);
                ldm_x4(bl0, bl1, bl2, bl3, tBl[cur] + n*(LDS_*2) + kbyte);
#pragma unroll
                for (int mt = 0; mt < 2; mt++) {
                    mma16816(acc[mt][ng*2+0], ah[mt], bh0, bh2);
                    mma16816(acc[mt][ng*2+1], ah[mt], bh1, bh3);
                    mma16816(acc[mt][ng*2+0], al[mt], bh0, bh2);
                    mma16816(acc[mt][ng*2+1], al[mt], bh1, bh3);
                    mma16816(acc[mt][ng*2+0], ah[mt], bl0, bl2);
                    mma16816(acc[mt][ng*2+1], ah[mt], bl1, bl3);
                }
            }
        }
        __syncthreads();
    }
#undef QSTAGE

    // epilogue: bias add + f32 store (+ bf16 hi/lo of Q when z==0)
#pragma unroll
    for (int mt = 0; mt < 2; mt++) {
        const int r = row0 + warp_m*32 + mt*16 + (lane >> 2);
#pragma unroll
        for (int nt = 0; nt < 8; nt++) {
            const int cc = col0 + warp_n*64 + nt*8 + (lane & 3)*2;
            float v00 = acc[mt][nt][0] + bias[cc];
            float v01 = acc[mt][nt][1] + bias[cc+1];
            float v10 = acc[mt][nt][2] + bias[cc];
            float v11 = acc[mt][nt][3] + bias[cc+1];
            *(float2*)(Y + (size_t)r*HIDD + cc)     = make_float2(v00, v01);
            *(float2*)(Y + (size_t)(r+8)*HIDD + cc) = make_float2(v10, v11);
            if (z == 0) {
                __nv_bfloat16 h00 = __float2bfloat16(v00), h01 = __float2bfloat16(v01);
                __nv_bfloat16 h10 = __float2bfloat16(v10), h11 = __float2bfloat16(v11);
                __nv_bfloat162 hh0; hh0.x = h00; hh0.y = h01;
                __nv_bfloat162 hh1; hh1.x = h10; hh1.y = h11;
                __nv_bfloat162 ll0;
                ll0.x = __float2bfloat16(v00 - __bfloat162float(h00));
                ll0.y = __float2bfloat16(v01 - __bfloat162float(h01));
                __nv_bfloat162 ll1;
                ll1.x = __float2bfloat16(v10 - __bfloat162float(h10));
                ll1.y = __float2bfloat16(v11 - __bfloat162float(h11));
                *(__nv_bfloat162*)(g_Qhi + (size_t)r*HIDD + cc)     = hh0;
                *(__nv_bfloat162*)(g_Qhi + (size_t)(r+8)*HIDD + cc) = hh1;
                *(__nv_bfloat162*)(g_Qlo + (size_t)r*HIDD + cc)     = ll0;
                *(__nv_bfloat162*)(g_Qlo + (size_t)(r+8)*HIDD + cc) = ll1;
            }
        }
    }
}

// ---------------- edge logits via mma.sync, 1D exact-chunk grid ----------------
// P = Qh@Rh + Ql@Rh + Qh@Rl (K=64), then logit = (P·Ke)/8 in fp32.
// Block: 256 edge-head rows x 64 cols, 8 warps each 32 rows x 64 cols.
__global__ __launch_bounds__(256) void logits_mma_k(
    const int* __restrict__ ei, const float* __restrict__ rel)
{
    extern __shared__ __align__(16) char dsm[];
    __nv_bfloat16* sBh = (__nv_bfloat16*)dsm;
    __nv_bfloat16* sBl = (__nv_bfloat16*)(dsm + 9216);
    __nv_bfloat16* sAh = (__nv_bfloat16*)(dsm + 18432);
    __nv_bfloat16* sAl = (__nv_bfloat16*)(dsm + 55296);
    int* rowK  = (int*)(dsm + 92160);
    int* rowEH = (int*)(dsm + 93184);
    int* rowQ  = (int*)(dsm + 94208);
    __shared__ int sRel;

    const int bid = blockIdx.x;
    const int tid = threadIdx.x;
    const int wid = tid >> 5, lane = tid & 31;

    // locate (relation, chunk) from the prefix table with two ballots
    if (tid < 32) {
        unsigned f0 = __ballot_sync(0xffffffffu, g_chunk_off[lane+1]  <= bid);
        unsigned f1 = __ballot_sync(0xffffffffu, g_chunk_off[lane+33] <= bid);
        if (lane == 0) sRel = __popc(f0) + __popc(f1);
    }
    __syncthreads();
    const int r = sRel;
    if (r >= NREL) return;

    const int off  = g_rel_off[r];
    const int cnt  = g_rel_off[r+1] - off;
    const int rows = cnt * Hh;
    const int row0 = (bid - g_chunk_off[r]) * 256;
    if (row0 >= rows) return;

    {
        int row = row0 + tid;
        if (row < rows) {
            int el = row / Hh, h = row - el*Hh;
            int e  = g_rel_list[off + el];
            int b  = ei[e], hn = ei[Ee+e], tn = ei[2*Ee+e];
            rowQ[tid]  = (b*Nn + hn)*HIDD + h*Dh;
            rowK[tid]  = (b*Nn + tn)*HIDD + h*Dh;
            rowEH[tid] = e*Hh + h;
        } else {
            rowQ[tid] = 0; rowK[tid] = 0; rowEH[tid] = -1;
        }
    }

    // stage B = split of Re^T: sB*[n][d] from R[d][n]
    const float* Rg = rel + (size_t)r*4096;
#pragma unroll 4
    for (int i = tid; i < 4096; i += 256) {
        int d = i >> 6, n = i & 63;
        float f = Rg[i];
        __nv_bfloat16 hi = __float2bfloat16(f);
        sBh[n*LST + d] = hi;
        sBl[n*LST + d] = __float2bfloat16(f - __bfloat162float(hi));
    }

    // stage A from g_Qhi/g_Qlo (own rowQ slot — no sync needed for that read)
    {
        const int row = tid;
        const __nv_bfloat16* qh = g_Qhi + rowQ[row];
        const __nv_bfloat16* ql = g_Qlo + rowQ[row];
        __nv_bfloat16* dh = sAh + row*LST;
        __nv_bfloat16* dl = sAl + row*LST;
#pragma unroll
        for (int j = 0; j < 8; j++) {
            *(uint4*)(dh + j*8) = *(const uint4*)(qh + j*8);
            *(uint4*)(dl + j*8) = *(const uint4*)(ql + j*8);
        }
    }
    __syncthreads();

    const uint32_t sAhu = smem_u32(sAh), sAlu = smem_u32(sAl);
    const uint32_t sBhu = smem_u32(sBh), sBlu = smem_u32(sBl);

    float acc[2][8][4];
#pragma unroll
    for (int mt = 0; mt < 2; mt++)
#pragma unroll
        for (int nt = 0; nt < 8; nt++)
#pragma unroll
            for (int q = 0; q < 4; q++) acc[mt][nt][q] = 0.f;

#pragma unroll
    for (int ks = 0; ks < 4; ks++) {
        const int kbyte = (ks*16 + ((lane >> 4) * 8)) * 2;
        uint32_t ah[2][4], al[2][4];
#pragma unroll
        for (int mt = 0; mt < 2; mt++) {
            int rr = wid*32 + mt*16 + (lane & 15);
            ldm_x4(ah[mt][0], ah[mt][1], ah[mt][2], ah[mt][3],
                   sAhu + rr*(LST*2) + kbyte);
            ldm_x4(al[mt][0], al[mt][1], al[mt][2], al[mt][3],
                   sAlu + rr*(LST*2) + kbyte);
        }
#pragma unroll
        for (int ng = 0; ng < 4; ng++) {
            int n = ng*16 + (lane & 15);
            uint32_t bh0, bh1, bh2, bh3, bl0, bl1, bl2, bl3;
            ldm_x4(bh0, bh1, bh2, bh3, sBhu + n*(LST*2) + kbyte);
            ldm_x4(bl0, bl1, bl2, bl3, sBlu + n*(LST*2) + kbyte);
#pragma unroll
            for (int mt = 0; mt < 2; mt++) {
                mma16816(acc[mt][ng*2+0], ah[mt], bh0, bh2);
                mma16816(acc[mt][ng*2+1], ah[mt], bh1, bh3);
                mma16816(acc[mt][ng*2+0], al[mt], bh0, bh2);
                mma16816(acc[mt][ng*2+1], al[mt], bh1, bh3);
                mma16816(acc[mt][ng*2+0], ah[mt], bl0, bl2);
                mma16816(acc[mt][ng*2+1], ah[mt], bl1, bl3);
            }
        }
    }

    // logit = P . Ke  — each warp owns full rows: quad shfl completes the dot
#pragma unroll
    for (int mt = 0; mt < 2; mt++) {
        int rl0 = wid*32 + mt*16 + (lane >> 2);
        int rl1 = rl0 + 8;
        const float* k0p = g_K + rowK[rl0];
        const float* k1p = g_K + rowK[rl1];
        float s0 = 0.f, s1 = 0.f;
#pragma unroll
        for (int nt = 0; nt < 8; nt++) {
            int cc = (nt>>1)*16 + (nt&1)*8 + (lane & 3)*2;
            float2 kv0 = *(const float2*)(k0p + cc);
            float2 kv1 = *(const float2*)(k1p + cc);
            s0 += acc[mt][nt][0]*kv0.x + acc[mt][nt][1]*kv0.y;
            s1 += acc[mt][nt][2]*kv1.x + acc[mt][nt][3]*kv1.y;
        }
        s0 += __shfl_xor_sync(0xffffffffu, s0, 1);
        s0 += __shfl_xor_sync(0xffffffffu, s0, 2);
        s1 += __shfl_xor_sync(0xffffffffu, s1, 1);
        s1 += __shfl_xor_sync(0xffffffffu, s1, 2);
        if ((lane & 3) == 0) {
            if (rowEH[rl0] >= 0) g_logits[rowEH[rl0]] = s0 * 0.125f;
            if (rowEH[rl1] >= 0) g_logits[rowEH[rl1]] = s1 * 0.125f;
        }
    }
}

// ---------------- per-segment softmax + aggregation ----------------
__global__ __launch_bounds__(384) void softagg_k(
    const int* __restrict__ ei, float* __restrict__ out)
{
    __shared__ int sVoff[512];
    __shared__ int sEh[512];

    const int s   = blockIdx.x;
    const int off = g_seg_off[s];
    const int cnt = g_seg_off[s+1] - off;
    const int w = threadIdx.x >> 5, lane = threadIdx.x & 31;

    if (cnt == 0) {
        for (int i = threadIdx.x; i < HIDD; i += 384) out[(size_t)s*HIDD + i] = 0.f;
        return;
    }

    if (cnt <= 512) {
        for (int j = threadIdx.x; j < cnt; j += 384) {
            int e = g_seg_list[off+j];
            sVoff[j] = (ei[e]*Nn + ei[2*Ee+e])*HIDD;
            sEh[j]   = e*Hh;
        }
        __syncthreads();

        float m = -3.4e38f;
        for (int i = lane; i < cnt; i += 32)
            m = fmaxf(m, g_logits[sEh[i] + w]);
#pragma unroll
        for (int o = 16; o; o >>= 1) m = fmaxf(m, __shfl_xor_sync(0xffffffffu, m, o));

        float sm = 0.f;
        for (int i = lane; i < cnt; i += 32)
            sm += __expf(g_logits[sEh[i] + w] - m);
#pragma unroll
        for (int o = 16; o; o >>= 1) sm += __shfl_xor_sync(0xffffffffu, sm, o);
        const float rsc = 1.f / sm;

        float a0 = 0.f, a1 = 0.f;
#pragma unroll 4
        for (int i = 0; i < cnt; i++) {
            float p = __expf(g_logits[sEh[i] + w] - m);
            const float* vp = g_V + sVoff[i] + w*Dh;
            a0 += p * vp[lane];
            a1 += p * vp[lane+32];
        }
        out[(size_t)s*HIDD + w*Dh + lane]      = a0 * rsc;
        out[(size_t)s*HIDD + w*Dh + lane + 32] = a1 * rsc;
    } else {
        float m = -3.4e38f;
        for (int i = lane; i < cnt; i += 32)
            m = fmaxf(m, g_logits[g_seg_list[off+i]*Hh + w]);
#pragma unroll
        for (int o = 16; o; o >>= 1) m = fmaxf(m, __shfl_xor_sync(0xffffffffu, m, o));

        float sm = 0.f;
        for (int i = lane; i < cnt; i += 32)
            sm += __expf(g_logits[g_seg_list[off+i]*Hh + w] - m);
#pragma unroll
        for (int o = 16; o; o >>= 1) sm += __shfl_xor_sync(0xffffffffu, sm, o);
        const float rsc = 1.f / sm;

        float a0 = 0.f, a1 = 0.f;
        for (int i = 0; i < cnt; i++) {
            int e = g_seg_list[off+i];
            float p = __expf(g_logits[e*Hh + w] - m);
            const float* vp = g_V + ((size_t)(ei[e]*Nn + ei[2*Ee+e]))*HIDD + w*Dh;
            a0 += p * vp[lane];
            a1 += p * vp[lane+32];
        }
        out[(size_t)s*HIDD + w*Dh + lane]      = a0 * rsc;
        out[(size_t)s*HIDD + w*Dh + lane + 32] = a1 * rsc;
    }
}

// ---------------- launch ----------------
extern "C" void kernel_launch(void* const* d_in, const int* in_sizes, int n_in,
                              void* d_out, int out_size)
{
    const float* X    = (const float*)d_in[0];
    const int*   ei   = (const int*)  d_in[1];
    const float* Wq   = (const float*)d_in[3];
    const float* bq   = (const float*)d_in[4];
    const float* Wk   = (const float*)d_in[5];
    const float* bk   = (const float*)d_in[6];
    const float* Wv   = (const float*)d_in[7];
    const float* bv   = (const float*)d_in[8];
    const float* rel  = (const float*)d_in[9];
    float* out = (float*)d_out;

    cudaFuncSetAttribute(qkv_mma_k,
                         cudaFuncAttributeMaxDynamicSharedMemorySize, 81920);
    cudaFuncSetAttribute(logits_mma_k,
                         cudaFuncAttributeMaxDynamicSharedMemorySize, 95232);

    cudaStream_t s2;
    cudaStreamCreateWithFlags(&s2, cudaStreamNonBlocking);
    cudaEvent_t evF, evSort, evConv, evV;
    cudaEventCreateWithFlags(&evF,    cudaEventDisableTiming);
    cudaEventCreateWithFlags(&evSort, cudaEventDisableTiming);
    cudaEventCreateWithFlags(&evConv, cudaEventDisableTiming);
    cudaEventCreateWithFlags(&evV,    cudaEventDisableTiming);

    // fork side stream: sort chain, then the V projection (z=2)
    cudaEventRecord(evF, 0);
    cudaStreamWaitEvent(s2, evF, 0);
    zero_k   <<<8, 256, 0, s2>>>();
    hist_k   <<<Ee/256, 256, 0, s2>>>(ei);
    scan_k   <<<1, 1024, 0, s2>>>();
    scatter_k<<<Ee/256, 256, 0, s2>>>(ei);
    cudaEventRecord(evSort, s2);

    // main stream: conversions + Q,K projections
    convX_k  <<<(NSEG*HIDD)/256, 256>>>(X);
    convW_k  <<<dim3((HIDD*HIDD)/256, 3), 256>>>(Wq, Wk, Wv);
    cudaEventRecord(evConv, 0);

    // V projection on side stream (after conversions), overlaps with logits
    cudaStreamWaitEvent(s2, evConv, 0);
    qkv_mma_k<<<dim3(16, 6, 1), 256, 81920, s2>>>(bq, bk, bv, 2);
    cudaEventRecord(evV, s2);

    // Q,K projections on main stream
    qkv_mma_k<<<dim3(16, 6, 2), 256, 81920>>>(bq, bk, bv, 0);

    cudaStreamWaitEvent(0, evSort, 0);   // logits needs relation sort
    logits_mma_k<<<NCHK, 256, 95232>>>(ei, rel);

    cudaStreamWaitEvent(0, evV, 0);      // softagg needs V
    softagg_k<<<NSEG, 384>>>(ei, out);
}

// round 14
// speedup vs baseline: 2.6578x; 1.1524x over previous
#include <cuda_runtime.h>
#include <cuda_fp16.h>
#include <cstdint>

#define Bq   4
#define Nn   512
#define Hh   12
#define Dh   64
#define HIDD 768
#define Ee   65536
#define NREL 64
#define NSEG (Bq*Nn)      // 2048
#define BK   32
#define NITQ (HIDD/BK)    // 24
#define LDS_ 40           // qkv smem row stride (fp16 elems)
#define LST  72           // logits smem row stride (fp16 elems)
#define NCHK 3136         // max total 256-row chunks over all relations

__device__ __forceinline__ uint32_t smem_u32(const void* p) {
    uint32_t a;
    asm("{ .reg .u64 t; cvta.to.shared.u64 t, %1; cvt.u32.u64 %0, t; }"
        : "=r"(a) : "l"(p));
    return a;
}
__device__ __forceinline__ void ldm_x4(uint32_t& r0, uint32_t& r1, uint32_t& r2,
                                       uint32_t& r3, uint32_t addr) {
    asm volatile("ldmatrix.sync.aligned.m8n8.x4.shared.b16 {%0,%1,%2,%3},[%4];"
                 : "=r"(r0), "=r"(r1), "=r"(r2), "=r"(r3) : "r"(addr));
}
__device__ __forceinline__ void mma16816(float* c, const uint32_t* a,
                                         uint32_t b0, uint32_t b1) {
    asm volatile("mma.sync.aligned.m16n8k16.row.col.f32.f16.f16.f32 "
                 "{%0,%1,%2,%3},{%4,%5,%6,%7},{%8,%9},{%0,%1,%2,%3};"
                 : "+f"(c[0]), "+f"(c[1]), "+f"(c[2]), "+f"(c[3])
                 : "r"(a[0]), "r"(a[1]), "r"(a[2]), "r"(a[3]), "r"(b0), "r"(b1));
}
__device__ __forceinline__ void cpa16(uint32_t s, const void* g) {
    asm volatile("cp.async.cg.shared.global [%0],[%1],16;" :: "r"(s), "l"(g));
}

// ---------------- device scratch ----------------
__device__ float g_Q[NSEG*HIDD];
__device__ float g_K[NSEG*HIDD];
__device__ float g_V[NSEG*HIDD];
__device__ __half g_Qhi[NSEG*HIDD];
__device__ __half g_Qlo[NSEG*HIDD];
__device__ float g_logits[Ee*Hh];
__device__ int   g_rel_cnt[NREL], g_rel_off[NREL+1], g_rel_cur[NREL];
__device__ int   g_chunk_off[NREL+1];
__device__ int   g_seg_cnt[NSEG], g_seg_off[NSEG+1], g_seg_cur[NSEG];
__device__ int   g_rel_list[Ee], g_seg_list[Ee];
__device__ __half g_Xhi[NSEG*HIDD];
__device__ __half g_Xlo[NSEG*HIDD];
__device__ __half g_Whi[3*HIDD*HIDD];

// ---------------- counting sorts ----------------
__global__ void zero_k() {
    int i = blockIdx.x*blockDim.x + threadIdx.x;
    if (i < NREL) g_rel_cnt[i] = 0;
    if (i < NSEG) g_seg_cnt[i] = 0;
}

__global__ void hist_k(const int* __restrict__ ei) {
    __shared__ int relh[NREL];
    int t = threadIdx.x;
    if (t < NREL) relh[t] = 0;
    __syncthreads();
    int e = blockIdx.x*blockDim.x + t;
    int b = ei[e], hn = ei[Ee+e], r = ei[3*Ee+e];
    atomicAdd(&relh[r], 1);
    atomicAdd(&g_seg_cnt[b*Nn + hn], 1);
    __syncthreads();
    if (t < NREL && relh[t]) atomicAdd(&g_rel_cnt[t], relh[t]);
}

// two-level shfl scan, 1024 threads, 2 elems/thread
__global__ void scan_k() {
    __shared__ int wsum[32];
    int t = threadIdx.x, lane = t & 31, w = t >> 5;
    int v0 = g_seg_cnt[2*t], v1 = g_seg_cnt[2*t+1];
    int s = v0 + v1, sc = s;
#pragma unroll
    for (int o = 1; o < 32; o <<= 1) {
        int u = __shfl_up_sync(0xffffffffu, sc, o);
        if (lane >= o) sc += u;
    }
    if (lane == 31) wsum[w] = sc;
    __syncthreads();
    if (w == 0) {
        int ws = wsum[lane];
#pragma unroll
        for (int o = 1; o < 32; o <<= 1) {
            int u = __shfl_up_sync(0xffffffffu, ws, o);
            if (lane >= o) ws += u;
        }
        wsum[lane] = ws;
    }
    __syncthreads();
    int base = (w ? wsum[w-1] : 0) + (sc - s);   // exclusive prefix of elem 2t
    g_seg_cur[2*t]   = base;
    g_seg_cur[2*t+1] = base + v0;
    if (t == 0) g_seg_off[0] = 0;
    g_seg_off[2*t+1] = base + v0;
    g_seg_off[2*t+2] = base + v0 + v1;
    if (t == 0) {
        int acc = 0, acc2 = 0;
        for (int r = 0; r < NREL; r++) {
            g_rel_off[r] = acc; g_rel_cur[r] = acc;
            g_chunk_off[r] = acc2;
            acc  += g_rel_cnt[r];
            acc2 += (g_rel_cnt[r]*Hh + 255) >> 8;
        }
        g_rel_off[NREL]   = acc;
        g_chunk_off[NREL] = acc2;
    }
}

__global__ void scatter_k(const int* __restrict__ ei) {
    __shared__ int relh[NREL], relbase[NREL];
    int t = threadIdx.x;
    if (t < NREL) relh[t] = 0;
    __syncthreads();
    int e = blockIdx.x*blockDim.x + t;
    int b = ei[e], hn = ei[Ee+e], r = ei[3*Ee+e];
    int myofs = atomicAdd(&relh[r], 1);
    __syncthreads();
    if (t < NREL) relbase[t] = relh[t] ? atomicAdd(&g_rel_cur[t], relh[t]) : 0;
    __syncthreads();
    g_rel_list[relbase[r] + myofs] = e;
    int p2 = atomicAdd(&g_seg_cur[b*Nn + hn], 1); g_seg_list[p2] = e;
}

// ---------------- fp16 hi/lo conversion ----------------
__global__ void convX_k(const float* __restrict__ X) {
    int i = blockIdx.x*blockDim.x + threadIdx.x;     // over 2048*768
    float x = X[i];
    __half hi = __float2half_rn(x);
    g_Xhi[i] = hi;
    g_Xlo[i] = __float2half_rn(x - __half2float(hi));
}

__global__ void convW_k(const float* __restrict__ Wq,
                        const float* __restrict__ Wk,
                        const float* __restrict__ Wv) {
    int z = blockIdx.y;
    const float* W = (z == 0) ? Wq : (z == 1) ? Wk : Wv;
    int i = blockIdx.x*blockDim.x + threadIdx.x;     // over 768*768
    g_Whi[(size_t)z*HIDD*HIDD + i] = __float2half_rn(W[i]);
}

// ---------------- QKV via mma.sync, fp16 2-product ----------------
// C = Ah@Bh + Al@Bh.  128x128 tile, BK=32, 24 iters, 8 warps (4m x 2n).
// z = zbase + blockIdx.z.
__global__ __launch_bounds__(256) void qkv_mma_k(
    const float* __restrict__ bq, const float* __restrict__ bk,
    const float* __restrict__ bv, int zbase)
{
    extern __shared__ __align__(16) char qsm[];
    const int TILEB = 128*LDS_*2;                     // bytes per tile

    const int tid = threadIdx.x;
    const int wid = tid >> 5, lane = tid & 31;
    const int warp_m = wid & 3, warp_n = wid >> 2;
    const int z = zbase + blockIdx.z;
    const int row0 = blockIdx.x * 128;
    const int col0 = blockIdx.y * 128;
    const float* bias = (z == 0) ? bq : (z == 1) ? bk : bv;
    float* Y = (z == 0) ? g_Q : (z == 1) ? g_K : g_V;

    const uint32_t s0 = smem_u32(qsm);
    const uint32_t tAh[2] = { s0,           s0 + TILEB };
    const uint32_t tAl[2] = { s0 + 2*TILEB, s0 + 3*TILEB };
    const uint32_t tBh[2] = { s0 + 4*TILEB, s0 + 5*TILEB };

    const __half* Ah = g_Xhi + (size_t)row0*HIDD;
    const __half* Al = g_Xlo + (size_t)row0*HIDD;
    const __half* Bh = g_Whi + (size_t)(z*HIDD + col0)*HIDD;

    const int ldrow0 = tid >> 2, ldc0 = (tid & 3) * 16;   // bytes
    const int ldrow1 = (tid + 256) >> 2;
    const int gofs0  = (tid & 3) * 8;                      // elems

    float acc[2][8][4];
#pragma unroll
    for (int mt = 0; mt < 2; mt++)
#pragma unroll
        for (int nt = 0; nt < 8; nt++)
#pragma unroll
            for (int q = 0; q < 4; q++) acc[mt][nt][q] = 0.f;

#define QSTAGE(nb, kb)                                                            \
    do {                                                                          \
        cpa16(tAh[nb] + ldrow0*(LDS_*2) + ldc0, Ah + (size_t)ldrow0*HIDD + (kb) + gofs0); \
        cpa16(tAh[nb] + ldrow1*(LDS_*2) + ldc0, Ah + (size_t)ldrow1*HIDD + (kb) + gofs0); \
        cpa16(tAl[nb] + ldrow0*(LDS_*2) + ldc0, Al + (size_t)ldrow0*HIDD + (kb) + gofs0); \
        cpa16(tAl[nb] + ldrow1*(LDS_*2) + ldc0, Al + (size_t)ldrow1*HIDD + (kb) + gofs0); \
        cpa16(tBh[nb] + ldrow0*(LDS_*2) + ldc0, Bh + (size_t)ldrow0*HIDD + (kb) + gofs0); \
        cpa16(tBh[nb] + ldrow1*(LDS_*2) + ldc0, Bh + (size_t)ldrow1*HIDD + (kb) + gofs0); \
        asm volatile("cp.async.commit_group;" ::: "memory");                      \
    } while (0)

    QSTAGE(0, 0);

    for (int it = 0; it < NITQ; it++) {
        const int cur = it & 1;
        if (it + 1 < NITQ) {
            QSTAGE(cur ^ 1, (it + 1) * BK);
            asm volatile("cp.async.wait_group 1;" ::: "memory");
        } else {
            asm volatile("cp.async.wait_group 0;" ::: "memory");
        }
        __syncthreads();

#pragma unroll
        for (int ks = 0; ks < 2; ks++) {
            const int kbyte = (ks*16 + ((lane >> 4) * 8)) * 2;
            uint32_t ah[2][4], al[2][4];
#pragma unroll
            for (int mt = 0; mt < 2; mt++) {
                int rr = warp_m*32 + mt*16 + (lane & 15);
                ldm_x4(ah[mt][0], ah[mt][1], ah[mt][2], ah[mt][3],
                       tAh[cur] + rr*(LDS_*2) + kbyte);
                ldm_x4(al[mt][0], al[mt][1], al[mt][2], al[mt][3],
                       tAl[cur] + rr*(LDS_*2) + kbyte);
            }
#pragma unroll
            for (int ng = 0; ng < 4; ng++) {
                int n = warp_n*64 + ng*16 + (lane & 15);
                uint32_t bh0, bh1, bh2, bh3;
                ldm_x4(bh0, bh1, bh2, bh3, tBh[cur] + n*(LDS_*2) + kbyte);
#pragma unroll
                for (int mt = 0; mt < 2; mt++) {
                    mma16816(acc[mt][ng*2+0], ah[mt], bh0, bh2);
                    mma16816(acc[mt][ng*2+1], ah[mt], bh1, bh3);
                    mma16816(acc[mt][ng*2+0], al[mt], bh0, bh2);
                    mma16816(acc[mt][ng*2+1], al[mt], bh1, bh3);
                }
            }
        }
        __syncthreads();
    }
#undef QSTAGE

    // epilogue: bias add + f32 store (+ fp16 hi/lo of Q when z==0)
#pragma unroll
    for (int mt = 0; mt < 2; mt++) {
        const int r = row0 + warp_m*32 + mt*16 + (lane >> 2);
#pragma unroll
        for (int nt = 0; nt < 8; nt++) {
            const int cc = col0 + warp_n*64 + nt*8 + (lane & 3)*2;
            float v00 = acc[mt][nt][0] + bias[cc];
            float v01 = acc[mt][nt][1] + bias[cc+1];
            float v10 = acc[mt][nt][2] + bias[cc];
            float v11 = acc[mt][nt][3] + bias[cc+1];
            *(float2*)(Y + (size_t)r*HIDD + cc)     = make_float2(v00, v01);
            *(float2*)(Y + (size_t)(r+8)*HIDD + cc) = make_float2(v10, v11);
            if (z == 0) {
                __half h00 = __float2half_rn(v00), h01 = __float2half_rn(v01);
                __half h10 = __float2half_rn(v10), h11 = __float2half_rn(v11);
                __half2 hh0; hh0.x = h00; hh0.y = h01;
                __half2 hh1; hh1.x = h10; hh1.y = h11;
                __half2 ll0;
                ll0.x = __float2half_rn(v00 - __half2float(h00));
                ll0.y = __float2half_rn(v01 - __half2float(h01));
                __half2 ll1;
                ll1.x = __float2half_rn(v10 - __half2float(h10));
                ll1.y = __float2half_rn(v11 - __half2float(h11));
                *(__half2*)(g_Qhi + (size_t)r*HIDD + cc)     = hh0;
                *(__half2*)(g_Qhi + (size_t)(r+8)*HIDD + cc) = hh1;
                *(__half2*)(g_Qlo + (size_t)r*HIDD + cc)     = ll0;
                *(__half2*)(g_Qlo + (size_t)(r+8)*HIDD + cc) = ll1;
            }
        }
    }
}

// ---------------- edge logits via mma.sync, fp16 2-product ----------------
// P = Qh@Rh + Ql@Rh (K=64), then logit = (P·Ke)/8 in fp32.
// Block: 256 edge-head rows x 64 cols, 8 warps each 32 rows x 64 cols.
// Dynamic smem (bytes): sBh@0 (9216) | sAh@9216 (36864) | sAl@46080 (36864)
//   | rowK@82944 | rowEH@83968 | rowQ@84992  => 86016
__global__ __launch_bounds__(256) void logits_mma_k(
    const int* __restrict__ ei, const float* __restrict__ rel)
{
    extern __shared__ __align__(16) char dsm[];
    __half* sBh = (__half*)dsm;
    __half* sAh = (__half*)(dsm + 9216);
    __half* sAl = (__half*)(dsm + 46080);
    int* rowK  = (int*)(dsm + 82944);
    int* rowEH = (int*)(dsm + 83968);
    int* rowQ  = (int*)(dsm + 84992);
    __shared__ int sRel;

    const int bid = blockIdx.x;
    const int tid = threadIdx.x;
    const int wid = tid >> 5, lane = tid & 31;

    // locate (relation, chunk) from the prefix table with two ballots
    if (tid < 32) {
        unsigned f0 = __ballot_sync(0xffffffffu, g_chunk_off[lane+1]  <= bid);
        unsigned f1 = __ballot_sync(0xffffffffu, g_chunk_off[lane+33] <= bid);
        if (lane == 0) sRel = __popc(f0) + __popc(f1);
    }
    __syncthreads();
    const int r = sRel;
    if (r >= NREL) return;

    const int off  = g_rel_off[r];
    const int cnt  = g_rel_off[r+1] - off;
    const int rows = cnt * Hh;
    const int row0 = (bid - g_chunk_off[r]) * 256;
    if (row0 >= rows) return;

    {
        int row = row0 + tid;
        if (row < rows) {
            int el = row / Hh, h = row - el*Hh;
            int e  = g_rel_list[off + el];
            int b  = ei[e], hn = ei[Ee+e], tn = ei[2*Ee+e];
            rowQ[tid]  = (b*Nn + hn)*HIDD + h*Dh;
            rowK[tid]  = (b*Nn + tn)*HIDD + h*Dh;
            rowEH[tid] = e*Hh + h;
        } else {
            rowQ[tid] = 0; rowK[tid] = 0; rowEH[tid] = -1;
        }
    }

    // stage B = Re^T rounded to fp16: sBh[n][d] from R[d][n]
    const float* Rg = rel + (size_t)r*4096;
#pragma unroll 4
    for (int i = tid; i < 4096; i += 256) {
        int d = i >> 6, n = i & 63;
        sBh[n*LST + d] = __float2half_rn(Rg[i]);
    }

    // stage A from g_Qhi/g_Qlo (own rowQ slot — no sync needed for that read)
    {
        const int row = tid;
        const __half* qh = g_Qhi + rowQ[row];
        const __half* ql = g_Qlo + rowQ[row];
        __half* dh = sAh + row*LST;
        __half* dl = sAl + row*LST;
#pragma unroll
        for (int j = 0; j < 8; j++) {
            *(uint4*)(dh + j*8) = *(const uint4*)(qh + j*8);
            *(uint4*)(dl + j*8) = *(const uint4*)(ql + j*8);
        }
    }
    __syncthreads();

    const uint32_t sAhu = smem_u32(sAh), sAlu = smem_u32(sAl);
    const uint32_t sBhu = smem_u32(sBh);

    float acc[2][8][4];
#pragma unroll
    for (int mt = 0; mt < 2; mt++)
#pragma unroll
        for (int nt = 0; nt < 8; nt++)
#pragma unroll
            for (int q = 0; q < 4; q++) acc[mt][nt][q] = 0.f;

#pragma unroll
    for (int ks = 0; ks < 4; ks++) {
        const int kbyte = (ks*16 + ((lane >> 4) * 8)) * 2;
        uint32_t ah[2][4], al[2][4];
#pragma unroll
        for (int mt = 0; mt < 2; mt++) {
            int rr = wid*32 + mt*16 + (lane & 15);
            ldm_x4(ah[mt][0], ah[mt][1], ah[mt][2], ah[mt][3],
                   sAhu + rr*(LST*2) + kbyte);
            ldm_x4(al[mt][0], al[mt][1], al[mt][2], al[mt][3],
                   sAlu + rr*(LST*2) + kbyte);
        }
#pragma unroll
        for (int ng = 0; ng < 4; ng++) {
            int n = ng*16 + (lane & 15);
            uint32_t bh0, bh1, bh2, bh3;
            ldm_x4(bh0, bh1, bh2, bh3, sBhu + n*(LST*2) + kbyte);
#pragma unroll
            for (int mt = 0; mt < 2; mt++) {
                mma16816(acc[mt][ng*2+0], ah[mt], bh0, bh2);
                mma16816(acc[mt][ng*2+1], ah[mt], bh1, bh3);
                mma16816(acc[mt][ng*2+0], al[mt], bh0, bh2);
                mma16816(acc[mt][ng*2+1], al[mt], bh1, bh3);
            }
        }
    }

    // logit = P . Ke  — each warp owns full rows: quad shfl completes the dot
#pragma unroll
    for (int mt = 0; mt < 2; mt++) {
        int rl0 = wid*32 + mt*16 + (lane >> 2);
        int rl1 = rl0 + 8;
        const float* k0p = g_K + rowK[rl0];
        const float* k1p = g_K + rowK[rl1];
        float s0 = 0.f, s1 = 0.f;
#pragma unroll
        for (int nt = 0; nt < 8; nt++) {
            int cc = (nt>>1)*16 + (nt&1)*8 + (lane & 3)*2;
            float2 kv0 = *(const float2*)(k0p + cc);
            float2 kv1 = *(const float2*)(k1p + cc);
            s0 += acc[mt][nt][0]*kv0.x + acc[mt][nt][1]*kv0.y;
            s1 += acc[mt][nt][2]*kv1.x + acc[mt][nt][3]*kv1.y;
        }
        s0 += __shfl_xor_sync(0xffffffffu, s0, 1);
        s0 += __shfl_xor_sync(0xffffffffu, s0, 2);
        s1 += __shfl_xor_sync(0xffffffffu, s1, 1);
        s1 += __shfl_xor_sync(0xffffffffu, s1, 2);
        if ((lane & 3) == 0) {
            if (rowEH[rl0] >= 0) g_logits[rowEH[rl0]] = s0 * 0.125f;
            if (rowEH[rl1] >= 0) g_logits[rowEH[rl1]] = s1 * 0.125f;
        }
    }
}

// ---------------- per-segment softmax + aggregation ----------------
__global__ __launch_bounds__(384) void softagg_k(
    const int* __restrict__ ei, float* __restrict__ out)
{
    __shared__ int sVoff[512];
    __shared__ int sEh[512];

    const int s   = blockIdx.x;
    const int off = g_seg_off[s];
    const int cnt = g_seg_off[s+1] - off;
    const int w = threadIdx.x >> 5, lane = threadIdx.x & 31;

    if (cnt == 0) {
        for (int i = threadIdx.x; i < HIDD; i += 384) out[(size_t)s*HIDD + i] = 0.f;
        return;
    }

    if (cnt <= 512) {
        for (int j = threadIdx.x; j < cnt; j += 384) {
            int e = g_seg_list[off+j];
            sVoff[j] = (ei[e]*Nn + ei[2*Ee+e])*HIDD;
            sEh[j]   = e*Hh;
        }
        __syncthreads();

        float m = -3.4e38f;
        for (int i = lane; i < cnt; i += 32)
            m = fmaxf(m, g_logits[sEh[i] + w]);
#pragma unroll
        for (int o = 16; o; o >>= 1) m = fmaxf(m, __shfl_xor_sync(0xffffffffu, m, o));

        float sm = 0.f;
        for (int i = lane; i < cnt; i += 32)
            sm += __expf(g_logits[sEh[i] + w] - m);
#pragma unroll
        for (int o = 16; o; o >>= 1) sm += __shfl_xor_sync(0xffffffffu, sm, o);
        const float rsc = 1.f / sm;

        float a0 = 0.f, a1 = 0.f;
#pragma unroll 4
        for (int i = 0; i < cnt; i++) {
            float p = __expf(g_logits[sEh[i] + w] - m);
            const float* vp = g_V + sVoff[i] + w*Dh;
            a0 += p * vp[lane];
            a1 += p * vp[lane+32];
        }
        out[(size_t)s*HIDD + w*Dh + lane]      = a0 * rsc;
        out[(size_t)s*HIDD + w*Dh + lane + 32] = a1 * rsc;
    } else {
        float m = -3.4e38f;
        for (int i = lane; i < cnt; i += 32)
            m = fmaxf(m, g_logits[g_seg_list[off+i]*Hh + w]);
#pragma unroll
        for (int o = 16; o; o >>= 1) m = fmaxf(m, __shfl_xor_sync(0xffffffffu, m, o));

        float sm = 0.f;
        for (int i = lane; i < cnt; i += 32)
            sm += __expf(g_logits[g_seg_list[off+i]*Hh + w] - m);
#pragma unroll
        for (int o = 16; o; o >>= 1) sm += __shfl_xor_sync(0xffffffffu, sm, o);
        const float rsc = 1.f / sm;

        float a0 = 0.f, a1 = 0.f;
        for (int i = 0; i < cnt; i++) {
            int e = g_seg_list[off+i];
            float p = __expf(g_logits[e*Hh + w] - m);
            const float* vp = g_V + ((size_t)(ei[e]*Nn + ei[2*Ee+e]))*HIDD + w*Dh;
            a0 += p * vp[lane];
            a1 += p * vp[lane+32];
        }
        out[(size_t)s*HIDD + w*Dh + lane]      = a0 * rsc;
        out[(size_t)s*HIDD + w*Dh + lane + 32] = a1 * rsc;
    }
}

// ---------------- launch ----------------
extern "C" void kernel_launch(void* const* d_in, const int* in_sizes, int n_in,
                              void* d_out, int out_size)
{
    const float* X    = (const float*)d_in[0];
    const int*   ei   = (const int*)  d_in[1];
    const float* Wq   = (const float*)d_in[3];
    const float* bq   = (const float*)d_in[4];
    const float* Wk   = (const float*)d_in[5];
    const float* bk   = (const float*)d_in[6];
    const float* Wv   = (const float*)d_in[7];
    const float* bv   = (const float*)d_in[8];
    const float* rel  = (const float*)d_in[9];
    float* out = (float*)d_out;

    cudaFuncSetAttribute(qkv_mma_k,
                         cudaFuncAttributeMaxDynamicSharedMemorySize, 61440);
    cudaFuncSetAttribute(logits_mma_k,
                         cudaFuncAttributeMaxDynamicSharedMemorySize, 86016);

    cudaStream_t s2;
    cudaStreamCreateWithFlags(&s2, cudaStreamNonBlocking);
    cudaEvent_t evF, evSort, evConv, evV;
    cudaEventCreateWithFlags(&evF,    cudaEventDisableTiming);
    cudaEventCreateWithFlags(&evSort, cudaEventDisableTiming);
    cudaEventCreateWithFlags(&evConv, cudaEventDisableTiming);
    cudaEventCreateWithFlags(&evV,    cudaEventDisableTiming);

    // fork side stream: sort chain, then the V projection (z=2)
    cudaEventRecord(evF, 0);
    cudaStreamWaitEvent(s2, evF, 0);
    zero_k   <<<8, 256, 0, s2>>>();
    hist_k   <<<Ee/256, 256, 0, s2>>>(ei);
    scan_k   <<<1, 1024, 0, s2>>>();
    scatter_k<<<Ee/256, 256, 0, s2>>>(ei);
    cudaEventRecord(evSort, s2);

    // main stream: conversions + Q,K projections
    convX_k  <<<(NSEG*HIDD)/256, 256>>>(X);
    convW_k  <<<dim3((HIDD*HIDD)/256, 3), 256>>>(Wq, Wk, Wv);
    cudaEventRecord(evConv, 0);

    // V projection on side stream (after conversions), overlaps with logits
    cudaStreamWaitEvent(s2, evConv, 0);
    qkv_mma_k<<<dim3(16, 6, 1), 256, 61440, s2>>>(bq, bk, bv, 2);
    cudaEventRecord(evV, s2);

    // Q,K projections on main stream
    qkv_mma_k<<<dim3(16, 6, 2), 256, 61440>>>(bq, bk, bv, 0);

    cudaStreamWaitEvent(0, evSort, 0);   // logits needs relation sort
    logits_mma_k<<<NCHK, 256, 86016>>>(ei, rel);

    cudaStreamWaitEvent(0, evV, 0);      // softagg needs V
    softagg_k<<<NSEG, 384>>>(ei, out);
}

// round 15
// speedup vs baseline: 2.6671x; 1.0035x over previous
#include <cuda_runtime.h>
#include <cuda_fp16.h>
#include <cstdint>

#define Bq   4
#define Nn   512
#define Hh   12
#define Dh   64
#define HIDD 768
#define Ee   65536
#define NREL 64
#define NSEG (Bq*Nn)      // 2048
#define BK   32
#define NITQ (HIDD/BK)    // 24
#define LDS_ 40           // qkv smem row stride (fp16 elems)
#define LST  72           // logits smem row stride (fp16 elems)
#define NCHK 3136         // max total 256-row chunks over all relations
#define NXEL (NSEG*HIDD)  // 1572864

__device__ __forceinline__ uint32_t smem_u32(const void* p) {
    uint32_t a;
    asm("{ .reg .u64 t; cvta.to.shared.u64 t, %1; cvt.u32.u64 %0, t; }"
        : "=r"(a) : "l"(p));
    return a;
}
__device__ __forceinline__ void ldm_x4(uint32_t& r0, uint32_t& r1, uint32_t& r2,
                                       uint32_t& r3, uint32_t addr) {
    asm volatile("ldmatrix.sync.aligned.m8n8.x4.shared.b16 {%0,%1,%2,%3},[%4];"
                 : "=r"(r0), "=r"(r1), "=r"(r2), "=r"(r3) : "r"(addr));
}
__device__ __forceinline__ void mma16816(float* c, const uint32_t* a,
                                         uint32_t b0, uint32_t b1) {
    asm volatile("mma.sync.aligned.m16n8k16.row.col.f32.f16.f16.f32 "
                 "{%0,%1,%2,%3},{%4,%5,%6,%7},{%8,%9},{%0,%1,%2,%3};"
                 : "+f"(c[0]), "+f"(c[1]), "+f"(c[2]), "+f"(c[3])
                 : "r"(a[0]), "r"(a[1]), "r"(a[2]), "r"(a[3]), "r"(b0), "r"(b1));
}
__device__ __forceinline__ void cpa16(uint32_t s, const void* g) {
    asm volatile("cp.async.cg.shared.global [%0],[%1],16;" :: "r"(s), "l"(g));
}

// ---------------- device scratch ----------------
__device__ float g_Q[NSEG*HIDD];
__device__ float g_K[NSEG*HIDD];
__device__ float g_V[NSEG*HIDD];
__device__ __half g_Qhi[NSEG*HIDD];
__device__ __half g_Qlo[NSEG*HIDD];
__device__ float g_logits[Ee*Hh];
__device__ int   g_rel_cnt[NREL], g_rel_off[NREL+1], g_rel_cur[NREL];
__device__ int   g_chunk_off[NREL+1];
__device__ int   g_seg_cnt[NSEG], g_seg_off[NSEG+1], g_seg_cur[NSEG];
__device__ int   g_rel_list[Ee], g_seg_list[Ee];
__device__ __half g_Xhi[NSEG*HIDD];
__device__ __half g_Xlo[NSEG*HIDD];
__device__ __half g_Whi[3*HIDD*HIDD];

// ---------------- counting sorts ----------------
__global__ void zero_k() {
    int i = blockIdx.x*blockDim.x + threadIdx.x;
    if (i < NREL) g_rel_cnt[i] = 0;
    if (i < NSEG) g_seg_cnt[i] = 0;
}

__global__ void hist_k(const int* __restrict__ ei) {
    __shared__ int relh[NREL];
    int t = threadIdx.x;
    if (t < NREL) relh[t] = 0;
    __syncthreads();
    int e = blockIdx.x*blockDim.x + t;
    int b = ei[e], hn = ei[Ee+e], r = ei[3*Ee+e];
    atomicAdd(&relh[r], 1);
    atomicAdd(&g_seg_cnt[b*Nn + hn], 1);
    __syncthreads();
    if (t < NREL && relh[t]) atomicAdd(&g_rel_cnt[t], relh[t]);
}

// two-level shfl scan, 1024 threads, 2 elems/thread
__global__ void scan_k() {
    __shared__ int wsum[32];
    int t = threadIdx.x, lane = t & 31, w = t >> 5;
    int v0 = g_seg_cnt[2*t], v1 = g_seg_cnt[2*t+1];
    int s = v0 + v1, sc = s;
#pragma unroll
    for (int o = 1; o < 32; o <<= 1) {
        int u = __shfl_up_sync(0xffffffffu, sc, o);
        if (lane >= o) sc += u;
    }
    if (lane == 31) wsum[w] = sc;
    __syncthreads();
    if (w == 0) {
        int ws = wsum[lane];
#pragma unroll
        for (int o = 1; o < 32; o <<= 1) {
            int u = __shfl_up_sync(0xffffffffu, ws, o);
            if (lane >= o) ws += u;
        }
        wsum[lane] = ws;
    }
    __syncthreads();
    int base = (w ? wsum[w-1] : 0) + (sc - s);   // exclusive prefix of elem 2t
    g_seg_cur[2*t]   = base;
    g_seg_cur[2*t+1] = base + v0;
    if (t == 0) g_seg_off[0] = 0;
    g_seg_off[2*t+1] = base + v0;
    g_seg_off[2*t+2] = base + v0 + v1;
    if (t == 0) {
        int acc = 0, acc2 = 0;
        for (int r = 0; r < NREL; r++) {
            g_rel_off[r] = acc; g_rel_cur[r] = acc;
            g_chunk_off[r] = acc2;
            acc  += g_rel_cnt[r];
            acc2 += (g_rel_cnt[r]*Hh + 255) >> 8;
        }
        g_rel_off[NREL]   = acc;
        g_chunk_off[NREL] = acc2;
    }
}

__global__ void scatter_k(const int* __restrict__ ei) {
    __shared__ int relh[NREL], relbase[NREL];
    int t = threadIdx.x;
    if (t < NREL) relh[t] = 0;
    __syncthreads();
    int e = blockIdx.x*blockDim.x + t;
    int b = ei[e], hn = ei[Ee+e], r = ei[3*Ee+e];
    int myofs = atomicAdd(&relh[r], 1);
    __syncthreads();
    if (t < NREL) relbase[t] = relh[t] ? atomicAdd(&g_rel_cur[t], relh[t]) : 0;
    __syncthreads();
    g_rel_list[relbase[r] + myofs] = e;
    int p2 = atomicAdd(&g_seg_cur[b*Nn + hn], 1); g_seg_list[p2] = e;
}

// ---------------- merged fp16 conversion (X hi/lo + W hi) ----------------
__global__ void conv_k(const float* __restrict__ X,
                       const float* __restrict__ Wq,
                       const float* __restrict__ Wk,
                       const float* __restrict__ Wv) {
    int i = blockIdx.x*blockDim.x + threadIdx.x;
    if (i < NXEL) {
        float x = X[i];
        __half hi = __float2half_rn(x);
        g_Xhi[i] = hi;
        g_Xlo[i] = __float2half_rn(x - __half2float(hi));
    } else {
        int j = i - NXEL;                  // 0 .. 3*HIDD*HIDD-1
        int z = j / (HIDD*HIDD);
        int k = j - z*(HIDD*HIDD);
        const float* W = (z == 0) ? Wq : (z == 1) ? Wk : Wv;
        g_Whi[j] = __float2half_rn(W[k]);
    }
}

// ---------------- QKV via mma.sync ----------------
// Q,K: C = Ah@Bh + Al@Bh (fp16 2-product). V (z==2): C = Ah@Bh only.
// 128x128 tile, BK=32, 24 iters, 8 warps (4m x 2n). grid (16,6,3).
__global__ __launch_bounds__(256) void qkv_mma_k(
    const float* __restrict__ bq, const float* __restrict__ bk,
    const float* __restrict__ bv)
{
    extern __shared__ __align__(16) char qsm[];
    const int TILEB = 128*LDS_*2;                     // bytes per tile

    const int tid = threadIdx.x;
    const int wid = tid >> 5, lane = tid & 31;
    const int warp_m = wid & 3, warp_n = wid >> 2;
    const int z = blockIdx.z;
    const bool tp = (z != 2);                          // two-product?
    const int row0 = blockIdx.x * 128;
    const int col0 = blockIdx.y * 128;
    const float* bias = (z == 0) ? bq : (z == 1) ? bk : bv;
    float* Y = (z == 0) ? g_Q : (z == 1) ? g_K : g_V;

    const uint32_t s0 = smem_u32(qsm);
    const uint32_t tAh[2] = { s0,           s0 + TILEB };
    const uint32_t tAl[2] = { s0 + 2*TILEB, s0 + 3*TILEB };
    const uint32_t tBh[2] = { s0 + 4*TILEB, s0 + 5*TILEB };

    const __half* Ah = g_Xhi + (size_t)row0*HIDD;
    const __half* Al = g_Xlo + (size_t)row0*HIDD;
    const __half* Bh = g_Whi + (size_t)(z*HIDD + col0)*HIDD;

    const int ldrow0 = tid >> 2, ldc0 = (tid & 3) * 16;   // bytes
    const int ldrow1 = (tid + 256) >> 2;
    const int gofs0  = (tid & 3) * 8;                      // elems

    float acc[2][8][4];
#pragma unroll
    for (int mt = 0; mt < 2; mt++)
#pragma unroll
        for (int nt = 0; nt < 8; nt++)
#pragma unroll
            for (int q = 0; q < 4; q++) acc[mt][nt][q] = 0.f;

#define QSTAGE(nb, kb)                                                            \
    do {                                                                          \
        cpa16(tAh[nb] + ldrow0*(LDS_*2) + ldc0, Ah + (size_t)ldrow0*HIDD + (kb) + gofs0); \
        cpa16(tAh[nb] + ldrow1*(LDS_*2) + ldc0, Ah + (size_t)ldrow1*HIDD + (kb) + gofs0); \
        if (tp) {                                                                 \
            cpa16(tAl[nb] + ldrow0*(LDS_*2) + ldc0, Al + (size_t)ldrow0*HIDD + (kb) + gofs0); \
            cpa16(tAl[nb] + ldrow1*(LDS_*2) + ldc0, Al + (size_t)ldrow1*HIDD + (kb) + gofs0); \
        }                                                                         \
        cpa16(tBh[nb] + ldrow0*(LDS_*2) + ldc0, Bh + (size_t)ldrow0*HIDD + (kb) + gofs0); \
        cpa16(tBh[nb] + ldrow1*(LDS_*2) + ldc0, Bh + (size_t)ldrow1*HIDD + (kb) + gofs0); \
        asm volatile("cp.async.commit_group;" ::: "memory");                      \
    } while (0)

    QSTAGE(0, 0);

    for (int it = 0; it < NITQ; it++) {
        const int cur = it & 1;
        if (it + 1 < NITQ) {
            QSTAGE(cur ^ 1, (it + 1) * BK);
            asm volatile("cp.async.wait_group 1;" ::: "memory");
        } else {
            asm volatile("cp.async.wait_group 0;" ::: "memory");
        }
        __syncthreads();

#pragma unroll
        for (int ks = 0; ks < 2; ks++) {
            const int kbyte = (ks*16 + ((lane >> 4) * 8)) * 2;
            uint32_t ah[2][4], al[2][4];
#pragma unroll
            for (int mt = 0; mt < 2; mt++) {
                int rr = warp_m*32 + mt*16 + (lane & 15);
                ldm_x4(ah[mt][0], ah[mt][1], ah[mt][2], ah[mt][3],
                       tAh[cur] + rr*(LDS_*2) + kbyte);
                if (tp)
                    ldm_x4(al[mt][0], al[mt][1], al[mt][2], al[mt][3],
                           tAl[cur] + rr*(LDS_*2) + kbyte);
            }
#pragma unroll
            for (int ng = 0; ng < 4; ng++) {
                int n = warp_n*64 + ng*16 + (lane & 15);
                uint32_t bh0, bh1, bh2, bh3;
                ldm_x4(bh0, bh1, bh2, bh3, tBh[cur] + n*(LDS_*2) + kbyte);
#pragma unroll
                for (int mt = 0; mt < 2; mt++) {
                    mma16816(acc[mt][ng*2+0], ah[mt], bh0, bh2);
                    mma16816(acc[mt][ng*2+1], ah[mt], bh1, bh3);
                    if (tp) {
                        mma16816(acc[mt][ng*2+0], al[mt], bh0, bh2);
                        mma16816(acc[mt][ng*2+1], al[mt], bh1, bh3);
                    }
                }
            }
        }
        __syncthreads();
    }
#undef QSTAGE

    // epilogue: bias add + f32 store (+ fp16 hi/lo of Q when z==0)
#pragma unroll
    for (int mt = 0; mt < 2; mt++) {
        const int r = row0 + warp_m*32 + mt*16 + (lane >> 2);
#pragma unroll
        for (int nt = 0; nt < 8; nt++) {
            const int cc = col0 + warp_n*64 + nt*8 + (lane & 3)*2;
            float v00 = acc[mt][nt][0] + bias[cc];
            float v01 = acc[mt][nt][1] + bias[cc+1];
            float v10 = acc[mt][nt][2] + bias[cc];
            float v11 = acc[mt][nt][3] + bias[cc+1];
            *(float2*)(Y + (size_t)r*HIDD + cc)     = make_float2(v00, v01);
            *(float2*)(Y + (size_t)(r+8)*HIDD + cc) = make_float2(v10, v11);
            if (z == 0) {
                __half h00 = __float2half_rn(v00), h01 = __float2half_rn(v01);
                __half h10 = __float2half_rn(v10), h11 = __float2half_rn(v11);
                __half2 hh0; hh0.x = h00; hh0.y = h01;
                __half2 hh1; hh1.x = h10; hh1.y = h11;
                __half2 ll0;
                ll0.x = __float2half_rn(v00 - __half2float(h00));
                ll0.y = __float2half_rn(v01 - __half2float(h01));
                __half2 ll1;
                ll1.x = __float2half_rn(v10 - __half2float(h10));
                ll1.y = __float2half_rn(v11 - __half2float(h11));
                *(__half2*)(g_Qhi + (size_t)r*HIDD + cc)     = hh0;
                *(__half2*)(g_Qhi + (size_t)(r+8)*HIDD + cc) = hh1;
                *(__half2*)(g_Qlo + (size_t)r*HIDD + cc)     = ll0;
                *(__half2*)(g_Qlo + (size_t)(r+8)*HIDD + cc) = ll1;
            }
        }
    }
}

// ---------------- edge logits via mma.sync, fp16 2-product ----------------
// P = Qh@Rh + Ql@Rh (K=64), then logit = (P·Ke)/8 in fp32.
// Block: 256 edge-head rows x 64 cols, 8 warps each 32 rows x 64 cols.
__global__ __launch_bounds__(256) void logits_mma_k(
    const int* __restrict__ ei, const float* __restrict__ rel)
{
    extern __shared__ __align__(16) char dsm[];
    __half* sBh = (__half*)dsm;
    __half* sAh = (__half*)(dsm + 9216);
    __half* sAl = (__half*)(dsm + 46080);
    int* rowK  = (int*)(dsm + 82944);
    int* rowEH = (int*)(dsm + 83968);
    int* rowQ  = (int*)(dsm + 84992);
    __shared__ int sRel;

    const int bid = blockIdx.x;
    const int tid = threadIdx.x;
    const int wid = tid >> 5, lane = tid & 31;

    // locate (relation, chunk) from the prefix table with two ballots
    if (tid < 32) {
        unsigned f0 = __ballot_sync(0xffffffffu, g_chunk_off[lane+1]  <= bid);
        unsigned f1 = __ballot_sync(0xffffffffu, g_chunk_off[lane+33] <= bid);
        if (lane == 0) sRel = __popc(f0) + __popc(f1);
    }
    __syncthreads();
    const int r = sRel;
    if (r >= NREL) return;

    const int off  = g_rel_off[r];
    const int cnt  = g_rel_off[r+1] - off;
    const int rows = cnt * Hh;
    const int row0 = (bid - g_chunk_off[r]) * 256;
    if (row0 >= rows) return;

    {
        int row = row0 + tid;
        if (row < rows) {
            int el = row / Hh, h = row - el*Hh;
            int e  = g_rel_list[off + el];
            int b  = ei[e], hn = ei[Ee+e], tn = ei[2*Ee+e];
            rowQ[tid]  = (b*Nn + hn)*HIDD + h*Dh;
            rowK[tid]  = (b*Nn + tn)*HIDD + h*Dh;
            rowEH[tid] = e*Hh + h;
        } else {
            rowQ[tid] = 0; rowK[tid] = 0; rowEH[tid] = -1;
        }
    }

    // stage B = Re^T rounded to fp16: sBh[n][d] from R[d][n]
    const float* Rg = rel + (size_t)r*4096;
#pragma unroll 4
    for (int i = tid; i < 4096; i += 256) {
        int d = i >> 6, n = i & 63;
        sBh[n*LST + d] = __float2half_rn(Rg[i]);
    }

    // stage A from g_Qhi/g_Qlo (own rowQ slot — no sync needed for that read)
    {
        const int row = tid;
        const __half* qh = g_Qhi + rowQ[row];
        const __half* ql = g_Qlo + rowQ[row];
        __half* dh = sAh + row*LST;
        __half* dl = sAl + row*LST;
#pragma unroll
        for (int j = 0; j < 8; j++) {
            *(uint4*)(dh + j*8) = *(const uint4*)(qh + j*8);
            *(uint4*)(dl + j*8) = *(const uint4*)(ql + j*8);
        }
    }
    __syncthreads();

    const uint32_t sAhu = smem_u32(sAh), sAlu = smem_u32(sAl);
    const uint32_t sBhu = smem_u32(sBh);

    float acc[2][8][4];
#pragma unroll
    for (int mt = 0; mt < 2; mt++)
#pragma unroll
        for (int nt = 0; nt < 8; nt++)
#pragma unroll
            for (int q = 0; q < 4; q++) acc[mt][nt][q] = 0.f;

#pragma unroll
    for (int ks = 0; ks < 4; ks++) {
        const int kbyte = (ks*16 + ((lane >> 4) * 8)) * 2;
        uint32_t ah[2][4], al[2][4];
#pragma unroll
        for (int mt = 0; mt < 2; mt++) {
            int rr = wid*32 + mt*16 + (lane & 15);
            ldm_x4(ah[mt][0], ah[mt][1], ah[mt][2], ah[mt][3],
                   sAhu + rr*(LST*2) + kbyte);
            ldm_x4(al[mt][0], al[mt][1], al[mt][2], al[mt][3],
                   sAlu + rr*(LST*2) + kbyte);
        }
#pragma unroll
        for (int ng = 0; ng < 4; ng++) {
            int n = ng*16 + (lane & 15);
            uint32_t bh0, bh1, bh2, bh3;
            ldm_x4(bh0, bh1, bh2, bh3, sBhu + n*(LST*2) + kbyte);
#pragma unroll
            for (int mt = 0; mt < 2; mt++) {
                mma16816(acc[mt][ng*2+0], ah[mt], bh0, bh2);
                mma16816(acc[mt][ng*2+1], ah[mt], bh1, bh3);
                mma16816(acc[mt][ng*2+0], al[mt], bh0, bh2);
                mma16816(acc[mt][ng*2+1], al[mt], bh1, bh3);
            }
        }
    }

    // logit = P . Ke  — each warp owns full rows: quad shfl completes the dot
#pragma unroll
    for (int mt = 0; mt < 2; mt++) {
        int rl0 = wid*32 + mt*16 + (lane >> 2);
        int rl1 = rl0 + 8;
        const float* k0p = g_K + rowK[rl0];
        const float* k1p = g_K + rowK[rl1];
        float s0 = 0.f, s1 = 0.f;
#pragma unroll
        for (int nt = 0; nt < 8; nt++) {
            int cc = (nt>>1)*16 + (nt&1)*8 + (lane & 3)*2;
            float2 kv0 = *(const float2*)(k0p + cc);
            float2 kv1 = *(const float2*)(k1p + cc);
            s0 += acc[mt][nt][0]*kv0.x + acc[mt][nt][1]*kv0.y;
            s1 += acc[mt][nt][2]*kv1.x + acc[mt][nt][3]*kv1.y;
        }
        s0 += __shfl_xor_sync(0xffffffffu, s0, 1);
        s0 += __shfl_xor_sync(0xffffffffu, s0, 2);
        s1 += __shfl_xor_sync(0xffffffffu, s1, 1);
        s1 += __shfl_xor_sync(0xffffffffu, s1, 2);
        if ((lane & 3) == 0) {
            if (rowEH[rl0] >= 0) g_logits[rowEH[rl0]] = s0 * 0.125f;
            if (rowEH[rl1] >= 0) g_logits[rowEH[rl1]] = s1 * 0.125f;
        }
    }
}

// ---------------- per-segment softmax + aggregation ----------------
__global__ __launch_bounds__(384) void softagg_k(
    const int* __restrict__ ei, float* __restrict__ out)
{
    __shared__ int sVoff[512];
    __shared__ int sEh[512];
    __shared__ float sP[512*13];     // p cache, padded stride 13 (conflict-free)

    const int s   = blockIdx.x;
    const int off = g_seg_off[s];
    const int cnt = g_seg_off[s+1] - off;
    const int w = threadIdx.x >> 5, lane = threadIdx.x & 31;

    if (cnt == 0) {
        for (int i = threadIdx.x; i < HIDD; i += 384) out[(size_t)s*HIDD + i] = 0.f;
        return;
    }

    if (cnt <= 512) {
        for (int j = threadIdx.x; j < cnt; j += 384) {
            int e = g_seg_list[off+j];
            sVoff[j] = (ei[e]*Nn + ei[2*Ee+e])*HIDD;
            sEh[j]   = e*Hh;
        }
        __syncthreads();

        float m = -3.4e38f;
        for (int i = lane; i < cnt; i += 32)
            m = fmaxf(m, g_logits[sEh[i] + w]);
#pragma unroll
        for (int o = 16; o; o >>= 1) m = fmaxf(m, __shfl_xor_sync(0xffffffffu, m, o));

        float sm = 0.f;
        for (int i = lane; i < cnt; i += 32) {
            float p = __expf(g_logits[sEh[i] + w] - m);
            sP[i*13 + w] = p;
            sm += p;
        }
#pragma unroll
        for (int o = 16; o; o >>= 1) sm += __shfl_xor_sync(0xffffffffu, sm, o);
        const float rsc = 1.f / sm;
        __syncwarp();

        float a0 = 0.f, a1 = 0.f;
#pragma unroll 4
        for (int i = 0; i < cnt; i++) {
            float p = sP[i*13 + w];
            const float* vp = g_V + sVoff[i] + w*Dh;
            a0 += p * vp[lane];
            a1 += p * vp[lane+32];
        }
        out[(size_t)s*HIDD + w*Dh + lane]      = a0 * rsc;
        out[(size_t)s*HIDD + w*Dh + lane + 32] = a1 * rsc;
    } else {
        float m = -3.4e38f;
        for (int i = lane; i < cnt; i += 32)
            m = fmaxf(m, g_logits[g_seg_list[off+i]*Hh + w]);
#pragma unroll
        for (int o = 16; o; o >>= 1) m = fmaxf(m, __shfl_xor_sync(0xffffffffu, m, o));

        float sm = 0.f;
        for (int i = lane; i < cnt; i += 32)
            sm += __expf(g_logits[g_seg_list[off+i]*Hh + w] - m);
#pragma unroll
        for (int o = 16; o; o >>= 1) sm += __shfl_xor_sync(0xffffffffu, sm, o);
        const float rsc = 1.f / sm;

        float a0 = 0.f, a1 = 0.f;
        for (int i = 0; i < cnt; i++) {
            int e = g_seg_list[off+i];
            float p = __expf(g_logits[e*Hh + w] - m);
            const float* vp = g_V + ((size_t)(ei[e]*Nn + ei[2*Ee+e]))*HIDD + w*Dh;
            a0 += p * vp[lane];
            a1 += p * vp[lane+32];
        }
        out[(size_t)s*HIDD + w*Dh + lane]      = a0 * rsc;
        out[(size_t)s*HIDD + w*Dh + lane + 32] = a1 * rsc;
    }
}

// ---------------- launch (single stream; 6th launch = qkv_mma_k for ncu) ----------------
extern "C" void kernel_launch(void* const* d_in, const int* in_sizes, int n_in,
                              void* d_out, int out_size)
{
    const float* X    = (const float*)d_in[0];
    const int*   ei   = (const int*)  d_in[1];
    const float* Wq   = (const float*)d_in[3];
    const float* bq   = (const float*)d_in[4];
    const float* Wk   = (const float*)d_in[5];
    const float* bk   = (const float*)d_in[6];
    const float* Wv   = (const float*)d_in[7];
    const float* bv   = (const float*)d_in[8];
    const float* rel  = (const float*)d_in[9];
    float* out = (float*)d_out;

    cudaFuncSetAttribute(qkv_mma_k,
                         cudaFuncAttributeMaxDynamicSharedMemorySize, 61440);
    cudaFuncSetAttribute(logits_mma_k,
                         cudaFuncAttributeMaxDynamicSharedMemorySize, 86016);

    zero_k   <<<8, 256>>>();
    hist_k   <<<Ee/256, 256>>>(ei);
    scan_k   <<<1, 1024>>>();
    scatter_k<<<Ee/256, 256>>>(ei);
    conv_k   <<<(NXEL + 3*HIDD*HIDD)/256, 256>>>(X, Wq, Wk, Wv);
    qkv_mma_k<<<dim3(16, 6, 3), 256, 61440>>>(bq, bk, bv);
    logits_mma_k<<<NCHK, 256, 86016>>>(ei, rel);
    softagg_k<<<NSEG, 384>>>(ei, out);
}